// round 1
// baseline (speedup 1.0000x reference)
#include <cuda_runtime.h>
#include <math.h>

// Problem constants
#define Bb     8
#define Cc     384
#define HH     64
#define WW     64
#define NN     4096          // H*W
#define HEADS  8
#define HD     48
#define CN     (Cc*NN)       // 1,572,864
#define C6c    64
#define C2c    192
#define C4c    96

// ---------------- scratch (module-load allocated, not cudaMalloc) ----------
__device__ float g_qkv  [Bb*3*CN];       // (B, 3C, N)
__device__ float g_at   [Bb*CN];         // attention output (B,C,N)
__device__ float g_t1   [Bb*CN];         // dw1 output
__device__ float g_convx[Bb*CN];         // dw2 output
__device__ float g_chmap[Bb*CN];
__device__ float g_spmap[Bb*CN];
__device__ float g_y    [Bb*CN];
__device__ float g_tt   [Bb*C6c*NN];
__device__ float g_u1   [Bb*C6c*NN];
__device__ float g_u2   [Bb*C6c*NN];
__device__ float g_sp   [Bb*C2c*NN];
__device__ float g_spd  [Bb*C2c*NN];
__device__ float g_gated[Bb*C4c*NN];
__device__ float g_inv  [Bb*2*Cc];
__device__ float g_gram [Bb*HEADS*HD*HD];
__device__ float g_attn [Bb*HEADS*HD*HD];
__device__ float g_tmean[Bb*C6c];
__device__ float g_ci1v [Bb*C6c];
__device__ float g_cm   [Bb*Cc];

// ---------------- generic per-batch SGEMM: Y[b] = W (MxK) * X[b] (KxN) -----
// N fixed at 4096. Requires M%64==0, K%16==0 (true for all call sites).
#define GBM 64
#define GBN 128
#define GBK 16
__global__ __launch_bounds__(256)
void gemm64x128(const float* __restrict__ A, const float* __restrict__ X,
                const float* __restrict__ bias, float* __restrict__ Y,
                int M, int K, long long xstride)
{
    const int b  = blockIdx.z;
    const float* Xb = X + (size_t)b * xstride;
    float*       Yb = Y + (size_t)b * M * NN;
    const int m0 = blockIdx.y * GBM;
    const int n0 = blockIdx.x * GBN;

    __shared__ float As[GBK][GBM];
    __shared__ float Bs[GBK][GBN];

    const int tid = threadIdx.x;
    const int am  = tid >> 2;            // 0..63
    const int ak  = (tid & 3) << 2;      // 0,4,8,12
    const int bk  = tid >> 4;            // 0..15
    const int bn  = (tid & 15) << 3;     // 0..120
    const int tx  = tid & 15;
    const int ty  = tid >> 4;
    const int tn0 = tx * 8;
    const int tm0 = ty * 4;

    float acc[4][8];
    #pragma unroll
    for (int i = 0; i < 4; i++)
        #pragma unroll
        for (int j = 0; j < 8; j++) acc[i][j] = 0.f;

    for (int k0 = 0; k0 < K; k0 += GBK) {
        float4 a4 = *(const float4*)(A + (size_t)(m0 + am) * K + k0 + ak);
        As[ak + 0][am] = a4.x; As[ak + 1][am] = a4.y;
        As[ak + 2][am] = a4.z; As[ak + 3][am] = a4.w;
        const float* xp = Xb + (size_t)(k0 + bk) * NN + n0 + bn;
        *(float4*)&Bs[bk][bn]     = *(const float4*)(xp);
        *(float4*)&Bs[bk][bn + 4] = *(const float4*)(xp + 4);
        __syncthreads();
        #pragma unroll
        for (int kk = 0; kk < GBK; kk++) {
            float ar[4], br[8];
            #pragma unroll
            for (int i = 0; i < 4; i++) ar[i] = As[kk][tm0 + i];
            #pragma unroll
            for (int j = 0; j < 8; j++) br[j] = Bs[kk][tn0 + j];
            #pragma unroll
            for (int i = 0; i < 4; i++)
                #pragma unroll
                for (int j = 0; j < 8; j++) acc[i][j] += ar[i] * br[j];
        }
        __syncthreads();
    }

    #pragma unroll
    for (int i = 0; i < 4; i++) {
        int row = m0 + tm0 + i;
        float bv = bias ? bias[row] : 0.f;
        float* yp = Yb + (size_t)row * NN + n0 + tn0;
        float4 o0 = make_float4(acc[i][0]+bv, acc[i][1]+bv, acc[i][2]+bv, acc[i][3]+bv);
        float4 o1 = make_float4(acc[i][4]+bv, acc[i][5]+bv, acc[i][6]+bv, acc[i][7]+bv);
        *(float4*)(yp)     = o0;
        *(float4*)(yp + 4) = o1;
    }
}

// ---------------- L2 row norms for q,k rows ---------------------------------
__global__ void rownorm_kernel(const float* __restrict__ qkv, float* __restrict__ inv)
{
    int row = blockIdx.x;                       // 0 .. Bb*2*Cc-1
    int b = row / (2 * Cc), r = row % (2 * Cc);
    const float* p = qkv + (size_t)b * 3 * CN + (size_t)r * NN;
    float s = 0.f;
    for (int i = threadIdx.x; i < NN; i += 256) { float v = p[i]; s += v * v; }
    __shared__ float red[256];
    red[threadIdx.x] = s; __syncthreads();
    for (int st = 128; st > 0; st >>= 1) {
        if (threadIdx.x < st) red[threadIdx.x] += red[threadIdx.x + st];
        __syncthreads();
    }
    if (threadIdx.x == 0) inv[row] = 1.0f / fmaxf(sqrtf(red[0]), 1e-12f);
}

// ---------------- gram: per (b,h) 48x48 = q @ k^T over N --------------------
__global__ __launch_bounds__(256)
void gram_kernel(const float* __restrict__ qkv, float* __restrict__ gram)
{
    int bh = blockIdx.x;
    int b = bh >> 3, h = bh & 7;
    const float* qp = qkv + (size_t)b * 3 * CN + (size_t)h * HD * NN;
    const float* kp = qp + CN;
    __shared__ float qs[HD][33];
    __shared__ float ks[HD][33];
    int tid = threadIdx.x;
    int tx = tid & 15, ty = tid >> 4;
    float acc[3][3] = {{0}};
    for (int n0 = 0; n0 < NN; n0 += 32) {
        for (int e = tid; e < HD * 32; e += 256) {
            int r = e >> 5, c = e & 31;
            qs[r][c] = qp[(size_t)r * NN + n0 + c];
            ks[r][c] = kp[(size_t)r * NN + n0 + c];
        }
        __syncthreads();
        #pragma unroll
        for (int kk = 0; kk < 32; kk++) {
            float qr[3], kr[3];
            #pragma unroll
            for (int i = 0; i < 3; i++) qr[i] = qs[ty * 3 + i][kk];
            #pragma unroll
            for (int j = 0; j < 3; j++) kr[j] = ks[tx * 3 + j][kk];
            #pragma unroll
            for (int i = 0; i < 3; i++)
                #pragma unroll
                for (int j = 0; j < 3; j++) acc[i][j] += qr[i] * kr[j];
        }
        __syncthreads();
    }
    float* gp = gram + (size_t)bh * HD * HD;
    #pragma unroll
    for (int i = 0; i < 3; i++)
        #pragma unroll
        for (int j = 0; j < 3; j++)
            gp[(ty * 3 + i) * HD + tx * 3 + j] = acc[i][j];
}

// ---------------- softmax over rows of 48x48 with norm+temperature ---------
__global__ void softmax_kernel(const float* __restrict__ gram, const float* __restrict__ inv,
                               const float* __restrict__ temp, float* __restrict__ attn)
{
    int gi = blockIdx.x;
    int i = gi % HD; int bh = gi / HD;
    int b = bh >> 3, h = bh & 7;
    int tid = threadIdx.x;     // 64
    float v = -3.4e38f;
    if (tid < HD) {
        float qi = inv[b * 2 * Cc + h * HD + i];
        float kj = inv[b * 2 * Cc + Cc + h * HD + tid];
        v = gram[(size_t)bh * HD * HD + i * HD + tid] * qi * kj * temp[h];
    }
    __shared__ float red[64];
    red[tid] = v; __syncthreads();
    for (int st = 32; st > 0; st >>= 1) {
        if (tid < st) red[tid] = fmaxf(red[tid], red[tid + st]);
        __syncthreads();
    }
    float m = red[0]; __syncthreads();
    float e = (tid < HD) ? expf(v - m) : 0.f;
    red[tid] = e; __syncthreads();
    for (int st = 32; st > 0; st >>= 1) {
        if (tid < st) red[tid] += red[tid + st];
        __syncthreads();
    }
    float s = red[0];
    if (tid < HD) attn[(size_t)bh * HD * HD + i * HD + tid] = e / s;
}

// ---------------- at = attn (48x48) @ v (48xN) ------------------------------
__global__ __launch_bounds__(128)
void attnv_kernel(const float* __restrict__ qkv, const float* __restrict__ attn,
                  float* __restrict__ out)
{
    int bh = blockIdx.y; int b = bh >> 3, h = bh & 7;
    int n = blockIdx.x * 128 + threadIdx.x;
    __shared__ float sa[HD * HD];
    for (int e = threadIdx.x; e < HD * HD; e += 128)
        sa[e] = attn[(size_t)bh * HD * HD + e];
    __syncthreads();
    const float* vp = qkv + (size_t)b * 3 * CN + 2 * CN + (size_t)h * HD * NN;
    float vr[HD];
    #pragma unroll
    for (int j = 0; j < HD; j++) vr[j] = vp[(size_t)j * NN + n];
    float* op = out + (size_t)b * CN + (size_t)h * HD * NN;
    for (int i = 0; i < HD; i++) {
        float s = 0.f;
        #pragma unroll
        for (int j = 0; j < HD; j++) s += sa[i * HD + j] * vr[j];
        op[(size_t)i * NN + n] = s;
    }
}

// ---------------- generic depthwise conv ------------------------------------
__global__ void dwconv_kernel(const float* __restrict__ in, const float* __restrict__ w,
                              const float* __restrict__ bias, float* __restrict__ out,
                              int C, int ks, int pad, int dil, int total)
{
    int idx = blockIdx.x * 256 + threadIdx.x;
    if (idx >= total) return;
    int x = idx & (WW - 1);
    int h = (idx >> 6) & (HH - 1);
    int c = (idx >> 12) % C;
    int b = idx / (C * NN);
    const float* ip = in + (size_t)(b * C + c) * NN;
    const float* wp = w + c * ks * ks;
    float acc = bias[c];
    for (int ky = 0; ky < ks; ky++) {
        int y = h - pad + ky * dil;
        if ((unsigned)y >= (unsigned)HH) continue;
        for (int kx = 0; kx < ks; kx++) {
            int xx = x - pad + kx * dil;
            if ((unsigned)xx >= (unsigned)WW) continue;
            acc += ip[y * WW + xx] * wp[ky * ks + kx];
        }
    }
    out[idx] = acc;
}

// ---------------- spatial mean per (b,c) -------------------------------------
__global__ void mean_kernel(const float* __restrict__ in, float* __restrict__ out)
{
    int bc = blockIdx.x;
    const float* p = in + (size_t)bc * NN;
    float s = 0.f;
    for (int i = threadIdx.x; i < NN; i += 256) s += p[i];
    __shared__ float red[256];
    red[threadIdx.x] = s; __syncthreads();
    for (int st = 128; st > 0; st >>= 1) {
        if (threadIdx.x < st) red[threadIdx.x] += red[threadIdx.x + st];
        __syncthreads();
    }
    if (threadIdx.x == 0) out[bc] = red[0] * (1.f / NN);
}

// ---------------- ci1: tiny 64x64 1x1 conv on means --------------------------
__global__ void ci1_kernel(const float* __restrict__ w, const float* __restrict__ bias,
                           const float* __restrict__ tmean, float* __restrict__ outv)
{
    int b = blockIdx.x; int co = threadIdx.x;       // 64 threads
    __shared__ float tm[C6c];
    tm[co] = tmean[b * C6c + co]; __syncthreads();
    float acc = bias[co];
    #pragma unroll
    for (int ci = 0; ci < C6c; ci++) acc += w[co * C6c + ci] * tm[ci];
    outv[b * C6c + co] = acc;
}

// ---------------- out = t * ci1[b,c] * ci2 ----------------------------------
__global__ void mul3_kernel(const float* __restrict__ t, const float* __restrict__ ci1v,
                            const float* __restrict__ ci2, float* __restrict__ out, int total)
{
    int idx = blockIdx.x * 256 + threadIdx.x;
    if (idx >= total) return;
    int c = (idx >> 12) % C6c;
    int b = idx / (C6c * NN);
    out[idx] = t[idx] * ci1v[b * C6c + c] * ci2[idx];
}

// ---------------- gated = gelu(x1)*x2 (split along channels) ----------------
__global__ void gelugate_kernel(const float* __restrict__ d, float* __restrict__ out, int total)
{
    int idx = blockIdx.x * 256 + threadIdx.x;
    if (idx >= total) return;
    int n = idx & (NN - 1);
    int j = (idx >> 12) % C4c;
    int b = idx / (C4c * NN);
    const float* dp = d + (size_t)b * C2c * NN;
    float x1 = dp[(size_t)j * NN + n];
    float x2 = dp[(size_t)(j + C4c) * NN + n];
    float g = 0.5f * x1 * (1.f + erff(x1 * 0.70710678118654752f));
    out[idx] = g * x2;
}

// ---------------- final combine ----------------------------------------------
__global__ void combine_kernel(const float* __restrict__ at, const float* __restrict__ chmap,
                               const float* __restrict__ spmap, const float* __restrict__ convx,
                               const float* __restrict__ cm, float* __restrict__ y, int total)
{
    int idx = blockIdx.x * 256 + threadIdx.x;
    if (idx >= total) return;
    int c = (idx >> 12) % Cc;
    int b = idx / (Cc * NN);
    float s1 = 1.f / (1.f + expf(-spmap[idx]));
    float s2 = 1.f / (1.f + expf(-cm[b * Cc + c]));
    y[idx] = (at[idx] + chmap[idx]) * s1 + convx[idx] * s2;
}

// ================================================================= launch ===
extern "C" void kernel_launch(void* const* d_in, const int* in_sizes, int n_in,
                              void* d_out, int out_size)
{
    const float* x           = (const float*)d_in[0];
    const float* temperature = (const float*)d_in[1];
    const float* qkv_w       = (const float*)d_in[2];
    const float* proj_w      = (const float*)d_in[3];
    const float* proj_b      = (const float*)d_in[4];
    const float* dw1_w       = (const float*)d_in[5];
    const float* dw1_b       = (const float*)d_in[6];
    const float* dw2_w       = (const float*)d_in[7];
    const float* dw2_b       = (const float*)d_in[8];
    const float* cp_in_w     = (const float*)d_in[9];
    const float* cp_in_b     = (const float*)d_in[10];
    const float* ci1_w       = (const float*)d_in[11];
    const float* ci1_b       = (const float*)d_in[12];
    const float* ci2a_w      = (const float*)d_in[13];
    const float* ci2a_b      = (const float*)d_in[14];
    const float* ci2b_w      = (const float*)d_in[15];
    const float* ci2b_b      = (const float*)d_in[16];
    const float* ci2c_w      = (const float*)d_in[17];
    const float* ci2c_b      = (const float*)d_in[18];
    const float* cp_out_w    = (const float*)d_in[19];
    const float* cp_out_b    = (const float*)d_in[20];
    const float* sp_in_w     = (const float*)d_in[21];
    const float* sp_in_b     = (const float*)d_in[22];
    const float* sp_dw_w     = (const float*)d_in[23];
    const float* sp_dw_b     = (const float*)d_in[24];
    const float* sp_out_w    = (const float*)d_in[25];
    const float* sp_out_b    = (const float*)d_in[26];
    float* out = (float*)d_out;

    float *qkv, *at, *t1, *convx, *chmap, *spmap, *y, *tt, *u1, *u2, *sp, *spd,
          *gated, *inv, *gram, *attn, *tmean, *ci1v, *cm;
    cudaGetSymbolAddress((void**)&qkv,   g_qkv);
    cudaGetSymbolAddress((void**)&at,    g_at);
    cudaGetSymbolAddress((void**)&t1,    g_t1);
    cudaGetSymbolAddress((void**)&convx, g_convx);
    cudaGetSymbolAddress((void**)&chmap, g_chmap);
    cudaGetSymbolAddress((void**)&spmap, g_spmap);
    cudaGetSymbolAddress((void**)&y,     g_y);
    cudaGetSymbolAddress((void**)&tt,    g_tt);
    cudaGetSymbolAddress((void**)&u1,    g_u1);
    cudaGetSymbolAddress((void**)&u2,    g_u2);
    cudaGetSymbolAddress((void**)&sp,    g_sp);
    cudaGetSymbolAddress((void**)&spd,   g_spd);
    cudaGetSymbolAddress((void**)&gated, g_gated);
    cudaGetSymbolAddress((void**)&inv,   g_inv);
    cudaGetSymbolAddress((void**)&gram,  g_gram);
    cudaGetSymbolAddress((void**)&attn,  g_attn);
    cudaGetSymbolAddress((void**)&tmean, g_tmean);
    cudaGetSymbolAddress((void**)&ci1v,  g_ci1v);
    cudaGetSymbolAddress((void**)&cm,    g_cm);

    // 1. QKV projection: (B,1152,N) = qkv_w @ x
    gemm64x128<<<dim3(32, 18, Bb), 256>>>(qkv_w, x, nullptr, qkv, 3 * Cc, Cc, (long long)CN);
    // 2. L2 norms of q,k rows
    rownorm_kernel<<<Bb * 2 * Cc, 256>>>(qkv, inv);
    // 3. gram matrices (48x48 per b,h)
    gram_kernel<<<Bb * HEADS, 256>>>(qkv, gram);
    // 4. scaled softmax
    softmax_kernel<<<Bb * HEADS * HD, 64>>>(gram, inv, temperature, attn);
    // 5. at = attn @ v
    attnv_kernel<<<dim3(NN / 128, Bb * HEADS), 128>>>(qkv, attn, at);
    // 6. dw1: 1x1 conv on v
    gemm64x128<<<dim3(32, 6, Bb), 256>>>(dw1_w, qkv + 2 * CN, dw1_b, t1, Cc, Cc, 3LL * CN);
    // 7. dw2: depthwise 3x3
    dwconv_kernel<<<(Bb * CN) / 256, 256>>>(t1, dw2_w, dw2_b, convx, Cc, 3, 1, 1, Bb * CN);
    // 8. cp_in: 1x1 C->64 on attention output
    gemm64x128<<<dim3(32, 1, Bb), 256>>>(cp_in_w, at, cp_in_b, tt, C6c, Cc, (long long)CN);
    // 9. spatial mean of t
    mean_kernel<<<Bb * C6c, 256>>>(tt, tmean);
    // 10. ci1 tiny conv
    ci1_kernel<<<Bb, C6c>>>(ci1_w, ci1_b, tmean, ci1v);
    // 11. ci2a: dw 3x3
    dwconv_kernel<<<(Bb * C6c * NN) / 256, 256>>>(tt, ci2a_w, ci2a_b, u1, C6c, 3, 1, 1, Bb * C6c * NN);
    // 12. ci2b: dw 7x7 pad9 dil3
    dwconv_kernel<<<(Bb * C6c * NN) / 256, 256>>>(u1, ci2b_w, ci2b_b, u2, C6c, 7, 9, 3, Bb * C6c * NN);
    // 13. ci2c: 1x1 64->64
    gemm64x128<<<dim3(32, 1, Bb), 256>>>(ci2c_w, u2, ci2c_b, u1, C6c, C6c, (long long)C6c * NN);
    // 14. t * ci1 * ci2
    mul3_kernel<<<(Bb * C6c * NN) / 256, 256>>>(tt, ci1v, u1, u2, Bb * C6c * NN);
    // 15. cp_out: 1x1 64->384
    gemm64x128<<<dim3(32, 6, Bb), 256>>>(cp_out_w, u2, cp_out_b, chmap, Cc, C6c, (long long)C6c * NN);
    // 16. cm = mean(channel_map)
    mean_kernel<<<Bb * Cc, 256>>>(chmap, cm);
    // 17. sp_in: 1x1 C->192 on conv branch
    gemm64x128<<<dim3(32, 3, Bb), 256>>>(sp_in_w, convx, sp_in_b, sp, C2c, Cc, (long long)CN);
    // 18. sp_dw: dw 3x3
    dwconv_kernel<<<(Bb * C2c * NN) / 256, 256>>>(sp, sp_dw_w, sp_dw_b, spd, C2c, 3, 1, 1, Bb * C2c * NN);
    // 19. gelu gate
    gelugate_kernel<<<(Bb * C4c * NN) / 256, 256>>>(spd, gated, Bb * C4c * NN);
    // 20. sp_out: 1x1 96->384
    gemm64x128<<<dim3(32, 6, Bb), 256>>>(sp_out_w, gated, sp_out_b, spmap, Cc, C4c, (long long)C4c * NN);
    // 21. combine: y = (at+chmap)*sig(spmap) + convx*sig(cm)
    combine_kernel<<<(Bb * CN) / 256, 256>>>(at, chmap, spmap, convx, cm, y, Bb * CN);
    // 22. final projection -> d_out in (B,C,N) layout
    gemm64x128<<<dim3(32, 6, Bb), 256>>>(proj_w, y, proj_b, out, Cc, Cc, (long long)CN);
}

// round 2
// speedup vs baseline: 1.0028x; 1.0028x over previous
#include <cuda_runtime.h>
#include <math.h>

// Problem constants
#define Bb     8
#define Cc     384
#define HH     64
#define WW     64
#define NN     4096          // H*W
#define HEADS  8
#define HD     48
#define CN     (Cc*NN)       // 1,572,864
#define C6c    64
#define C2c    192
#define C4c    96

// ---------------- scratch (module-load allocated, not cudaMalloc) ----------
__device__ float g_qkv  [Bb*3*CN];       // (B, 3C, N)
__device__ float g_at   [Bb*CN];         // attention output (B,C,N)
__device__ float g_t1   [Bb*CN];         // dw1 output
__device__ float g_convx[Bb*CN];         // dw2 output
__device__ float g_chmap[Bb*CN];
__device__ float g_spmap[Bb*CN];
__device__ float g_y    [Bb*CN];
__device__ float g_tt   [Bb*C6c*NN];
__device__ float g_u1   [Bb*C6c*NN];
__device__ float g_u2   [Bb*C6c*NN];
__device__ float g_sp   [Bb*C2c*NN];
__device__ float g_spd  [Bb*C2c*NN];
__device__ float g_gated[Bb*C4c*NN];
__device__ float g_inv  [Bb*2*Cc];
__device__ float g_gram [Bb*HEADS*HD*HD];
__device__ float g_attn [Bb*HEADS*HD*HD];
__device__ float g_tmean[Bb*C6c];
__device__ float g_ci1v [Bb*C6c];
__device__ float g_cm   [Bb*Cc];

// ---------------- generic per-batch SGEMM: Y[b] = W (MxK) * X[b] (KxN) -----
// N fixed at 4096. Requires M%64==0, K%16==0 (true for all call sites).
#define GBM 64
#define GBN 128
#define GBK 16
__global__ __launch_bounds__(256)
void gemm64x128(const float* __restrict__ A, const float* __restrict__ X,
                const float* __restrict__ bias, float* __restrict__ Y,
                int M, int K, long long xstride)
{
    const int b  = blockIdx.z;
    const float* Xb = X + (size_t)b * xstride;
    float*       Yb = Y + (size_t)b * M * NN;
    const int m0 = blockIdx.y * GBM;
    const int n0 = blockIdx.x * GBN;

    __shared__ float As[GBK][GBM];
    __shared__ float Bs[GBK][GBN];

    const int tid = threadIdx.x;
    const int am  = tid >> 2;            // 0..63
    const int ak  = (tid & 3) << 2;      // 0,4,8,12
    const int bk  = tid >> 4;            // 0..15
    const int bn  = (tid & 15) << 3;     // 0..120
    const int tx  = tid & 15;
    const int ty  = tid >> 4;
    const int tn0 = tx * 8;
    const int tm0 = ty * 4;

    float acc[4][8];
    #pragma unroll
    for (int i = 0; i < 4; i++)
        #pragma unroll
        for (int j = 0; j < 8; j++) acc[i][j] = 0.f;

    for (int k0 = 0; k0 < K; k0 += GBK) {
        float4 a4 = *(const float4*)(A + (size_t)(m0 + am) * K + k0 + ak);
        As[ak + 0][am] = a4.x; As[ak + 1][am] = a4.y;
        As[ak + 2][am] = a4.z; As[ak + 3][am] = a4.w;
        const float* xp = Xb + (size_t)(k0 + bk) * NN + n0 + bn;
        *(float4*)&Bs[bk][bn]     = *(const float4*)(xp);
        *(float4*)&Bs[bk][bn + 4] = *(const float4*)(xp + 4);
        __syncthreads();
        #pragma unroll
        for (int kk = 0; kk < GBK; kk++) {
            float ar[4], br[8];
            #pragma unroll
            for (int i = 0; i < 4; i++) ar[i] = As[kk][tm0 + i];
            #pragma unroll
            for (int j = 0; j < 8; j++) br[j] = Bs[kk][tn0 + j];
            #pragma unroll
            for (int i = 0; i < 4; i++)
                #pragma unroll
                for (int j = 0; j < 8; j++) acc[i][j] += ar[i] * br[j];
        }
        __syncthreads();
    }

    #pragma unroll
    for (int i = 0; i < 4; i++) {
        int row = m0 + tm0 + i;
        float bv = bias ? bias[row] : 0.f;
        float* yp = Yb + (size_t)row * NN + n0 + tn0;
        float4 o0 = make_float4(acc[i][0]+bv, acc[i][1]+bv, acc[i][2]+bv, acc[i][3]+bv);
        float4 o1 = make_float4(acc[i][4]+bv, acc[i][5]+bv, acc[i][6]+bv, acc[i][7]+bv);
        *(float4*)(yp)     = o0;
        *(float4*)(yp + 4) = o1;
    }
}

// ---------------- L2 row norms for q,k rows ---------------------------------
__global__ void rownorm_kernel(const float* __restrict__ qkv, float* __restrict__ inv)
{
    int row = blockIdx.x;                       // 0 .. Bb*2*Cc-1
    int b = row / (2 * Cc), r = row % (2 * Cc);
    const float* p = qkv + (size_t)b * 3 * CN + (size_t)r * NN;
    float s = 0.f;
    for (int i = threadIdx.x; i < NN; i += 256) { float v = p[i]; s += v * v; }
    __shared__ float red[256];
    red[threadIdx.x] = s; __syncthreads();
    for (int st = 128; st > 0; st >>= 1) {
        if (threadIdx.x < st) red[threadIdx.x] += red[threadIdx.x + st];
        __syncthreads();
    }
    if (threadIdx.x == 0) inv[row] = 1.0f / fmaxf(sqrtf(red[0]), 1e-12f);
}

// ---------------- gram: per (b,h) 48x48 = q @ k^T over N --------------------
__global__ __launch_bounds__(256)
void gram_kernel(const float* __restrict__ qkv, float* __restrict__ gram)
{
    int bh = blockIdx.x;
    int b = bh >> 3, h = bh & 7;
    const float* qp = qkv + (size_t)b * 3 * CN + (size_t)h * HD * NN;
    const float* kp = qp + CN;
    __shared__ float qs[HD][33];
    __shared__ float ks[HD][33];
    int tid = threadIdx.x;
    int tx = tid & 15, ty = tid >> 4;
    float acc[3][3] = {{0}};
    for (int n0 = 0; n0 < NN; n0 += 32) {
        for (int e = tid; e < HD * 32; e += 256) {
            int r = e >> 5, c = e & 31;
            qs[r][c] = qp[(size_t)r * NN + n0 + c];
            ks[r][c] = kp[(size_t)r * NN + n0 + c];
        }
        __syncthreads();
        #pragma unroll
        for (int kk = 0; kk < 32; kk++) {
            float qr[3], kr[3];
            #pragma unroll
            for (int i = 0; i < 3; i++) qr[i] = qs[ty * 3 + i][kk];
            #pragma unroll
            for (int j = 0; j < 3; j++) kr[j] = ks[tx * 3 + j][kk];
            #pragma unroll
            for (int i = 0; i < 3; i++)
                #pragma unroll
                for (int j = 0; j < 3; j++) acc[i][j] += qr[i] * kr[j];
        }
        __syncthreads();
    }
    float* gp = gram + (size_t)bh * HD * HD;
    #pragma unroll
    for (int i = 0; i < 3; i++)
        #pragma unroll
        for (int j = 0; j < 3; j++)
            gp[(ty * 3 + i) * HD + tx * 3 + j] = acc[i][j];
}

// ---------------- softmax over rows of 48x48 with norm+temperature ---------
__global__ void softmax_kernel(const float* __restrict__ gram, const float* __restrict__ inv,
                               const float* __restrict__ temp, float* __restrict__ attn)
{
    int gi = blockIdx.x;
    int i = gi % HD; int bh = gi / HD;
    int b = bh >> 3, h = bh & 7;
    int tid = threadIdx.x;     // 64
    float v = -3.4e38f;
    if (tid < HD) {
        float qi = inv[b * 2 * Cc + h * HD + i];
        float kj = inv[b * 2 * Cc + Cc + h * HD + tid];
        v = gram[(size_t)bh * HD * HD + i * HD + tid] * qi * kj * temp[h];
    }
    __shared__ float red[64];
    red[tid] = v; __syncthreads();
    for (int st = 32; st > 0; st >>= 1) {
        if (tid < st) red[tid] = fmaxf(red[tid], red[tid + st]);
        __syncthreads();
    }
    float m = red[0]; __syncthreads();
    float e = (tid < HD) ? expf(v - m) : 0.f;
    red[tid] = e; __syncthreads();
    for (int st = 32; st > 0; st >>= 1) {
        if (tid < st) red[tid] += red[tid + st];
        __syncthreads();
    }
    float s = red[0];
    if (tid < HD) attn[(size_t)bh * HD * HD + i * HD + tid] = e / s;
}

// ---------------- at = attn (48x48) @ v (48xN) ------------------------------
__global__ __launch_bounds__(128)
void attnv_kernel(const float* __restrict__ qkv, const float* __restrict__ attn,
                  float* __restrict__ out)
{
    int bh = blockIdx.y; int b = bh >> 3, h = bh & 7;
    int n = blockIdx.x * 128 + threadIdx.x;
    __shared__ float sa[HD * HD];
    for (int e = threadIdx.x; e < HD * HD; e += 128)
        sa[e] = attn[(size_t)bh * HD * HD + e];
    __syncthreads();
    const float* vp = qkv + (size_t)b * 3 * CN + 2 * CN + (size_t)h * HD * NN;
    float vr[HD];
    #pragma unroll
    for (int j = 0; j < HD; j++) vr[j] = vp[(size_t)j * NN + n];
    float* op = out + (size_t)b * CN + (size_t)h * HD * NN;
    for (int i = 0; i < HD; i++) {
        float s = 0.f;
        #pragma unroll
        for (int j = 0; j < HD; j++) s += sa[i * HD + j] * vr[j];
        op[(size_t)i * NN + n] = s;
    }
}

// ---------------- generic depthwise conv ------------------------------------
__global__ void dwconv_kernel(const float* __restrict__ in, const float* __restrict__ w,
                              const float* __restrict__ bias, float* __restrict__ out,
                              int C, int ks, int pad, int dil, int total)
{
    int idx = blockIdx.x * 256 + threadIdx.x;
    if (idx >= total) return;
    int x = idx & (WW - 1);
    int h = (idx >> 6) & (HH - 1);
    int c = (idx >> 12) % C;
    int b = idx / (C * NN);
    const float* ip = in + (size_t)(b * C + c) * NN;
    const float* wp = w + c * ks * ks;
    float acc = bias[c];
    for (int ky = 0; ky < ks; ky++) {
        int y = h - pad + ky * dil;
        if ((unsigned)y >= (unsigned)HH) continue;
        for (int kx = 0; kx < ks; kx++) {
            int xx = x - pad + kx * dil;
            if ((unsigned)xx >= (unsigned)WW) continue;
            acc += ip[y * WW + xx] * wp[ky * ks + kx];
        }
    }
    out[idx] = acc;
}

// ---------------- spatial mean per (b,c) -------------------------------------
__global__ void mean_kernel(const float* __restrict__ in, float* __restrict__ out)
{
    int bc = blockIdx.x;
    const float* p = in + (size_t)bc * NN;
    float s = 0.f;
    for (int i = threadIdx.x; i < NN; i += 256) s += p[i];
    __shared__ float red[256];
    red[threadIdx.x] = s; __syncthreads();
    for (int st = 128; st > 0; st >>= 1) {
        if (threadIdx.x < st) red[threadIdx.x] += red[threadIdx.x + st];
        __syncthreads();
    }
    if (threadIdx.x == 0) out[bc] = red[0] * (1.f / NN);
}

// ---------------- ci1: tiny 64x64 1x1 conv on means --------------------------
__global__ void ci1_kernel(const float* __restrict__ w, const float* __restrict__ bias,
                           const float* __restrict__ tmean, float* __restrict__ outv)
{
    int b = blockIdx.x; int co = threadIdx.x;       // 64 threads
    __shared__ float tm[C6c];
    tm[co] = tmean[b * C6c + co]; __syncthreads();
    float acc = bias[co];
    #pragma unroll
    for (int ci = 0; ci < C6c; ci++) acc += w[co * C6c + ci] * tm[ci];
    outv[b * C6c + co] = acc;
}

// ---------------- out = t * ci1[b,c] * ci2 ----------------------------------
__global__ void mul3_kernel(const float* __restrict__ t, const float* __restrict__ ci1v,
                            const float* __restrict__ ci2, float* __restrict__ out, int total)
{
    int idx = blockIdx.x * 256 + threadIdx.x;
    if (idx >= total) return;
    int c = (idx >> 12) % C6c;
    int b = idx / (C6c * NN);
    out[idx] = t[idx] * ci1v[b * C6c + c] * ci2[idx];
}

// ---------------- gated = gelu(x1)*x2 (split along channels) ----------------
__global__ void gelugate_kernel(const float* __restrict__ d, float* __restrict__ out, int total)
{
    int idx = blockIdx.x * 256 + threadIdx.x;
    if (idx >= total) return;
    int n = idx & (NN - 1);
    int j = (idx >> 12) % C4c;
    int b = idx / (C4c * NN);
    const float* dp = d + (size_t)b * C2c * NN;
    float x1 = dp[(size_t)j * NN + n];
    float x2 = dp[(size_t)(j + C4c) * NN + n];
    float g = 0.5f * x1 * (1.f + erff(x1 * 0.70710678118654752f));
    out[idx] = g * x2;
}

// ---------------- final combine ----------------------------------------------
__global__ void combine_kernel(const float* __restrict__ at, const float* __restrict__ chmap,
                               const float* __restrict__ spmap, const float* __restrict__ convx,
                               const float* __restrict__ cm, float* __restrict__ y, int total)
{
    int idx = blockIdx.x * 256 + threadIdx.x;
    if (idx >= total) return;
    int c = (idx >> 12) % Cc;
    int b = idx / (Cc * NN);
    float s1 = 1.f / (1.f + expf(-spmap[idx]));
    float s2 = 1.f / (1.f + expf(-cm[b * Cc + c]));
    y[idx] = (at[idx] + chmap[idx]) * s1 + convx[idx] * s2;
}

// ================================================================= launch ===
extern "C" void kernel_launch(void* const* d_in, const int* in_sizes, int n_in,
                              void* d_out, int out_size)
{
    const float* x           = (const float*)d_in[0];
    const float* temperature = (const float*)d_in[1];
    const float* qkv_w       = (const float*)d_in[2];
    const float* proj_w      = (const float*)d_in[3];
    const float* proj_b      = (const float*)d_in[4];
    const float* dw1_w       = (const float*)d_in[5];
    const float* dw1_b       = (const float*)d_in[6];
    const float* dw2_w       = (const float*)d_in[7];
    const float* dw2_b       = (const float*)d_in[8];
    const float* cp_in_w     = (const float*)d_in[9];
    const float* cp_in_b     = (const float*)d_in[10];
    const float* ci1_w       = (const float*)d_in[11];
    const float* ci1_b       = (const float*)d_in[12];
    const float* ci2a_w      = (const float*)d_in[13];
    const float* ci2a_b      = (const float*)d_in[14];
    const float* ci2b_w      = (const float*)d_in[15];
    const float* ci2b_b      = (const float*)d_in[16];
    const float* ci2c_w      = (const float*)d_in[17];
    const float* ci2c_b      = (const float*)d_in[18];
    const float* cp_out_w    = (const float*)d_in[19];
    const float* cp_out_b    = (const float*)d_in[20];
    const float* sp_in_w     = (const float*)d_in[21];
    const float* sp_in_b     = (const float*)d_in[22];
    const float* sp_dw_w     = (const float*)d_in[23];
    const float* sp_dw_b     = (const float*)d_in[24];
    const float* sp_out_w    = (const float*)d_in[25];
    const float* sp_out_b    = (const float*)d_in[26];
    float* out = (float*)d_out;

    float *qkv, *at, *t1, *convx, *chmap, *spmap, *y, *tt, *u1, *u2, *sp, *spd,
          *gated, *inv, *gram, *attn, *tmean, *ci1v, *cm;
    cudaGetSymbolAddress((void**)&qkv,   g_qkv);
    cudaGetSymbolAddress((void**)&at,    g_at);
    cudaGetSymbolAddress((void**)&t1,    g_t1);
    cudaGetSymbolAddress((void**)&convx, g_convx);
    cudaGetSymbolAddress((void**)&chmap, g_chmap);
    cudaGetSymbolAddress((void**)&spmap, g_spmap);
    cudaGetSymbolAddress((void**)&y,     g_y);
    cudaGetSymbolAddress((void**)&tt,    g_tt);
    cudaGetSymbolAddress((void**)&u1,    g_u1);
    cudaGetSymbolAddress((void**)&u2,    g_u2);
    cudaGetSymbolAddress((void**)&sp,    g_sp);
    cudaGetSymbolAddress((void**)&spd,   g_spd);
    cudaGetSymbolAddress((void**)&gated, g_gated);
    cudaGetSymbolAddress((void**)&inv,   g_inv);
    cudaGetSymbolAddress((void**)&gram,  g_gram);
    cudaGetSymbolAddress((void**)&attn,  g_attn);
    cudaGetSymbolAddress((void**)&tmean, g_tmean);
    cudaGetSymbolAddress((void**)&ci1v,  g_ci1v);
    cudaGetSymbolAddress((void**)&cm,    g_cm);

    // 1. QKV projection: (B,1152,N) = qkv_w @ x
    gemm64x128<<<dim3(32, 18, Bb), 256>>>(qkv_w, x, nullptr, qkv, 3 * Cc, Cc, (long long)CN);
    // 2. L2 norms of q,k rows
    rownorm_kernel<<<Bb * 2 * Cc, 256>>>(qkv, inv);
    // 3. gram matrices (48x48 per b,h)
    gram_kernel<<<Bb * HEADS, 256>>>(qkv, gram);
    // 4. scaled softmax
    softmax_kernel<<<Bb * HEADS * HD, 64>>>(gram, inv, temperature, attn);
    // 5. at = attn @ v
    attnv_kernel<<<dim3(NN / 128, Bb * HEADS), 128>>>(qkv, attn, at);
    // 6. dw1: 1x1 conv on v
    gemm64x128<<<dim3(32, 6, Bb), 256>>>(dw1_w, qkv + 2 * CN, dw1_b, t1, Cc, Cc, 3LL * CN);
    // 7. dw2: depthwise 3x3
    dwconv_kernel<<<(Bb * CN) / 256, 256>>>(t1, dw2_w, dw2_b, convx, Cc, 3, 1, 1, Bb * CN);
    // 8. cp_in: 1x1 C->64 on attention output
    gemm64x128<<<dim3(32, 1, Bb), 256>>>(cp_in_w, at, cp_in_b, tt, C6c, Cc, (long long)CN);
    // 9. spatial mean of t
    mean_kernel<<<Bb * C6c, 256>>>(tt, tmean);
    // 10. ci1 tiny conv
    ci1_kernel<<<Bb, C6c>>>(ci1_w, ci1_b, tmean, ci1v);
    // 11. ci2a: dw 3x3
    dwconv_kernel<<<(Bb * C6c * NN) / 256, 256>>>(tt, ci2a_w, ci2a_b, u1, C6c, 3, 1, 1, Bb * C6c * NN);
    // 12. ci2b: dw 7x7 pad9 dil3
    dwconv_kernel<<<(Bb * C6c * NN) / 256, 256>>>(u1, ci2b_w, ci2b_b, u2, C6c, 7, 9, 3, Bb * C6c * NN);
    // 13. ci2c: 1x1 64->64
    gemm64x128<<<dim3(32, 1, Bb), 256>>>(ci2c_w, u2, ci2c_b, u1, C6c, C6c, (long long)C6c * NN);
    // 14. t * ci1 * ci2
    mul3_kernel<<<(Bb * C6c * NN) / 256, 256>>>(tt, ci1v, u1, u2, Bb * C6c * NN);
    // 15. cp_out: 1x1 64->384
    gemm64x128<<<dim3(32, 6, Bb), 256>>>(cp_out_w, u2, cp_out_b, chmap, Cc, C6c, (long long)C6c * NN);
    // 16. cm = mean(channel_map)
    mean_kernel<<<Bb * Cc, 256>>>(chmap, cm);
    // 17. sp_in: 1x1 C->192 on conv branch
    gemm64x128<<<dim3(32, 3, Bb), 256>>>(sp_in_w, convx, sp_in_b, sp, C2c, Cc, (long long)CN);
    // 18. sp_dw: dw 3x3
    dwconv_kernel<<<(Bb * C2c * NN) / 256, 256>>>(sp, sp_dw_w, sp_dw_b, spd, C2c, 3, 1, 1, Bb * C2c * NN);
    // 19. gelu gate
    gelugate_kernel<<<(Bb * C4c * NN) / 256, 256>>>(spd, gated, Bb * C4c * NN);
    // 20. sp_out: 1x1 96->384
    gemm64x128<<<dim3(32, 6, Bb), 256>>>(sp_out_w, gated, sp_out_b, spmap, Cc, C4c, (long long)C4c * NN);
    // 21. combine: y = (at+chmap)*sig(spmap) + convx*sig(cm)
    combine_kernel<<<(Bb * CN) / 256, 256>>>(at, chmap, spmap, convx, cm, y, Bb * CN);
    // 22. final projection -> d_out in (B,C,N) layout
    gemm64x128<<<dim3(32, 6, Bb), 256>>>(proj_w, y, proj_b, out, Cc, Cc, (long long)CN);
}

// round 4
// speedup vs baseline: 1.9568x; 1.9513x over previous
#include <cuda_runtime.h>
#include <cstdint>
#include <math.h>

#define Bb     8
#define Cc     384
#define NN     4096
#define HEADS  8
#define HD     48
#define CN     (Cc*NN)
#define C3     1152
#define C6c    64
#define C2c    192
#define C4c    96

// ---------------- scratch ----------------------------------------------------
__device__ float g_xT  [Bb*NN*Cc];         // (B,N,C)
__device__ float g_qkvT[(size_t)Bb*NN*C3]; // (B,N,3C)
__device__ float g_at  [Bb*NN*Cc];
__device__ float g_t1  [Bb*NN*Cc];
__device__ float g_convx[Bb*NN*Cc];
__device__ float g_chmap[Bb*NN*Cc];
__device__ float g_spmap[Bb*NN*Cc];
__device__ float g_y   [Bb*NN*Cc];
__device__ float g_tt  [Bb*NN*C6c];
__device__ float g_u1  [Bb*NN*C6c];
__device__ float g_u2  [Bb*NN*C6c];
__device__ float g_u3  [Bb*NN*C6c];
__device__ float g_sp  [Bb*NN*C2c];
__device__ float g_spd [Bb*NN*C2c];
__device__ float g_gated[Bb*NN*C4c];
__device__ float g_sumsq[Bb*2*Cc];
__device__ float g_gram [Bb*HEADS*HD*HD];
__device__ float g_attn [Bb*HEADS*HD*HD];
__device__ float g_tmean[Bb*C6c];
__device__ float g_ci1v [Bb*C6c];
__device__ float g_cm  [Bb*Cc];

__device__ __forceinline__ float tf32r(float f) {
    uint32_t u; asm("cvt.rna.tf32.f32 %0, %1;" : "=r"(u) : "f"(f));
    return __uint_as_float(u);
}
__device__ __forceinline__ void mma_tf32(float* d, float a0, float a1, float a2, float a3,
                                         float b0, float b1) {
    asm volatile(
        "mma.sync.aligned.m16n8k8.row.col.f32.tf32.tf32.f32 "
        "{%0,%1,%2,%3}, {%4,%5,%6,%7}, {%8,%9}, {%0,%1,%2,%3};"
        : "+f"(d[0]), "+f"(d[1]), "+f"(d[2]), "+f"(d[3])
        : "r"(__float_as_uint(a0)), "r"(__float_as_uint(a1)),
          "r"(__float_as_uint(a2)), "r"(__float_as_uint(a3)),
          "r"(__float_as_uint(b0)), "r"(__float_as_uint(b1)));
}

// ---------------- tf32 mma.sync GEMM ------------------------------------------
// D[i][j] = sum_k Arows[i][k] * Brows[j][k]   (both operands K-major)
// CTA tile: 128 A-rows x (NI*32) B-rows, BK=32. 8 warps, warp = 64 x (NI*8).
// SMEM paired-k layout: within each k-step of 8, cols stored as
// (c, c+4) pairs so tf32 fragments load as single LDS.64, row stride 40 floats.
#define RS 40
template<int NI>
__global__ __launch_bounds__(256)
void mma_gemm(const float* __restrict__ A, int lda, long long abatch,
              const float* __restrict__ B, int ldb, long long bbatch,
              const float* __restrict__ bias, int biasRowMode,
              float* __restrict__ Out, int ldo, long long obatch, int K)
{
    constexpr int n_tile = NI * 32;
    __shared__ float As[128 * RS];
    __shared__ float Bs[128 * RS];

    const int tid  = threadIdx.x;
    const int wid  = tid >> 5, lane = tid & 31;
    const int g    = lane >> 2, tig = lane & 3;
    const int z    = blockIdx.z;
    const int arow0 = blockIdx.y * 128;
    const int brow0 = blockIdx.x * n_tile;
    const int wm = (wid & 1) * 64;
    const int wn = (wid >> 1) * (NI * 8);

    const float* Ab = A + (size_t)z * abatch + (size_t)arow0 * lda;
    const float* Bp = B + (size_t)z * bbatch + (size_t)brow0 * ldb;

    float c[4][NI][4];
    #pragma unroll
    for (int mi = 0; mi < 4; mi++)
        #pragma unroll
        for (int ni = 0; ni < NI; ni++)
            #pragma unroll
            for (int q = 0; q < 4; q++) c[mi][ni][q] = 0.f;

    const int r = tid >> 1, h = tid & 1;
    const int nch = K >> 5;
    for (int kc = 0; kc < nch; kc++) {
        if (kc) __syncthreads();
        // A tile fill: each thread handles row r, 16 k values (half h)
        {
            const float* src = Ab + (size_t)r * lda + kc * 32 + h * 16;
            float v[16];
            #pragma unroll
            for (int q = 0; q < 4; q++) {
                float4 t4 = *(const float4*)(src + q * 4);
                v[q*4+0] = t4.x; v[q*4+1] = t4.y; v[q*4+2] = t4.z; v[q*4+3] = t4.w;
            }
            float* dst = As + r * RS + h * 16;
            #pragma unroll
            for (int p = 0; p < 4; p++) {
                *(float2*)(dst + p*2)     = make_float2(tf32r(v[p]),   tf32r(v[p+4]));
                *(float2*)(dst + 8 + p*2) = make_float2(tf32r(v[8+p]), tf32r(v[12+p]));
            }
        }
        // B tile fill
        for (int idx = tid; idx < n_tile * 2; idx += 256) {
            const int rb = idx >> 1, hb = idx & 1;
            const float* src = Bp + (size_t)rb * ldb + kc * 32 + hb * 16;
            float v[16];
            #pragma unroll
            for (int q = 0; q < 4; q++) {
                float4 t4 = *(const float4*)(src + q * 4);
                v[q*4+0] = t4.x; v[q*4+1] = t4.y; v[q*4+2] = t4.z; v[q*4+3] = t4.w;
            }
            float* dst = Bs + rb * RS + hb * 16;
            #pragma unroll
            for (int p = 0; p < 4; p++) {
                *(float2*)(dst + p*2)     = make_float2(tf32r(v[p]),   tf32r(v[p+4]));
                *(float2*)(dst + 8 + p*2) = make_float2(tf32r(v[8+p]), tf32r(v[12+p]));
            }
        }
        __syncthreads();

        #pragma unroll
        for (int ks = 0; ks < 4; ks++) {
            float2 afr[4][2];
            #pragma unroll
            for (int mi = 0; mi < 4; mi++) {
                const float* ap = As + (wm + mi * 16 + g) * RS + ks * 8 + tig * 2;
                afr[mi][0] = *(const float2*)ap;            // a0(.x), a2(.y)
                afr[mi][1] = *(const float2*)(ap + 8 * RS); // a1(.x), a3(.y)
            }
            #pragma unroll
            for (int ni = 0; ni < NI; ni++) {
                const float* bp = Bs + (wn + ni * 8 + g) * RS + ks * 8 + tig * 2;
                float2 bf = *(const float2*)bp;             // b0(.x), b1(.y)
                #pragma unroll
                for (int mi = 0; mi < 4; mi++)
                    mma_tf32(c[mi][ni], afr[mi][0].x, afr[mi][1].x,
                             afr[mi][0].y, afr[mi][1].y, bf.x, bf.y);
            }
        }
    }

    // epilogue: direct register -> global
    #pragma unroll
    for (int mi = 0; mi < 4; mi++) {
        const int row = arow0 + wm + mi * 16 + g;
        float bv0 = 0.f, bv1 = 0.f;
        if (bias && biasRowMode) { bv0 = bias[row]; bv1 = bias[row + 8]; }
        #pragma unroll
        for (int ni = 0; ni < NI; ni++) {
            const int col = brow0 + wn + ni * 8 + tig * 2;
            float bc0 = 0.f, bc1 = 0.f;
            if (bias && !biasRowMode) { bc0 = bias[col]; bc1 = bias[col + 1]; }
            float* op = Out + (size_t)z * obatch + (size_t)row * ldo + col;
            *(float2*)op = make_float2(c[mi][ni][0] + bv0 + bc0,
                                       c[mi][ni][1] + bv0 + bc1);
            *(float2*)(op + 8 * (size_t)ldo) = make_float2(c[mi][ni][2] + bv1 + bc0,
                                                           c[mi][ni][3] + bv1 + bc1);
        }
    }
}

// ---------------- small kernels ------------------------------------------------
__global__ void zero_kernel() {
    int i = blockIdx.x * 256 + threadIdx.x;
    if (i < Bb*2*Cc)          g_sumsq[i] = 0.f;
    if (i < Bb*HEADS*HD*HD)   g_gram[i]  = 0.f;
    if (i < Bb*C6c)           g_tmean[i] = 0.f;
    if (i < Bb*Cc)            g_cm[i]    = 0.f;
}

__global__ void transpose_kernel(const float* __restrict__ in) {
    __shared__ float t[32][33];
    int b = blockIdx.z, c0 = blockIdx.y * 32, n0 = blockIdx.x * 32;
    int tx = threadIdx.x, ty = threadIdx.y;
    for (int i = ty; i < 32; i += 8)
        t[i][tx] = in[(size_t)b * CN + (size_t)(c0 + i) * NN + n0 + tx];
    __syncthreads();
    for (int i = ty; i < 32; i += 8)
        g_xT[(size_t)b * CN + (size_t)(n0 + i) * Cc + c0 + tx] = t[tx][i];
}

__global__ void sumsq_kernel() {
    int b = blockIdx.z;
    int c = blockIdx.y * 256 + threadIdx.x;       // 0..767
    int n0 = blockIdx.x * 512;
    const float* p = g_qkvT + (size_t)b * NN * C3 + c;
    float s = 0.f;
    for (int n = n0; n < n0 + 512; n++) { float v = p[(size_t)n * C3]; s += v * v; }
    atomicAdd(&g_sumsq[b * 2 * Cc + c], s);
}

__global__ __launch_bounds__(256) void gram_kernel() {
    int bh = blockIdx.y; int b = bh >> 3, h = bh & 7;
    int n0 = blockIdx.x * 512;
    const float* qp = g_qkvT + (size_t)b * NN * C3 + h * HD;
    const float* kp = qp + Cc;
    __shared__ float qs[32][HD], ks[32][HD];
    int tid = threadIdx.x, tx = tid & 15, ty = tid >> 4;
    float acc[3][3] = {};
    for (int nb = 0; nb < 512; nb += 32) {
        for (int e = tid; e < 32 * HD; e += 256) {
            int rr = e / HD, cc = e % HD;
            size_t off = (size_t)(n0 + nb + rr) * C3 + cc;
            qs[rr][cc] = qp[off]; ks[rr][cc] = kp[off];
        }
        __syncthreads();
        #pragma unroll
        for (int kk = 0; kk < 32; kk++) {
            float qr[3], kr[3];
            #pragma unroll
            for (int i = 0; i < 3; i++) qr[i] = qs[kk][ty * 3 + i];
            #pragma unroll
            for (int j = 0; j < 3; j++) kr[j] = ks[kk][tx * 3 + j];
            #pragma unroll
            for (int i = 0; i < 3; i++)
                #pragma unroll
                for (int j = 0; j < 3; j++) acc[i][j] += qr[i] * kr[j];
        }
        __syncthreads();
    }
    float* gp = g_gram + (size_t)bh * HD * HD;
    #pragma unroll
    for (int i = 0; i < 3; i++)
        #pragma unroll
        for (int j = 0; j < 3; j++)
            atomicAdd(&gp[(ty * 3 + i) * HD + tx * 3 + j], acc[i][j]);
}

__global__ void softmax_kernel(const float* __restrict__ temp) {
    int gi = blockIdx.x;
    int i = gi % HD; int bh = gi / HD;
    int b = bh >> 3, h = bh & 7;
    int tid = threadIdx.x;      // 64
    float qi = rsqrtf(fmaxf(g_sumsq[b * 2 * Cc + h * HD + i], 1e-24f));
    float v = -3.4e38f;
    if (tid < HD) {
        float kj = rsqrtf(fmaxf(g_sumsq[b * 2 * Cc + Cc + h * HD + tid], 1e-24f));
        v = g_gram[(size_t)bh * HD * HD + i * HD + tid] * qi * kj * temp[h];
    }
    __shared__ float red[64];
    red[tid] = v; __syncthreads();
    for (int st = 32; st > 0; st >>= 1) {
        if (tid < st) red[tid] = fmaxf(red[tid], red[tid + st]);
        __syncthreads();
    }
    float m = red[0]; __syncthreads();
    float e = (tid < HD) ? expf(v - m) : 0.f;
    red[tid] = e; __syncthreads();
    for (int st = 32; st > 0; st >>= 1) {
        if (tid < st) red[tid] += red[tid + st];
        __syncthreads();
    }
    if (tid < HD) g_attn[(size_t)bh * HD * HD + i * HD + tid] = e / red[0];
}

__global__ __launch_bounds__(128) void attnv_kernel() {
    int bh = blockIdx.y; int b = bh >> 3, h = bh & 7;
    int n = blockIdx.x * 128 + threadIdx.x;
    __shared__ float sa[HD * HD];
    for (int e = threadIdx.x; e < HD * HD; e += 128)
        sa[e] = g_attn[(size_t)bh * HD * HD + e];
    __syncthreads();
    const float* vp = g_qkvT + (size_t)(b * NN + n) * C3 + 2 * Cc + h * HD;
    float vr[HD];
    #pragma unroll
    for (int j = 0; j < HD; j++) vr[j] = vp[j];
    float* op = g_at + (size_t)(b * NN + n) * Cc + h * HD;
    for (int i = 0; i < HD; i++) {
        float s = 0.f;
        #pragma unroll
        for (int j = 0; j < HD; j++) s += sa[i * HD + j] * vr[j];
        op[i] = s;
    }
}

__global__ void dwconv_nhwc(const float* __restrict__ in, const float* __restrict__ w,
                            const float* __restrict__ bias, float* __restrict__ out,
                            int C, int ks, int pad, int dil)
{
    int idx = blockIdx.x * 256 + threadIdx.x;
    int c = idx % C;
    int rest = idx / C;
    int xx = rest & 63, yy = (rest >> 6) & 63;
    int b = rest >> 12;
    const float* ip = in + (size_t)b * NN * C + c;
    const float* wp = w + c * ks * ks;
    float acc = bias[c];
    for (int ky = 0; ky < ks; ky++) {
        int y = yy - pad + ky * dil;
        if ((unsigned)y >= 64u) continue;
        for (int kx = 0; kx < ks; kx++) {
            int x = xx - pad + kx * dil;
            if ((unsigned)x >= 64u) continue;
            acc += ip[(size_t)(y * 64 + x) * C] * wp[ky * ks + kx];
        }
    }
    out[idx] = acc;
}

__global__ void tmean_kernel() {
    int b = blockIdx.y, n0 = blockIdx.x * 512, c = threadIdx.x;
    const float* p = g_tt + (size_t)b * NN * C6c + c;
    float s = 0.f;
    for (int n = n0; n < n0 + 512; n++) s += p[(size_t)n * C6c];
    atomicAdd(&g_tmean[b * C6c + c], s);
}

__global__ void ci1_kernel(const float* __restrict__ w, const float* __restrict__ bias) {
    int b = blockIdx.x, co = threadIdx.x;
    __shared__ float tm[C6c];
    tm[co] = g_tmean[b * C6c + co] * (1.f / NN);
    __syncthreads();
    float a = bias[co];
    #pragma unroll
    for (int ci = 0; ci < C6c; ci++) a += w[co * C6c + ci] * tm[ci];
    g_ci1v[b * C6c + co] = a;
}

__global__ void mul3_kernel() {
    int idx = blockIdx.x * 256 + threadIdx.x;
    int c = idx % C6c;
    int b = idx / (NN * C6c);
    g_u1[idx] = g_tt[idx] * g_ci1v[b * C6c + c] * g_u3[idx];
}

__global__ void cm_kernel() {
    int b = blockIdx.y, n0 = blockIdx.x * 512, c = threadIdx.x;   // 384 threads
    const float* p = g_chmap + (size_t)b * NN * Cc + c;
    float s = 0.f;
    for (int n = n0; n < n0 + 512; n++) s += p[(size_t)n * Cc];
    atomicAdd(&g_cm[b * Cc + c], s);
}

__global__ void gelugate_kernel() {
    int idx = blockIdx.x * 256 + threadIdx.x;
    int j = idx % C4c;
    int bn = idx / C4c;
    float x1 = g_spd[(size_t)bn * C2c + j];
    float x2 = g_spd[(size_t)bn * C2c + j + C4c];
    float g = 0.5f * x1 * (1.f + erff(x1 * 0.70710678118654752f));
    g_gated[idx] = g * x2;
}

__global__ void combine_kernel() {
    int idx = blockIdx.x * 256 + threadIdx.x;
    int c = idx % Cc;
    int b = idx / (NN * Cc);
    float s1 = 1.f / (1.f + expf(-g_spmap[idx]));
    float s2 = 1.f / (1.f + expf(-g_cm[b * Cc + c] * (1.f / NN)));
    g_y[idx] = (g_at[idx] + g_chmap[idx]) * s1 + g_convx[idx] * s2;
}

// ================================================================= launch ===
extern "C" void kernel_launch(void* const* d_in, const int* in_sizes, int n_in,
                              void* d_out, int out_size)
{
    const float* x           = (const float*)d_in[0];
    const float* temperature = (const float*)d_in[1];
    const float* qkv_w       = (const float*)d_in[2];
    const float* proj_w      = (const float*)d_in[3];
    const float* proj_b      = (const float*)d_in[4];
    const float* dw1_w       = (const float*)d_in[5];
    const float* dw1_b       = (const float*)d_in[6];
    const float* dw2_w       = (const float*)d_in[7];
    const float* dw2_b       = (const float*)d_in[8];
    const float* cp_in_w     = (const float*)d_in[9];
    const float* cp_in_b     = (const float*)d_in[10];
    const float* ci1_w       = (const float*)d_in[11];
    const float* ci1_b       = (const float*)d_in[12];
    const float* ci2a_w      = (const float*)d_in[13];
    const float* ci2a_b      = (const float*)d_in[14];
    const float* ci2b_w      = (const float*)d_in[15];
    const float* ci2b_b      = (const float*)d_in[16];
    const float* ci2c_w      = (const float*)d_in[17];
    const float* ci2c_b      = (const float*)d_in[18];
    const float* cp_out_w    = (const float*)d_in[19];
    const float* cp_out_b    = (const float*)d_in[20];
    const float* sp_in_w     = (const float*)d_in[21];
    const float* sp_in_b     = (const float*)d_in[22];
    const float* sp_dw_w     = (const float*)d_in[23];
    const float* sp_dw_b     = (const float*)d_in[24];
    const float* sp_out_w    = (const float*)d_in[25];
    const float* sp_out_b    = (const float*)d_in[26];
    float* out = (float*)d_out;

    float *xT, *qkvT, *at, *t1, *convx, *chmap, *spmap, *y, *tt, *u1, *u2, *u3,
          *sp, *spd, *gated;
    cudaGetSymbolAddress((void**)&xT,    g_xT);
    cudaGetSymbolAddress((void**)&qkvT,  g_qkvT);
    cudaGetSymbolAddress((void**)&at,    g_at);
    cudaGetSymbolAddress((void**)&t1,    g_t1);
    cudaGetSymbolAddress((void**)&convx, g_convx);
    cudaGetSymbolAddress((void**)&chmap, g_chmap);
    cudaGetSymbolAddress((void**)&spmap, g_spmap);
    cudaGetSymbolAddress((void**)&y,     g_y);
    cudaGetSymbolAddress((void**)&tt,    g_tt);
    cudaGetSymbolAddress((void**)&u1,    g_u1);
    cudaGetSymbolAddress((void**)&u2,    g_u2);
    cudaGetSymbolAddress((void**)&u3,    g_u3);
    cudaGetSymbolAddress((void**)&sp,    g_sp);
    cudaGetSymbolAddress((void**)&spd,   g_spd);
    cudaGetSymbolAddress((void**)&gated, g_gated);

    const long long bCN  = CN;
    const long long b3CN = (long long)NN * C3;
    const long long b64  = (long long)NN * C6c;
    const long long b192 = (long long)NN * C2c;
    const long long b96  = (long long)NN * C4c;

    zero_kernel<<<576, 256>>>();
    transpose_kernel<<<dim3(128, 12, Bb), dim3(32, 8)>>>(x);

    // qkv: (B,N,1152) = xT @ qkv_w^T
    mma_gemm<4><<<dim3(9, 32, Bb), 256>>>(xT, Cc, bCN, qkv_w, Cc, 0,
                                          nullptr, 0, qkvT, C3, b3CN, Cc);
    sumsq_kernel<<<dim3(8, 3, Bb), 256>>>();
    gram_kernel<<<dim3(8, Bb * HEADS), 256>>>();
    softmax_kernel<<<Bb * HEADS * HD, 64>>>(temperature);
    attnv_kernel<<<dim3(NN / 128, Bb * HEADS), 128>>>();

    // dw1 on v: (B,N,384)
    mma_gemm<4><<<dim3(3, 32, Bb), 256>>>(qkvT + 2 * Cc, C3, b3CN, dw1_w, Cc, 0,
                                          dw1_b, 0, t1, Cc, bCN, Cc);
    dwconv_nhwc<<<(Bb * NN * Cc) / 256, 256>>>(t1, dw2_w, dw2_b, convx, Cc, 3, 1, 1);

    // cp_in: (B,N,64)
    mma_gemm<2><<<dim3(1, 32, Bb), 256>>>(at, Cc, bCN, cp_in_w, Cc, 0,
                                          cp_in_b, 0, tt, C6c, b64, Cc);
    tmean_kernel<<<dim3(8, Bb), 64>>>();
    ci1_kernel<<<Bb, C6c>>>(ci1_w, ci1_b);
    dwconv_nhwc<<<(Bb * NN * C6c) / 256, 256>>>(tt, ci2a_w, ci2a_b, u1, C6c, 3, 1, 1);
    dwconv_nhwc<<<(Bb * NN * C6c) / 256, 256>>>(u1, ci2b_w, ci2b_b, u2, C6c, 7, 9, 3);
    mma_gemm<2><<<dim3(1, 32, Bb), 256>>>(u2, C6c, b64, ci2c_w, C6c, 0,
                                          ci2c_b, 0, u3, C6c, b64, C6c);
    mul3_kernel<<<(Bb * NN * C6c) / 256, 256>>>();
    mma_gemm<4><<<dim3(3, 32, Bb), 256>>>(u1, C6c, b64, cp_out_w, C6c, 0,
                                          cp_out_b, 0, chmap, Cc, bCN, C6c);
    cm_kernel<<<dim3(8, Bb), Cc>>>();

    // spatial projection branch
    mma_gemm<3><<<dim3(2, 32, Bb), 256>>>(convx, Cc, bCN, sp_in_w, Cc, 0,
                                          sp_in_b, 0, sp, C2c, b192, Cc);
    dwconv_nhwc<<<(Bb * NN * C2c) / 256, 256>>>(sp, sp_dw_w, sp_dw_b, spd, C2c, 3, 1, 1);
    gelugate_kernel<<<(Bb * NN * C4c) / 256, 256>>>();
    mma_gemm<4><<<dim3(3, 32, Bb), 256>>>(gated, C4c, b96, sp_out_w, C4c, 0,
                                          sp_out_b, 0, spmap, Cc, bCN, C4c);

    combine_kernel<<<(Bb * NN * Cc) / 256, 256>>>();

    // final projection, output directly in (B,C,N): A=proj_w (rows=cout), B=y (rows=n)
    mma_gemm<4><<<dim3(32, 3, Bb), 256>>>(proj_w, Cc, 0, y, Cc, bCN,
                                          proj_b, 1, out, NN, bCN, Cc);
}

// round 5
// speedup vs baseline: 2.8081x; 1.4351x over previous
#include <cuda_runtime.h>
#include <cstdint>
#include <math.h>

#define Bb     8
#define Cc     384
#define NN     4096
#define HEADS  8
#define HD     48
#define CN     (Cc*NN)
#define C3     1152
#define C6c    64
#define C2c    192
#define C4c    96

// ---------------- scratch ----------------------------------------------------
__device__ float g_xT  [Bb*NN*Cc];         // (B,N,C)
__device__ float g_qkvT[(size_t)Bb*NN*C3]; // (B,N,3C)
__device__ float g_at  [Bb*NN*Cc];
__device__ float g_t1  [Bb*NN*Cc];
__device__ float g_convx[Bb*NN*Cc];
__device__ float g_chmap[Bb*NN*Cc];
__device__ float g_spmap[Bb*NN*Cc];
__device__ float g_y   [Bb*NN*Cc];
__device__ float g_tt  [Bb*NN*C6c];
__device__ float g_u1  [Bb*NN*C6c];
__device__ float g_u2  [Bb*NN*C6c];
__device__ float g_u3  [Bb*NN*C6c];
__device__ float g_sp  [Bb*NN*C2c];
__device__ float g_gated[Bb*NN*C4c];
__device__ float g_sumsq[Bb*2*Cc];
__device__ float g_gram [Bb*HEADS*HD*HD];
__device__ float g_attn [Bb*HEADS*HD*HD];
__device__ float g_tmean[Bb*C6c];
__device__ float g_ci1v [Bb*C6c];
__device__ float g_cm  [Bb*Cc];

__device__ __forceinline__ float tf32r(float f) {
    uint32_t u; asm("cvt.rna.tf32.f32 %0, %1;" : "=r"(u) : "f"(f));
    return __uint_as_float(u);
}
__device__ __forceinline__ uint32_t smem_u32(const void* p) {
    uint32_t a;
    asm("{ .reg .u64 t; cvta.to.shared.u64 t, %1; cvt.u32.u64 %0, t; }" : "=r"(a) : "l"(p));
    return a;
}
__device__ __forceinline__ void cpa16(uint32_t dst, const float* src) {
    asm volatile("cp.async.cg.shared.global [%0], [%1], 16;"
                 :: "r"(dst), "l"(__cvta_generic_to_global(src)) : "memory");
}
#define CP_COMMIT() asm volatile("cp.async.commit_group;" ::: "memory")
#define CP_WAIT0()  asm volatile("cp.async.wait_group 0;" ::: "memory")

__device__ __forceinline__ void mma_tf32(float* d, float a0, float a1, float a2, float a3,
                                         float b0, float b1) {
    asm volatile(
        "mma.sync.aligned.m16n8k8.row.col.f32.tf32.tf32.f32 "
        "{%0,%1,%2,%3}, {%4,%5,%6,%7}, {%8,%9}, {%0,%1,%2,%3};"
        : "+f"(d[0]), "+f"(d[1]), "+f"(d[2]), "+f"(d[3])
        : "r"(__float_as_uint(a0)), "r"(__float_as_uint(a1)),
          "r"(__float_as_uint(a2)), "r"(__float_as_uint(a3)),
          "r"(__float_as_uint(b0)), "r"(__float_as_uint(b1)));
}

// ---------------- pipelined tf32 mma.sync GEMM --------------------------------
// D[i][j] = sum_k Arows[i][k] * Brows[j][k]  (both operands K-major).
// CTA: 128 A-rows x (NI*32) B-rows, BK=32, double-buffered smem via cp.async.
// Plain k-contiguous smem layout, row stride 36 floats (conflict-free frags).
// tf32 rounding applied on consume (cvt.rna) -> numerics identical to R4.
#define RSW 36
template<int NI>
__global__ __launch_bounds__(256)
void mma_gemm(const float* __restrict__ A, int lda, long long abatch,
              const float* __restrict__ B, int ldb, long long bbatch,
              const float* __restrict__ bias, int biasRowMode,
              const float* __restrict__ emul, const float* __restrict__ escale,
              float* __restrict__ Out, int ldo, long long obatch, int K)
{
    constexpr int n_tile = NI * 32;
    extern __shared__ float smem[];
    float* As0 = smem;
    float* Bs0 = smem + 128 * RSW;
    float* As1 = smem + (128 + n_tile) * RSW;
    float* Bs1 = As1 + 128 * RSW;

    const int tid  = threadIdx.x;
    const int wid  = tid >> 5, lane = tid & 31;
    const int g    = lane >> 2, tig = lane & 3;
    const int z    = blockIdx.z;
    const int arow0 = blockIdx.y * 128;
    const int brow0 = blockIdx.x * n_tile;
    const int wm = (wid & 1) * 64;
    const int wn = (wid >> 1) * (NI * 8);

    const float* Ab = A + (size_t)z * abatch + (size_t)arow0 * lda;
    const float* Bp = B + (size_t)z * bbatch + (size_t)brow0 * ldb;

    float c[4][NI][4];
    #pragma unroll
    for (int mi = 0; mi < 4; mi++)
        #pragma unroll
        for (int ni = 0; ni < NI; ni++)
            #pragma unroll
            for (int q = 0; q < 4; q++) c[mi][ni][q] = 0.f;

    // async tile loaders: 16B per cp.async, full rows (no guards; shapes exact)
    auto loadTiles = [&](int kc, float* Ad, float* Bd) {
        #pragma unroll
        for (int i = 0; i < 4; i++) {
            int e = tid + i * 256;                 // < 1024
            int row = e >> 3, seg = e & 7;
            cpa16(smem_u32(Ad + row * RSW + seg * 4),
                  Ab + (size_t)row * lda + kc * 32 + seg * 4);
        }
        #pragma unroll
        for (int i = 0; i < NI; i++) {
            int e = tid + i * 256;                 // < n_tile*8
            int row = e >> 3, seg = e & 7;
            cpa16(smem_u32(Bd + row * RSW + seg * 4),
                  Bp + (size_t)row * ldb + kc * 32 + seg * 4);
        }
        CP_COMMIT();
    };

    const int nch = K >> 5;
    loadTiles(0, As0, Bs0);

    for (int kc = 0; kc < nch; kc++) {
        CP_WAIT0();
        __syncthreads();
        if (kc + 1 < nch)
            loadTiles(kc + 1, (kc & 1) ? As0 : As1, (kc & 1) ? Bs0 : Bs1);
        const float* Ac = (kc & 1) ? As1 : As0;
        const float* Bc = (kc & 1) ? Bs1 : Bs0;

        #pragma unroll
        for (int ks = 0; ks < 4; ks++) {
            float a0[4], a1[4], a2[4], a3[4];
            #pragma unroll
            for (int mi = 0; mi < 4; mi++) {
                const float* ap = Ac + (wm + mi * 16 + g) * RSW + ks * 8 + tig;
                a0[mi] = tf32r(ap[0]);
                a2[mi] = tf32r(ap[4]);
                a1[mi] = tf32r(ap[8 * RSW]);
                a3[mi] = tf32r(ap[8 * RSW + 4]);
            }
            #pragma unroll
            for (int ni = 0; ni < NI; ni++) {
                const float* bp = Bc + (wn + ni * 8 + g) * RSW + ks * 8 + tig;
                float b0 = tf32r(bp[0]), b1 = tf32r(bp[4]);
                #pragma unroll
                for (int mi = 0; mi < 4; mi++)
                    mma_tf32(c[mi][ni], a0[mi], a1[mi], a2[mi], a3[mi], b0, b1);
            }
        }
    }

    // epilogue
    #pragma unroll
    for (int mi = 0; mi < 4; mi++) {
        const int row = arow0 + wm + mi * 16 + g;
        float bv0 = 0.f, bv1 = 0.f;
        if (bias && biasRowMode) { bv0 = bias[row]; bv1 = bias[row + 8]; }
        #pragma unroll
        for (int ni = 0; ni < NI; ni++) {
            const int col = brow0 + wn + ni * 8 + tig * 2;
            float bc0 = 0.f, bc1 = 0.f;
            if (bias && !biasRowMode) { bc0 = bias[col]; bc1 = bias[col + 1]; }
            size_t o0 = (size_t)z * obatch + (size_t)row * ldo + col;
            size_t o1 = o0 + 8 * (size_t)ldo;
            float v00 = c[mi][ni][0] + bv0 + bc0, v01 = c[mi][ni][1] + bv0 + bc1;
            float v10 = c[mi][ni][2] + bv1 + bc0, v11 = c[mi][ni][3] + bv1 + bc1;
            if (emul) {   // fused: out = t * ci1 * (gemm+bias)
                float2 m0 = *(const float2*)(emul + o0);
                float2 m1 = *(const float2*)(emul + o1);
                float s0 = escale[z * C6c + col], s1 = escale[z * C6c + col + 1];
                v00 *= m0.x * s0; v01 *= m0.y * s1;
                v10 *= m1.x * s0; v11 *= m1.y * s1;
            }
            *(float2*)(Out + o0) = make_float2(v00, v01);
            *(float2*)(Out + o1) = make_float2(v10, v11);
        }
    }
}

// ---------------- small kernels ------------------------------------------------
__global__ void zero_kernel() {
    int i = blockIdx.x * 256 + threadIdx.x;
    if (i < Bb*2*Cc)          g_sumsq[i] = 0.f;
    if (i < Bb*HEADS*HD*HD)   g_gram[i]  = 0.f;
    if (i < Bb*C6c)           g_tmean[i] = 0.f;
    if (i < Bb*Cc)            g_cm[i]    = 0.f;
}

__global__ void transpose_kernel(const float* __restrict__ in) {
    __shared__ float t[32][33];
    int b = blockIdx.z, c0 = blockIdx.y * 32, n0 = blockIdx.x * 32;
    int tx = threadIdx.x, ty = threadIdx.y;
    for (int i = ty; i < 32; i += 8)
        t[i][tx] = in[(size_t)b * CN + (size_t)(c0 + i) * NN + n0 + tx];
    __syncthreads();
    for (int i = ty; i < 32; i += 8)
        g_xT[(size_t)b * CN + (size_t)(n0 + i) * Cc + c0 + tx] = t[tx][i];
}

__global__ void sumsq_kernel() {
    int b = blockIdx.z;
    int c = blockIdx.y * 256 + threadIdx.x;       // 0..767
    int n0 = blockIdx.x * 512;
    const float* p = g_qkvT + (size_t)b * NN * C3 + c;
    float s = 0.f;
    for (int n = n0; n < n0 + 512; n++) { float v = p[(size_t)n * C3]; s += v * v; }
    atomicAdd(&g_sumsq[b * 2 * Cc + c], s);
}

__global__ __launch_bounds__(256) void gram_kernel() {
    int bh = blockIdx.y; int b = bh >> 3, h = bh & 7;
    int n0 = blockIdx.x * 512;
    const float* qp = g_qkvT + (size_t)b * NN * C3 + h * HD;
    const float* kp = qp + Cc;
    __shared__ float qs[32][HD], ks[32][HD];
    int tid = threadIdx.x, tx = tid & 15, ty = tid >> 4;
    float acc[3][3] = {};
    for (int nb = 0; nb < 512; nb += 32) {
        for (int e = tid; e < 32 * HD; e += 256) {
            int rr = e / HD, cc = e % HD;
            size_t off = (size_t)(n0 + nb + rr) * C3 + cc;
            qs[rr][cc] = qp[off]; ks[rr][cc] = kp[off];
        }
        __syncthreads();
        #pragma unroll
        for (int kk = 0; kk < 32; kk++) {
            float qr[3], kr[3];
            #pragma unroll
            for (int i = 0; i < 3; i++) qr[i] = qs[kk][ty * 3 + i];
            #pragma unroll
            for (int j = 0; j < 3; j++) kr[j] = ks[kk][tx * 3 + j];
            #pragma unroll
            for (int i = 0; i < 3; i++)
                #pragma unroll
                for (int j = 0; j < 3; j++) acc[i][j] += qr[i] * kr[j];
        }
        __syncthreads();
    }
    float* gp = g_gram + (size_t)bh * HD * HD;
    #pragma unroll
    for (int i = 0; i < 3; i++)
        #pragma unroll
        for (int j = 0; j < 3; j++)
            atomicAdd(&gp[(ty * 3 + i) * HD + tx * 3 + j], acc[i][j]);
}

__global__ void softmax_kernel(const float* __restrict__ temp) {
    int gi = blockIdx.x;
    int i = gi % HD; int bh = gi / HD;
    int b = bh >> 3, h = bh & 7;
    int tid = threadIdx.x;      // 64
    float qi = rsqrtf(fmaxf(g_sumsq[b * 2 * Cc + h * HD + i], 1e-24f));
    float v = -3.4e38f;
    if (tid < HD) {
        float kj = rsqrtf(fmaxf(g_sumsq[b * 2 * Cc + Cc + h * HD + tid], 1e-24f));
        v = g_gram[(size_t)bh * HD * HD + i * HD + tid] * qi * kj * temp[h];
    }
    __shared__ float red[64];
    red[tid] = v; __syncthreads();
    for (int st = 32; st > 0; st >>= 1) {
        if (tid < st) red[tid] = fmaxf(red[tid], red[tid + st]);
        __syncthreads();
    }
    float m = red[0]; __syncthreads();
    float e = (tid < HD) ? expf(v - m) : 0.f;
    red[tid] = e; __syncthreads();
    for (int st = 32; st > 0; st >>= 1) {
        if (tid < st) red[tid] += red[tid + st];
        __syncthreads();
    }
    if (tid < HD) g_attn[(size_t)bh * HD * HD + i * HD + tid] = e / red[0];
}

__global__ __launch_bounds__(128) void attnv_kernel() {
    int bh = blockIdx.y; int b = bh >> 3, h = bh & 7;
    int n = blockIdx.x * 128 + threadIdx.x;
    __shared__ float sa[HD * HD];
    for (int e = threadIdx.x; e < HD * HD; e += 128)
        sa[e] = g_attn[(size_t)bh * HD * HD + e];
    __syncthreads();
    const float* vp = g_qkvT + (size_t)(b * NN + n) * C3 + 2 * Cc + h * HD;
    float vr[HD];
    #pragma unroll
    for (int j = 0; j < HD; j++) vr[j] = vp[j];
    float* op = g_at + (size_t)(b * NN + n) * Cc + h * HD;
    for (int i = 0; i < HD; i++) {
        float s = 0.f;
        #pragma unroll
        for (int j = 0; j < HD; j++) s += sa[i * HD + j] * vr[j];
        op[i] = s;
    }
}

// float4-vectorized depthwise conv (NHWC, C % 4 == 0)
__global__ void dwconv4(const float* __restrict__ in, const float* __restrict__ w,
                        const float* __restrict__ bias, float* __restrict__ out,
                        int C, int ks, int pad, int dil)
{
    int idx = blockIdx.x * 256 + threadIdx.x;
    int C4 = C >> 2;
    int c4 = idx % C4; int rest = idx / C4;
    int xx = rest & 63, yy = (rest >> 6) & 63, b = rest >> 12;
    int c = c4 << 2;
    const float* ip = in + (size_t)(b * NN) * C + c;
    float4 bv = *(const float4*)(bias + c);
    float ax = bv.x, ay = bv.y, az = bv.z, aw = bv.w;
    const float* wp = w + c * ks * ks;
    const int K2 = ks * ks;
    for (int ky = 0; ky < ks; ky++) {
        int y = yy - pad + ky * dil;
        if ((unsigned)y >= 64u) continue;
        for (int kx = 0; kx < ks; kx++) {
            int x = xx - pad + kx * dil;
            if ((unsigned)x >= 64u) continue;
            float4 v = *(const float4*)(ip + (size_t)(y * 64 + x) * C);
            int t = ky * ks + kx;
            ax += v.x * wp[t];
            ay += v.y * wp[t + K2];
            az += v.z * wp[t + 2 * K2];
            aw += v.w * wp[t + 3 * K2];
        }
    }
    *(float4*)(out + (size_t)(b * NN + yy * 64 + xx) * C + c) =
        make_float4(ax, ay, az, aw);
}

// fused sp_dw (3x3 depthwise over C2c) + gelu gate -> gated (B,N,96)
__global__ void spdw_gelu(const float* __restrict__ sp, const float* __restrict__ w,
                          const float* __restrict__ bias, float* __restrict__ out)
{
    int idx = blockIdx.x * 256 + threadIdx.x;   // over B*NN*24
    int c4 = idx % 24; int rest = idx / 24;
    int xx = rest & 63, yy = (rest >> 6) & 63, b = rest >> 12;
    int c = c4 << 2;                             // [0,96)
    const float* ip = sp + (size_t)(b * NN) * C2c;
    float4 bv1 = *(const float4*)(bias + c);
    float4 bv2 = *(const float4*)(bias + c + C4c);
    float a1[4] = {bv1.x, bv1.y, bv1.z, bv1.w};
    float a2[4] = {bv2.x, bv2.y, bv2.z, bv2.w};
    const float* w1 = w + c * 9;
    const float* w2 = w + (c + C4c) * 9;
    #pragma unroll
    for (int ky = 0; ky < 3; ky++) {
        int y = yy - 1 + ky;
        if ((unsigned)y >= 64u) continue;
        #pragma unroll
        for (int kx = 0; kx < 3; kx++) {
            int x = xx - 1 + kx;
            if ((unsigned)x >= 64u) continue;
            const float* pv = ip + (size_t)(y * 64 + x) * C2c + c;
            float4 v1 = *(const float4*)pv;
            float4 v2 = *(const float4*)(pv + C4c);
            int t = ky * 3 + kx;
            a1[0] += v1.x * w1[t];      a1[1] += v1.y * w1[t + 9];
            a1[2] += v1.z * w1[t + 18]; a1[3] += v1.w * w1[t + 27];
            a2[0] += v2.x * w2[t];      a2[1] += v2.y * w2[t + 9];
            a2[2] += v2.z * w2[t + 18]; a2[3] += v2.w * w2[t + 27];
        }
    }
    float4 o;
    float* op = &o.x;
    #pragma unroll
    for (int q = 0; q < 4; q++) {
        float g = 0.5f * a1[q] * (1.f + erff(a1[q] * 0.70710678118654752f));
        op[q] = g * a2[q];
    }
    *(float4*)(out + (size_t)(b * NN + yy * 64 + xx) * C4c + c) = o;
}

__global__ void tmean_kernel() {
    int b = blockIdx.y, n0 = blockIdx.x * 512, c = threadIdx.x;
    const float* p = g_tt + (size_t)b * NN * C6c + c;
    float s = 0.f;
    for (int n = n0; n < n0 + 512; n++) s += p[(size_t)n * C6c];
    atomicAdd(&g_tmean[b * C6c + c], s);
}

__global__ void ci1_kernel(const float* __restrict__ w, const float* __restrict__ bias) {
    int b = blockIdx.x, co = threadIdx.x;
    __shared__ float tm[C6c];
    tm[co] = g_tmean[b * C6c + co] * (1.f / NN);
    __syncthreads();
    float a = bias[co];
    #pragma unroll
    for (int ci = 0; ci < C6c; ci++) a += w[co * C6c + ci] * tm[ci];
    g_ci1v[b * C6c + co] = a;
}

__global__ void cm_kernel() {
    int b = blockIdx.y, n0 = blockIdx.x * 512, c = threadIdx.x;   // 384 threads
    const float* p = g_chmap + (size_t)b * NN * Cc + c;
    float s = 0.f;
    for (int n = n0; n < n0 + 512; n++) s += p[(size_t)n * Cc];
    atomicAdd(&g_cm[b * Cc + c], s);
}

__global__ void combine_kernel() {
    int idx = blockIdx.x * 256 + threadIdx.x;
    int c = idx % Cc;
    int b = idx / (NN * Cc);
    float s1 = 1.f / (1.f + expf(-g_spmap[idx]));
    float s2 = 1.f / (1.f + expf(-g_cm[b * Cc + c] * (1.f / NN)));
    g_y[idx] = (g_at[idx] + g_chmap[idx]) * s1 + g_convx[idx] * s2;
}

// ================================================================= launch ===
extern "C" void kernel_launch(void* const* d_in, const int* in_sizes, int n_in,
                              void* d_out, int out_size)
{
    const float* x           = (const float*)d_in[0];
    const float* temperature = (const float*)d_in[1];
    const float* qkv_w       = (const float*)d_in[2];
    const float* proj_w      = (const float*)d_in[3];
    const float* proj_b      = (const float*)d_in[4];
    const float* dw1_w       = (const float*)d_in[5];
    const float* dw1_b       = (const float*)d_in[6];
    const float* dw2_w       = (const float*)d_in[7];
    const float* dw2_b       = (const float*)d_in[8];
    const float* cp_in_w     = (const float*)d_in[9];
    const float* cp_in_b     = (const float*)d_in[10];
    const float* ci1_w       = (const float*)d_in[11];
    const float* ci1_b       = (const float*)d_in[12];
    const float* ci2a_w      = (const float*)d_in[13];
    const float* ci2a_b      = (const float*)d_in[14];
    const float* ci2b_w      = (const float*)d_in[15];
    const float* ci2b_b      = (const float*)d_in[16];
    const float* ci2c_w      = (const float*)d_in[17];
    const float* ci2c_b      = (const float*)d_in[18];
    const float* cp_out_w    = (const float*)d_in[19];
    const float* cp_out_b    = (const float*)d_in[20];
    const float* sp_in_w     = (const float*)d_in[21];
    const float* sp_in_b     = (const float*)d_in[22];
    const float* sp_dw_w     = (const float*)d_in[23];
    const float* sp_dw_b     = (const float*)d_in[24];
    const float* sp_out_w    = (const float*)d_in[25];
    const float* sp_out_b    = (const float*)d_in[26];
    float* out = (float*)d_out;

    float *xT, *qkvT, *at, *t1, *convx, *chmap, *spmap, *y, *tt, *u1, *u2, *u3,
          *sp, *gated, *ci1v;
    cudaGetSymbolAddress((void**)&xT,    g_xT);
    cudaGetSymbolAddress((void**)&qkvT,  g_qkvT);
    cudaGetSymbolAddress((void**)&at,    g_at);
    cudaGetSymbolAddress((void**)&t1,    g_t1);
    cudaGetSymbolAddress((void**)&convx, g_convx);
    cudaGetSymbolAddress((void**)&chmap, g_chmap);
    cudaGetSymbolAddress((void**)&spmap, g_spmap);
    cudaGetSymbolAddress((void**)&y,     g_y);
    cudaGetSymbolAddress((void**)&tt,    g_tt);
    cudaGetSymbolAddress((void**)&u1,    g_u1);
    cudaGetSymbolAddress((void**)&u2,    g_u2);
    cudaGetSymbolAddress((void**)&u3,    g_u3);
    cudaGetSymbolAddress((void**)&sp,    g_sp);
    cudaGetSymbolAddress((void**)&gated, g_gated);
    cudaGetSymbolAddress((void**)&ci1v,  g_ci1v);

    const long long bCN  = CN;
    const long long b3CN = (long long)NN * C3;
    const long long b64  = (long long)NN * C6c;
    const long long b192 = (long long)NN * C2c;
    const long long b96  = (long long)NN * C4c;

    // dynamic smem sizes: (128 + n_tile) * 36 floats * 2 buffers
    const int SM4 = (128 + 128) * RSW * 4 * 2;   // 73728
    const int SM3 = (128 + 96)  * RSW * 4 * 2;   // 64512
    const int SM2 = (128 + 64)  * RSW * 4 * 2;   // 55296
    cudaFuncSetAttribute(mma_gemm<4>, cudaFuncAttributeMaxDynamicSharedMemorySize, SM4);
    cudaFuncSetAttribute(mma_gemm<3>, cudaFuncAttributeMaxDynamicSharedMemorySize, SM3);
    cudaFuncSetAttribute(mma_gemm<2>, cudaFuncAttributeMaxDynamicSharedMemorySize, SM2);

    zero_kernel<<<576, 256>>>();
    transpose_kernel<<<dim3(128, 12, Bb), dim3(32, 8)>>>(x);

    // qkv: (B,N,1152) = xT @ qkv_w^T
    mma_gemm<4><<<dim3(9, 32, Bb), 256, SM4>>>(xT, Cc, bCN, qkv_w, Cc, 0,
                                               nullptr, 0, nullptr, nullptr,
                                               qkvT, C3, b3CN, Cc);
    sumsq_kernel<<<dim3(8, 3, Bb), 256>>>();
    gram_kernel<<<dim3(8, Bb * HEADS), 256>>>();
    softmax_kernel<<<Bb * HEADS * HD, 64>>>(temperature);
    attnv_kernel<<<dim3(NN / 128, Bb * HEADS), 128>>>();

    // dw1 on v: (B,N,384)
    mma_gemm<4><<<dim3(3, 32, Bb), 256, SM4>>>(qkvT + 2 * Cc, C3, b3CN, dw1_w, Cc, 0,
                                               dw1_b, 0, nullptr, nullptr,
                                               t1, Cc, bCN, Cc);
    dwconv4<<<(Bb * NN * Cc / 4) / 256, 256>>>(t1, dw2_w, dw2_b, convx, Cc, 3, 1, 1);

    // cp_in: (B,N,64)
    mma_gemm<2><<<dim3(1, 32, Bb), 256, SM2>>>(at, Cc, bCN, cp_in_w, Cc, 0,
                                               cp_in_b, 0, nullptr, nullptr,
                                               tt, C6c, b64, Cc);
    tmean_kernel<<<dim3(8, Bb), 64>>>();
    ci1_kernel<<<Bb, C6c>>>(ci1_w, ci1_b);
    dwconv4<<<(Bb * NN * C6c / 4) / 256, 256>>>(tt, ci2a_w, ci2a_b, u1, C6c, 3, 1, 1);
    dwconv4<<<(Bb * NN * C6c / 4) / 256, 256>>>(u1, ci2b_w, ci2b_b, u2, C6c, 7, 9, 3);
    // ci2c + fused mul3: u3 = tt * ci1v * (ci2c(u2)+bias)
    mma_gemm<2><<<dim3(1, 32, Bb), 256, SM2>>>(u2, C6c, b64, ci2c_w, C6c, 0,
                                               ci2c_b, 0, tt, ci1v,
                                               u3, C6c, b64, C6c);
    mma_gemm<4><<<dim3(3, 32, Bb), 256, SM4>>>(u3, C6c, b64, cp_out_w, C6c, 0,
                                               cp_out_b, 0, nullptr, nullptr,
                                               chmap, Cc, bCN, C6c);
    cm_kernel<<<dim3(8, Bb), Cc>>>();

    // spatial projection branch
    mma_gemm<3><<<dim3(2, 32, Bb), 256, SM3>>>(convx, Cc, bCN, sp_in_w, Cc, 0,
                                               sp_in_b, 0, nullptr, nullptr,
                                               sp, C2c, b192, Cc);
    spdw_gelu<<<(Bb * NN * 24) / 256, 256>>>(sp, sp_dw_w, sp_dw_b, gated);
    mma_gemm<4><<<dim3(3, 32, Bb), 256, SM4>>>(gated, C4c, b96, sp_out_w, C4c, 0,
                                               sp_out_b, 0, nullptr, nullptr,
                                               spmap, Cc, bCN, C4c);

    combine_kernel<<<(Bb * NN * Cc) / 256, 256>>>();

    // final projection, output directly in (B,C,N)
    mma_gemm<4><<<dim3(32, 3, Bb), 256, SM4>>>(proj_w, Cc, 0, y, Cc, bCN,
                                               proj_b, 1, nullptr, nullptr,
                                               out, NN, bCN, Cc);
}

// round 6
// speedup vs baseline: 2.8590x; 1.0181x over previous
#include <cuda_runtime.h>
#include <cuda_fp16.h>
#include <cstdint>
#include <math.h>

#define Bb     8
#define Cc     384
#define NN     4096
#define HEADS  8
#define HD     48
#define CN     (Cc*NN)
#define C3     1152
#define C6c    64
#define C2c    192
#define C4c    96

// ---------------- scratch ----------------------------------------------------
__device__ float g_xT  [Bb*NN*Cc];         // (B,N,C)
__device__ float g_qkvT[(size_t)Bb*NN*C3]; // (B,N,3C)
__device__ float g_at  [Bb*NN*Cc];
__device__ float g_t1  [Bb*NN*Cc];
__device__ float g_convx[Bb*NN*Cc];
__device__ float g_chmap[Bb*NN*Cc];
__device__ float g_spmap[Bb*NN*Cc];
__device__ float g_y   [Bb*NN*Cc];
__device__ float g_tt  [Bb*NN*C6c];
__device__ float g_u1  [Bb*NN*C6c];
__device__ float g_u2  [Bb*NN*C6c];
__device__ float g_u3  [Bb*NN*C6c];
__device__ float g_sp  [Bb*NN*C2c];
__device__ float g_gated[Bb*NN*C4c];
__device__ float g_sumsq[Bb*2*Cc];
__device__ float g_gram [Bb*HEADS*HD*HD];
__device__ float g_attn [Bb*HEADS*HD*HD];
__device__ float g_tmean[Bb*C6c];
__device__ float g_ci1v [Bb*C6c];
__device__ float g_cm  [Bb*Cc];

__device__ __forceinline__ uint32_t smem_u32(const void* p) {
    uint32_t a;
    asm("{ .reg .u64 t; cvta.to.shared.u64 t, %1; cvt.u32.u64 %0, t; }" : "=r"(a) : "l"(p));
    return a;
}
__device__ __forceinline__ void cpa16(uint32_t dst, const float* src) {
    asm volatile("cp.async.cg.shared.global [%0], [%1], 16;"
                 :: "r"(dst), "l"(__cvta_generic_to_global(src)) : "memory");
}
#define CP_COMMIT() asm volatile("cp.async.commit_group;" ::: "memory")
#define CP_WAIT0()  asm volatile("cp.async.wait_group 0;" ::: "memory")

__device__ __forceinline__ uint32_t pack_h2(float2 v) {
    __half2 h = __floats2half2_rn(v.x, v.y);
    return *reinterpret_cast<uint32_t*>(&h);
}
__device__ __forceinline__ void mma_f16(float* d, uint32_t a0, uint32_t a1,
                                        uint32_t a2, uint32_t a3,
                                        uint32_t b0, uint32_t b1) {
    asm volatile(
        "mma.sync.aligned.m16n8k16.row.col.f32.f16.f16.f32 "
        "{%0,%1,%2,%3}, {%4,%5,%6,%7}, {%8,%9}, {%0,%1,%2,%3};"
        : "+f"(d[0]), "+f"(d[1]), "+f"(d[2]), "+f"(d[3])
        : "r"(a0), "r"(a1), "r"(a2), "r"(a3), "r"(b0), "r"(b1));
}

// ---------------- pipelined fp16 mma.sync GEMM --------------------------------
// D[i][j] = sum_k Arows[i][k] * Brows[j][k]  (both operands K-major fp32 in
// gmem/smem; converted to fp16 on consume, fp32 accumulate).
// CTA: 128 A-rows x (NI*32) B-rows, BK=32, double-buffered smem via cp.async.
#define RSW 36
template<int NI>
__global__ __launch_bounds__(256)
void mma_gemm(const float* __restrict__ A, int lda, long long abatch,
              const float* __restrict__ B, int ldb, long long bbatch,
              const float* __restrict__ bias, int biasRowMode,
              const float* __restrict__ emul, const float* __restrict__ escale,
              float* __restrict__ ssq,
              float* __restrict__ Out, int ldo, long long obatch, int K)
{
    constexpr int n_tile = NI * 32;
    extern __shared__ float smem[];
    float* As0 = smem;
    float* Bs0 = smem + 128 * RSW;
    float* As1 = smem + (128 + n_tile) * RSW;
    float* Bs1 = As1 + 128 * RSW;

    const int tid  = threadIdx.x;
    const int wid  = tid >> 5, lane = tid & 31;
    const int g    = lane >> 2, tig = lane & 3;
    const int z    = blockIdx.z;
    const int arow0 = blockIdx.y * 128;
    const int brow0 = blockIdx.x * n_tile;
    const int wm = (wid & 1) * 64;
    const int wn = (wid >> 1) * (NI * 8);

    const float* Ab = A + (size_t)z * abatch + (size_t)arow0 * lda;
    const float* Bp = B + (size_t)z * bbatch + (size_t)brow0 * ldb;

    float c[4][NI][4];
    #pragma unroll
    for (int mi = 0; mi < 4; mi++)
        #pragma unroll
        for (int ni = 0; ni < NI; ni++)
            #pragma unroll
            for (int q = 0; q < 4; q++) c[mi][ni][q] = 0.f;

    auto loadTiles = [&](int kc, float* Ad, float* Bd) {
        #pragma unroll
        for (int i = 0; i < 4; i++) {
            int e = tid + i * 256;
            int row = e >> 3, seg = e & 7;
            cpa16(smem_u32(Ad + row * RSW + seg * 4),
                  Ab + (size_t)row * lda + kc * 32 + seg * 4);
        }
        #pragma unroll
        for (int i = 0; i < NI; i++) {
            int e = tid + i * 256;
            int row = e >> 3, seg = e & 7;
            cpa16(smem_u32(Bd + row * RSW + seg * 4),
                  Bp + (size_t)row * ldb + kc * 32 + seg * 4);
        }
        CP_COMMIT();
    };

    const int nch = K >> 5;
    loadTiles(0, As0, Bs0);

    for (int kc = 0; kc < nch; kc++) {
        CP_WAIT0();
        __syncthreads();
        if (kc + 1 < nch)
            loadTiles(kc + 1, (kc & 1) ? As0 : As1, (kc & 1) ? Bs0 : Bs1);
        const float* Ac = (kc & 1) ? As1 : As0;
        const float* Bc = (kc & 1) ? Bs1 : Bs0;

        #pragma unroll
        for (int ks = 0; ks < 2; ks++) {                  // k0 = ks*16
            uint32_t A0[4], A1[4], A2[4], A3[4];
            #pragma unroll
            for (int mi = 0; mi < 4; mi++) {
                const float* ap = Ac + (wm + mi * 16 + g) * RSW + ks * 16 + tig * 2;
                A0[mi] = pack_h2(*(const float2*)ap);
                A2[mi] = pack_h2(*(const float2*)(ap + 8));
                A1[mi] = pack_h2(*(const float2*)(ap + 8 * RSW));
                A3[mi] = pack_h2(*(const float2*)(ap + 8 * RSW + 8));
            }
            #pragma unroll
            for (int ni = 0; ni < NI; ni++) {
                const float* bp = Bc + (wn + ni * 8 + g) * RSW + ks * 16 + tig * 2;
                uint32_t B0 = pack_h2(*(const float2*)bp);
                uint32_t B1 = pack_h2(*(const float2*)(bp + 8));
                #pragma unroll
                for (int mi = 0; mi < 4; mi++)
                    mma_f16(c[mi][ni], A0[mi], A1[mi], A2[mi], A3[mi], B0, B1);
            }
        }
    }

    // optional fused column sum-of-squares (for qkv -> q,k L2 norms)
    if (ssq) {
        #pragma unroll
        for (int ni = 0; ni < NI; ni++) {
            int col = brow0 + wn + ni * 8 + tig * 2;
            if (col < 2 * Cc) {
                float s0 = 0.f, s1 = 0.f;
                #pragma unroll
                for (int mi = 0; mi < 4; mi++) {
                    s0 += c[mi][ni][0] * c[mi][ni][0] + c[mi][ni][2] * c[mi][ni][2];
                    s1 += c[mi][ni][1] * c[mi][ni][1] + c[mi][ni][3] * c[mi][ni][3];
                }
                s0 += __shfl_xor_sync(0xffffffffu, s0, 4);
                s1 += __shfl_xor_sync(0xffffffffu, s1, 4);
                s0 += __shfl_xor_sync(0xffffffffu, s0, 8);
                s1 += __shfl_xor_sync(0xffffffffu, s1, 8);
                s0 += __shfl_xor_sync(0xffffffffu, s0, 16);
                s1 += __shfl_xor_sync(0xffffffffu, s1, 16);
                if (g == 0) {
                    atomicAdd(&ssq[z * 2 * Cc + col], s0);
                    atomicAdd(&ssq[z * 2 * Cc + col + 1], s1);
                }
            }
        }
    }

    // epilogue
    #pragma unroll
    for (int mi = 0; mi < 4; mi++) {
        const int row = arow0 + wm + mi * 16 + g;
        float bv0 = 0.f, bv1 = 0.f;
        if (bias && biasRowMode) { bv0 = bias[row]; bv1 = bias[row + 8]; }
        #pragma unroll
        for (int ni = 0; ni < NI; ni++) {
            const int col = brow0 + wn + ni * 8 + tig * 2;
            float bc0 = 0.f, bc1 = 0.f;
            if (bias && !biasRowMode) { bc0 = bias[col]; bc1 = bias[col + 1]; }
            size_t o0 = (size_t)z * obatch + (size_t)row * ldo + col;
            size_t o1 = o0 + 8 * (size_t)ldo;
            float v00 = c[mi][ni][0] + bv0 + bc0, v01 = c[mi][ni][1] + bv0 + bc1;
            float v10 = c[mi][ni][2] + bv1 + bc0, v11 = c[mi][ni][3] + bv1 + bc1;
            if (emul) {   // fused: out = t * ci1 * (gemm+bias)
                float2 m0 = *(const float2*)(emul + o0);
                float2 m1 = *(const float2*)(emul + o1);
                float s0 = escale[z * C6c + col], s1 = escale[z * C6c + col + 1];
                v00 *= m0.x * s0; v01 *= m0.y * s1;
                v10 *= m1.x * s0; v11 *= m1.y * s1;
            }
            *(float2*)(Out + o0) = make_float2(v00, v01);
            *(float2*)(Out + o1) = make_float2(v10, v11);
        }
    }
}

// ---------------- small kernels ------------------------------------------------
__global__ void zero_kernel() {
    int i = blockIdx.x * 256 + threadIdx.x;
    if (i < Bb*2*Cc)          g_sumsq[i] = 0.f;
    if (i < Bb*HEADS*HD*HD)   g_gram[i]  = 0.f;
    if (i < Bb*C6c)           g_tmean[i] = 0.f;
    if (i < Bb*Cc)            g_cm[i]    = 0.f;
}

__global__ void transpose_kernel(const float* __restrict__ in) {
    __shared__ float t[32][33];
    int b = blockIdx.z, c0 = blockIdx.y * 32, n0 = blockIdx.x * 32;
    int tx = threadIdx.x, ty = threadIdx.y;
    for (int i = ty; i < 32; i += 8)
        t[i][tx] = in[(size_t)b * CN + (size_t)(c0 + i) * NN + n0 + tx];
    __syncthreads();
    for (int i = ty; i < 32; i += 8)
        g_xT[(size_t)b * CN + (size_t)(n0 + i) * Cc + c0 + tx] = t[tx][i];
}

__global__ __launch_bounds__(256) void gram_kernel() {
    int bh = blockIdx.y; int b = bh >> 3, h = bh & 7;
    int n0 = blockIdx.x * 512;
    const float* qp = g_qkvT + (size_t)b * NN * C3 + h * HD;
    const float* kp = qp + Cc;
    __shared__ float qs[32][HD], ks[32][HD];
    int tid = threadIdx.x, tx = tid & 15, ty = tid >> 4;
    float acc[3][3] = {};
    for (int nb = 0; nb < 512; nb += 32) {
        for (int e = tid; e < 32 * HD; e += 256) {
            int rr = e / HD, cc = e % HD;
            size_t off = (size_t)(n0 + nb + rr) * C3 + cc;
            qs[rr][cc] = qp[off]; ks[rr][cc] = kp[off];
        }
        __syncthreads();
        #pragma unroll
        for (int kk = 0; kk < 32; kk++) {
            float qr[3], kr[3];
            #pragma unroll
            for (int i = 0; i < 3; i++) qr[i] = qs[kk][ty * 3 + i];
            #pragma unroll
            for (int j = 0; j < 3; j++) kr[j] = ks[kk][tx * 3 + j];
            #pragma unroll
            for (int i = 0; i < 3; i++)
                #pragma unroll
                for (int j = 0; j < 3; j++) acc[i][j] += qr[i] * kr[j];
        }
        __syncthreads();
    }
    float* gp = g_gram + (size_t)bh * HD * HD;
    #pragma unroll
    for (int i = 0; i < 3; i++)
        #pragma unroll
        for (int j = 0; j < 3; j++)
            atomicAdd(&gp[(ty * 3 + i) * HD + tx * 3 + j], acc[i][j]);
}

__global__ void softmax_kernel(const float* __restrict__ temp) {
    int gi = blockIdx.x;
    int i = gi % HD; int bh = gi / HD;
    int b = bh >> 3, h = bh & 7;
    int tid = threadIdx.x;      // 64
    float qi = rsqrtf(fmaxf(g_sumsq[b * 2 * Cc + h * HD + i], 1e-24f));
    float v = -3.4e38f;
    if (tid < HD) {
        float kj = rsqrtf(fmaxf(g_sumsq[b * 2 * Cc + Cc + h * HD + tid], 1e-24f));
        v = g_gram[(size_t)bh * HD * HD + i * HD + tid] * qi * kj * temp[h];
    }
    __shared__ float red[64];
    red[tid] = v; __syncthreads();
    for (int st = 32; st > 0; st >>= 1) {
        if (tid < st) red[tid] = fmaxf(red[tid], red[tid + st]);
        __syncthreads();
    }
    float m = red[0]; __syncthreads();
    float e = (tid < HD) ? expf(v - m) : 0.f;
    red[tid] = e; __syncthreads();
    for (int st = 32; st > 0; st >>= 1) {
        if (tid < st) red[tid] += red[tid + st];
        __syncthreads();
    }
    if (tid < HD) g_attn[(size_t)bh * HD * HD + i * HD + tid] = e / red[0];
}

__global__ __launch_bounds__(128) void attnv_kernel() {
    int bh = blockIdx.y; int b = bh >> 3, h = bh & 7;
    int n = blockIdx.x * 128 + threadIdx.x;
    __shared__ float sa[HD * HD];
    for (int e = threadIdx.x; e < HD * HD; e += 128)
        sa[e] = g_attn[(size_t)bh * HD * HD + e];
    __syncthreads();
    const float* vp = g_qkvT + (size_t)(b * NN + n) * C3 + 2 * Cc + h * HD;
    float vr[HD];
    #pragma unroll
    for (int j = 0; j < HD; j++) vr[j] = vp[j];
    float* op = g_at + (size_t)(b * NN + n) * Cc + h * HD;
    for (int i = 0; i < HD; i++) {
        float s = 0.f;
        #pragma unroll
        for (int j = 0; j < HD; j++) s += sa[i * HD + j] * vr[j];
        op[i] = s;
    }
}

// float4-vectorized depthwise conv (NHWC, C % 4 == 0)
__global__ void dwconv4(const float* __restrict__ in, const float* __restrict__ w,
                        const float* __restrict__ bias, float* __restrict__ out,
                        int C, int ks, int pad, int dil)
{
    int idx = blockIdx.x * 256 + threadIdx.x;
    int C4 = C >> 2;
    int c4 = idx % C4; int rest = idx / C4;
    int xx = rest & 63, yy = (rest >> 6) & 63, b = rest >> 12;
    int c = c4 << 2;
    const float* ip = in + (size_t)(b * NN) * C + c;
    float4 bv = *(const float4*)(bias + c);
    float ax = bv.x, ay = bv.y, az = bv.z, aw = bv.w;
    const float* wp = w + c * ks * ks;
    const int K2 = ks * ks;
    for (int ky = 0; ky < ks; ky++) {
        int y = yy - pad + ky * dil;
        if ((unsigned)y >= 64u) continue;
        for (int kx = 0; kx < ks; kx++) {
            int x = xx - pad + kx * dil;
            if ((unsigned)x >= 64u) continue;
            float4 v = *(const float4*)(ip + (size_t)(y * 64 + x) * C);
            int t = ky * ks + kx;
            ax += v.x * wp[t];
            ay += v.y * wp[t + K2];
            az += v.z * wp[t + 2 * K2];
            aw += v.w * wp[t + 3 * K2];
        }
    }
    *(float4*)(out + (size_t)(b * NN + yy * 64 + xx) * C + c) =
        make_float4(ax, ay, az, aw);
}

// fused sp_dw (3x3 depthwise over C2c) + gelu gate -> gated (B,N,96)
__global__ void spdw_gelu(const float* __restrict__ sp, const float* __restrict__ w,
                          const float* __restrict__ bias, float* __restrict__ out)
{
    int idx = blockIdx.x * 256 + threadIdx.x;   // over B*NN*24
    int c4 = idx % 24; int rest = idx / 24;
    int xx = rest & 63, yy = (rest >> 6) & 63, b = rest >> 12;
    int c = c4 << 2;                             // [0,96)
    const float* ip = sp + (size_t)(b * NN) * C2c;
    float4 bv1 = *(const float4*)(bias + c);
    float4 bv2 = *(const float4*)(bias + c + C4c);
    float a1[4] = {bv1.x, bv1.y, bv1.z, bv1.w};
    float a2[4] = {bv2.x, bv2.y, bv2.z, bv2.w};
    const float* w1 = w + c * 9;
    const float* w2 = w + (c + C4c) * 9;
    #pragma unroll
    for (int ky = 0; ky < 3; ky++) {
        int y = yy - 1 + ky;
        if ((unsigned)y >= 64u) continue;
        #pragma unroll
        for (int kx = 0; kx < 3; kx++) {
            int x = xx - 1 + kx;
            if ((unsigned)x >= 64u) continue;
            const float* pv = ip + (size_t)(y * 64 + x) * C2c + c;
            float4 v1 = *(const float4*)pv;
            float4 v2 = *(const float4*)(pv + C4c);
            int t = ky * 3 + kx;
            a1[0] += v1.x * w1[t];      a1[1] += v1.y * w1[t + 9];
            a1[2] += v1.z * w1[t + 18]; a1[3] += v1.w * w1[t + 27];
            a2[0] += v2.x * w2[t];      a2[1] += v2.y * w2[t + 9];
            a2[2] += v2.z * w2[t + 18]; a2[3] += v2.w * w2[t + 27];
        }
    }
    float4 o;
    float* op = &o.x;
    #pragma unroll
    for (int q = 0; q < 4; q++) {
        float g = 0.5f * a1[q] * (1.f + erff(a1[q] * 0.70710678118654752f));
        op[q] = g * a2[q];
    }
    *(float4*)(out + (size_t)(b * NN + yy * 64 + xx) * C4c + c) = o;
}

__global__ void tmean_kernel() {
    int b = blockIdx.y, n0 = blockIdx.x * 512, c = threadIdx.x;
    const float* p = g_tt + (size_t)b * NN * C6c + c;
    float s = 0.f;
    for (int n = n0; n < n0 + 512; n++) s += p[(size_t)n * C6c];
    atomicAdd(&g_tmean[b * C6c + c], s);
}

__global__ void ci1_kernel(const float* __restrict__ w, const float* __restrict__ bias) {
    int b = blockIdx.x, co = threadIdx.x;
    __shared__ float tm[C6c];
    tm[co] = g_tmean[b * C6c + co] * (1.f / NN);
    __syncthreads();
    float a = bias[co];
    #pragma unroll
    for (int ci = 0; ci < C6c; ci++) a += w[co * C6c + ci] * tm[ci];
    g_ci1v[b * C6c + co] = a;
}

__global__ void cm_kernel() {
    int b = blockIdx.y, n0 = blockIdx.x * 512, c = threadIdx.x;   // 384 threads
    const float* p = g_chmap + (size_t)b * NN * Cc + c;
    float s = 0.f;
    for (int n = n0; n < n0 + 512; n++) s += p[(size_t)n * Cc];
    atomicAdd(&g_cm[b * Cc + c], s);
}

__global__ void combine_kernel() {
    int idx = blockIdx.x * 256 + threadIdx.x;
    int c = idx % Cc;
    int b = idx / (NN * Cc);
    float s1 = 1.f / (1.f + expf(-g_spmap[idx]));
    float s2 = 1.f / (1.f + expf(-g_cm[b * Cc + c] * (1.f / NN)));
    g_y[idx] = (g_at[idx] + g_chmap[idx]) * s1 + g_convx[idx] * s2;
}

// ================================================================= launch ===
extern "C" void kernel_launch(void* const* d_in, const int* in_sizes, int n_in,
                              void* d_out, int out_size)
{
    const float* x           = (const float*)d_in[0];
    const float* temperature = (const float*)d_in[1];
    const float* qkv_w       = (const float*)d_in[2];
    const float* proj_w      = (const float*)d_in[3];
    const float* proj_b      = (const float*)d_in[4];
    const float* dw1_w       = (const float*)d_in[5];
    const float* dw1_b       = (const float*)d_in[6];
    const float* dw2_w       = (const float*)d_in[7];
    const float* dw2_b       = (const float*)d_in[8];
    const float* cp_in_w     = (const float*)d_in[9];
    const float* cp_in_b     = (const float*)d_in[10];
    const float* ci1_w       = (const float*)d_in[11];
    const float* ci1_b       = (const float*)d_in[12];
    const float* ci2a_w      = (const float*)d_in[13];
    const float* ci2a_b      = (const float*)d_in[14];
    const float* ci2b_w      = (const float*)d_in[15];
    const float* ci2b_b      = (const float*)d_in[16];
    const float* ci2c_w      = (const float*)d_in[17];
    const float* ci2c_b      = (const float*)d_in[18];
    const float* cp_out_w    = (const float*)d_in[19];
    const float* cp_out_b    = (const float*)d_in[20];
    const float* sp_in_w     = (const float*)d_in[21];
    const float* sp_in_b     = (const float*)d_in[22];
    const float* sp_dw_w     = (const float*)d_in[23];
    const float* sp_dw_b     = (const float*)d_in[24];
    const float* sp_out_w    = (const float*)d_in[25];
    const float* sp_out_b    = (const float*)d_in[26];
    float* out = (float*)d_out;

    float *xT, *qkvT, *at, *t1, *convx, *chmap, *spmap, *y, *tt, *u1, *u2, *u3,
          *sp, *gated, *ci1v, *ssq;
    cudaGetSymbolAddress((void**)&xT,    g_xT);
    cudaGetSymbolAddress((void**)&qkvT,  g_qkvT);
    cudaGetSymbolAddress((void**)&at,    g_at);
    cudaGetSymbolAddress((void**)&t1,    g_t1);
    cudaGetSymbolAddress((void**)&convx, g_convx);
    cudaGetSymbolAddress((void**)&chmap, g_chmap);
    cudaGetSymbolAddress((void**)&spmap, g_spmap);
    cudaGetSymbolAddress((void**)&y,     g_y);
    cudaGetSymbolAddress((void**)&tt,    g_tt);
    cudaGetSymbolAddress((void**)&u1,    g_u1);
    cudaGetSymbolAddress((void**)&u2,    g_u2);
    cudaGetSymbolAddress((void**)&u3,    g_u3);
    cudaGetSymbolAddress((void**)&sp,    g_sp);
    cudaGetSymbolAddress((void**)&gated, g_gated);
    cudaGetSymbolAddress((void**)&ci1v,  g_ci1v);
    cudaGetSymbolAddress((void**)&ssq,   g_sumsq);

    const long long bCN  = CN;
    const long long b3CN = (long long)NN * C3;
    const long long b64  = (long long)NN * C6c;
    const long long b192 = (long long)NN * C2c;
    const long long b96  = (long long)NN * C4c;

    const int SM4 = (128 + 128) * RSW * 4 * 2;   // 73728
    const int SM3 = (128 + 96)  * RSW * 4 * 2;   // 64512
    const int SM2 = (128 + 64)  * RSW * 4 * 2;   // 55296
    cudaFuncSetAttribute(mma_gemm<4>, cudaFuncAttributeMaxDynamicSharedMemorySize, SM4);
    cudaFuncSetAttribute(mma_gemm<3>, cudaFuncAttributeMaxDynamicSharedMemorySize, SM3);
    cudaFuncSetAttribute(mma_gemm<2>, cudaFuncAttributeMaxDynamicSharedMemorySize, SM2);

    zero_kernel<<<576, 256>>>();
    transpose_kernel<<<dim3(128, 12, Bb), dim3(32, 8)>>>(x);

    // qkv: (B,N,1152) = xT @ qkv_w^T   (+ fused sumsq of q,k columns)
    mma_gemm<4><<<dim3(9, 32, Bb), 256, SM4>>>(xT, Cc, bCN, qkv_w, Cc, 0,
                                               nullptr, 0, nullptr, nullptr, ssq,
                                               qkvT, C3, b3CN, Cc);
    gram_kernel<<<dim3(8, Bb * HEADS), 256>>>();
    softmax_kernel<<<Bb * HEADS * HD, 64>>>(temperature);
    attnv_kernel<<<dim3(NN / 128, Bb * HEADS), 128>>>();

    // dw1 on v: (B,N,384)
    mma_gemm<4><<<dim3(3, 32, Bb), 256, SM4>>>(qkvT + 2 * Cc, C3, b3CN, dw1_w, Cc, 0,
                                               dw1_b, 0, nullptr, nullptr, nullptr,
                                               t1, Cc, bCN, Cc);
    dwconv4<<<(Bb * NN * Cc / 4) / 256, 256>>>(t1, dw2_w, dw2_b, convx, Cc, 3, 1, 1);

    // cp_in: (B,N,64)
    mma_gemm<2><<<dim3(1, 32, Bb), 256, SM2>>>(at, Cc, bCN, cp_in_w, Cc, 0,
                                               cp_in_b, 0, nullptr, nullptr, nullptr,
                                               tt, C6c, b64, Cc);
    tmean_kernel<<<dim3(8, Bb), 64>>>();
    ci1_kernel<<<Bb, C6c>>>(ci1_w, ci1_b);
    dwconv4<<<(Bb * NN * C6c / 4) / 256, 256>>>(tt, ci2a_w, ci2a_b, u1, C6c, 3, 1, 1);
    dwconv4<<<(Bb * NN * C6c / 4) / 256, 256>>>(u1, ci2b_w, ci2b_b, u2, C6c, 7, 9, 3);
    // ci2c + fused mul3: u3 = tt * ci1v * (ci2c(u2)+bias)
    mma_gemm<2><<<dim3(1, 32, Bb), 256, SM2>>>(u2, C6c, b64, ci2c_w, C6c, 0,
                                               ci2c_b, 0, tt, ci1v, nullptr,
                                               u3, C6c, b64, C6c);
    mma_gemm<4><<<dim3(3, 32, Bb), 256, SM4>>>(u3, C6c, b64, cp_out_w, C6c, 0,
                                               cp_out_b, 0, nullptr, nullptr, nullptr,
                                               chmap, Cc, bCN, C6c);
    cm_kernel<<<dim3(8, Bb), Cc>>>();

    // spatial projection branch
    mma_gemm<3><<<dim3(2, 32, Bb), 256, SM3>>>(convx, Cc, bCN, sp_in_w, Cc, 0,
                                               sp_in_b, 0, nullptr, nullptr, nullptr,
                                               sp, C2c, b192, Cc);
    spdw_gelu<<<(Bb * NN * 24) / 256, 256>>>(sp, sp_dw_w, sp_dw_b, gated);
    mma_gemm<4><<<dim3(3, 32, Bb), 256, SM4>>>(gated, C4c, b96, sp_out_w, C4c, 0,
                                               sp_out_b, 0, nullptr, nullptr, nullptr,
                                               spmap, Cc, bCN, C4c);

    combine_kernel<<<(Bb * NN * Cc) / 256, 256>>>();

    // final projection, output directly in (B,C,N)
    mma_gemm<4><<<dim3(32, 3, Bb), 256, SM4>>>(proj_w, Cc, 0, y, Cc, bCN,
                                               proj_b, 1, nullptr, nullptr, nullptr,
                                               out, NN, bCN, Cc);
}

// round 7
// speedup vs baseline: 4.5308x; 1.5847x over previous
#include <cuda_runtime.h>
#include <cuda_fp16.h>
#include <cstdint>
#include <math.h>

#define Bb     8
#define Cc     384
#define NN     4096
#define HEADS  8
#define HD     48
#define CN     (Cc*NN)
#define C3     1152
#define C6c    64
#define C2c    192
#define C4c    96

// ---------------- scratch ----------------------------------------------------
// fp16 GEMM operands
__device__ __align__(16) __half g_xh   [Bb*NN*Cc];
__device__ __align__(16) __half g_qkvh [(size_t)Bb*NN*C3];
__device__ __align__(16) __half g_ath  [Bb*NN*Cc];
__device__ __align__(16) __half g_convxh[Bb*NN*Cc];
__device__ __align__(16) __half g_u2h  [Bb*NN*C6c];
__device__ __align__(16) __half g_u3h  [Bb*NN*C6c];
__device__ __align__(16) __half g_gatedh[Bb*NN*C4c];
__device__ __align__(16) __half g_yh   [Bb*NN*Cc];
__device__ __align__(16) __half g_wbuf [901120];   // all weights, fp16
// fp32 intermediates for elementwise consumers
__device__ float g_at   [Bb*NN*Cc];
__device__ float g_t1   [Bb*NN*Cc];
__device__ float g_convx[Bb*NN*Cc];
__device__ float g_chmap[Bb*NN*Cc];
__device__ float g_spmap[Bb*NN*Cc];
__device__ float g_tt   [Bb*NN*C6c];
__device__ float g_u1   [Bb*NN*C6c];
__device__ float g_sp   [Bb*NN*C2c];
__device__ float g_sumsq[Bb*2*Cc];
__device__ float g_gram [Bb*HEADS*HD*HD];
__device__ float g_attn [Bb*HEADS*HD*HD];
__device__ float g_tmean[Bb*C6c];
__device__ float g_ci1v [Bb*C6c];
__device__ float g_cm   [Bb*Cc];

// weight offsets inside g_wbuf
#define W_QKV   0
#define W_DW1   442368
#define W_CPIN  589824
#define W_CI2C  614400
#define W_CPOUT 618496
#define W_SPIN  643072
#define W_SPOUT 716800
#define W_PROJ  753664

__device__ __forceinline__ uint32_t smem_u32(const void* p) {
    uint32_t a;
    asm("{ .reg .u64 t; cvta.to.shared.u64 t, %1; cvt.u32.u64 %0, t; }" : "=r"(a) : "l"(p));
    return a;
}
__device__ __forceinline__ void cpa16h(__half* dst, const __half* src) {
    asm volatile("cp.async.cg.shared.global [%0], [%1], 16;"
                 :: "r"(smem_u32(dst)), "l"(__cvta_generic_to_global(src)) : "memory");
}
#define CP_COMMIT() asm volatile("cp.async.commit_group;" ::: "memory")
#define CP_WAIT0()  asm volatile("cp.async.wait_group 0;" ::: "memory")

__device__ __forceinline__ void ldsm4(uint32_t* r, uint32_t addr) {
    asm volatile("ldmatrix.sync.aligned.m8n8.x4.shared.b16 {%0,%1,%2,%3}, [%4];"
        : "=r"(r[0]), "=r"(r[1]), "=r"(r[2]), "=r"(r[3]) : "r"(addr));
}
__device__ __forceinline__ void ldsm4t(uint32_t* r, uint32_t addr) {
    asm volatile("ldmatrix.sync.aligned.m8n8.x4.trans.shared.b16 {%0,%1,%2,%3}, [%4];"
        : "=r"(r[0]), "=r"(r[1]), "=r"(r[2]), "=r"(r[3]) : "r"(addr));
}
__device__ __forceinline__ void ldsm2(uint32_t* r, uint32_t addr) {
    asm volatile("ldmatrix.sync.aligned.m8n8.x2.shared.b16 {%0,%1}, [%2];"
        : "=r"(r[0]), "=r"(r[1]) : "r"(addr));
}
__device__ __forceinline__ void mma_f16(float* d, uint32_t a0, uint32_t a1,
                                        uint32_t a2, uint32_t a3,
                                        uint32_t b0, uint32_t b1) {
    asm volatile(
        "mma.sync.aligned.m16n8k16.row.col.f32.f16.f16.f32 "
        "{%0,%1,%2,%3}, {%4,%5,%6,%7}, {%8,%9}, {%0,%1,%2,%3};"
        : "+f"(d[0]), "+f"(d[1]), "+f"(d[2]), "+f"(d[3])
        : "r"(a0), "r"(a1), "r"(a2), "r"(a3), "r"(b0), "r"(b1));
}

// ---------------- pipelined fp16 ldmatrix GEMM --------------------------------
// D[i][j] = sum_k A[i][k]*B[j][k] (both fp16, K-major). CTA 128 x NI*32, BK=32.
#define RSH 40     // halves per smem row (80B) -> conflict-free ldmatrix
template<int NI>
__global__ __launch_bounds__(256)
void mma_gemm(const __half* __restrict__ A, int lda, long long abatch,
              const __half* __restrict__ B, int ldb, long long bbatch,
              const float* __restrict__ bias, int biasRowMode,
              const float* __restrict__ emul, const float* __restrict__ escale,
              float* __restrict__ ssq,
              float* __restrict__ Outf, __half* __restrict__ Outh,
              int ldo, long long obatch, int K)
{
    constexpr int n_tile = NI * 32;
    extern __shared__ __half sh[];
    __half* As0 = sh;
    __half* Bs0 = sh + 128 * RSH;
    __half* As1 = sh + (128 + n_tile) * RSH;
    __half* Bs1 = As1 + 128 * RSH;

    const int tid  = threadIdx.x;
    const int wid  = tid >> 5, lane = tid & 31;
    const int g    = lane >> 2, tig = lane & 3;
    const int z    = blockIdx.z;
    const int arow0 = blockIdx.y * 128;
    const int brow0 = blockIdx.x * n_tile;
    const int wm = (wid & 1) * 64;
    const int wn = (wid >> 1) * (NI * 8);

    const __half* Ab = A + (size_t)z * abatch + (size_t)arow0 * lda;
    const __half* Bp = B + (size_t)z * bbatch + (size_t)brow0 * ldb;

    float c[4][NI][4];
    #pragma unroll
    for (int mi = 0; mi < 4; mi++)
        #pragma unroll
        for (int ni = 0; ni < NI; ni++)
            #pragma unroll
            for (int q = 0; q < 4; q++) c[mi][ni][q] = 0.f;

    auto loadTiles = [&](int kc, __half* Ad, __half* Bd) {
        #pragma unroll
        for (int i = 0; i < 2; i++) {
            int e = tid + i * 256;                 // 512 tasks
            int row = e >> 2, seg = e & 3;
            cpa16h(Ad + row * RSH + seg * 8,
                   Ab + (size_t)row * lda + kc * 32 + seg * 8);
        }
        for (int e = tid; e < n_tile * 4; e += 256) {
            int row = e >> 2, seg = e & 3;
            cpa16h(Bd + row * RSH + seg * 8,
                   Bp + (size_t)row * ldb + kc * 32 + seg * 8);
        }
        CP_COMMIT();
    };

    const int nch = K >> 5;
    loadTiles(0, As0, Bs0);

    for (int kc = 0; kc < nch; kc++) {
        CP_WAIT0();
        __syncthreads();
        if (kc + 1 < nch)
            loadTiles(kc + 1, (kc & 1) ? As0 : As1, (kc & 1) ? Bs0 : Bs1);
        const uint32_t smA = smem_u32((kc & 1) ? As1 : As0);
        const uint32_t smB = smem_u32((kc & 1) ? Bs1 : Bs0);

        #pragma unroll
        for (int ks = 0; ks < 2; ks++) {
            uint32_t a[4][4];
            #pragma unroll
            for (int mi = 0; mi < 4; mi++) {
                uint32_t addr = smA +
                    (((wm + mi * 16 + (lane & 15)) * RSH) + ks * 16 + (lane >> 4) * 8) * 2;
                ldsm4(a[mi], addr);
            }
            uint32_t b[NI][2];
            #pragma unroll
            for (int np = 0; np < NI / 2; np++) {
                uint32_t addr = smB +
                    (((wn + np * 16 + ((lane >> 4) << 3) + (lane & 7)) * RSH) +
                     ks * 16 + ((lane >> 3) & 1) * 8) * 2;
                uint32_t r[4]; ldsm4(r, addr);
                b[2*np][0] = r[0]; b[2*np][1] = r[1];
                b[2*np+1][0] = r[2]; b[2*np+1][1] = r[3];
            }
            if (NI & 1) {
                uint32_t addr = smB +
                    (((wn + (NI - 1) * 8 + (lane & 7)) * RSH) +
                     ks * 16 + ((lane >> 3) & 1) * 8) * 2;
                ldsm2(b[NI-1], addr);
            }
            #pragma unroll
            for (int ni = 0; ni < NI; ni++)
                #pragma unroll
                for (int mi = 0; mi < 4; mi++)
                    mma_f16(c[mi][ni], a[mi][0], a[mi][1], a[mi][2], a[mi][3],
                            b[ni][0], b[ni][1]);
        }
    }

    // fused column sum-of-squares (qkv: q,k L2 norms)
    if (ssq) {
        #pragma unroll
        for (int ni = 0; ni < NI; ni++) {
            int col = brow0 + wn + ni * 8 + tig * 2;
            if (col < 2 * Cc) {
                float s0 = 0.f, s1 = 0.f;
                #pragma unroll
                for (int mi = 0; mi < 4; mi++) {
                    s0 += c[mi][ni][0] * c[mi][ni][0] + c[mi][ni][2] * c[mi][ni][2];
                    s1 += c[mi][ni][1] * c[mi][ni][1] + c[mi][ni][3] * c[mi][ni][3];
                }
                s0 += __shfl_xor_sync(0xffffffffu, s0, 4);
                s1 += __shfl_xor_sync(0xffffffffu, s1, 4);
                s0 += __shfl_xor_sync(0xffffffffu, s0, 8);
                s1 += __shfl_xor_sync(0xffffffffu, s1, 8);
                s0 += __shfl_xor_sync(0xffffffffu, s0, 16);
                s1 += __shfl_xor_sync(0xffffffffu, s1, 16);
                if (g == 0) {
                    atomicAdd(&ssq[z * 2 * Cc + col], s0);
                    atomicAdd(&ssq[z * 2 * Cc + col + 1], s1);
                }
            }
        }
    }

    // epilogue
    #pragma unroll
    for (int mi = 0; mi < 4; mi++) {
        const int row = arow0 + wm + mi * 16 + g;
        float bv0 = 0.f, bv1 = 0.f;
        if (bias && biasRowMode) { bv0 = bias[row]; bv1 = bias[row + 8]; }
        #pragma unroll
        for (int ni = 0; ni < NI; ni++) {
            const int col = brow0 + wn + ni * 8 + tig * 2;
            float bc0 = 0.f, bc1 = 0.f;
            if (bias && !biasRowMode) { bc0 = bias[col]; bc1 = bias[col + 1]; }
            size_t o0 = (size_t)z * obatch + (size_t)row * ldo + col;
            size_t o1 = o0 + 8 * (size_t)ldo;
            float v00 = c[mi][ni][0] + bv0 + bc0, v01 = c[mi][ni][1] + bv0 + bc1;
            float v10 = c[mi][ni][2] + bv1 + bc0, v11 = c[mi][ni][3] + bv1 + bc1;
            if (emul) {   // fused: out = t * ci1 * (gemm+bias)
                float2 m0 = *(const float2*)(emul + o0);
                float2 m1 = *(const float2*)(emul + o1);
                float s0 = escale[z * C6c + col], s1 = escale[z * C6c + col + 1];
                v00 *= m0.x * s0; v01 *= m0.y * s1;
                v10 *= m1.x * s0; v11 *= m1.y * s1;
            }
            if (Outh) {
                *(__half2*)(Outh + o0) = __floats2half2_rn(v00, v01);
                *(__half2*)(Outh + o1) = __floats2half2_rn(v10, v11);
            } else {
                *(float2*)(Outf + o0) = make_float2(v00, v01);
                *(float2*)(Outf + o1) = make_float2(v10, v11);
            }
        }
    }
}

// ---------------- weight fp32 -> fp16 -------------------------------------------
struct WList { const float* s[8]; int n[8]; int off[8]; };
__global__ void f2h_kernel(WList wl) {
    int idx = blockIdx.x * 256 + threadIdx.x;
    #pragma unroll
    for (int k = 0; k < 8; k++)
        if (idx < wl.n[k]) g_wbuf[wl.off[k] + idx] = __float2half(wl.s[k][idx]);
}

__global__ void zero_kernel() {
    int i = blockIdx.x * 256 + threadIdx.x;
    if (i < Bb*2*Cc)          g_sumsq[i] = 0.f;
    if (i < Bb*HEADS*HD*HD)   g_gram[i]  = 0.f;
    if (i < Bb*C6c)           g_tmean[i] = 0.f;
    if (i < Bb*Cc)            g_cm[i]    = 0.f;
}

__global__ void transpose_kernel(const float* __restrict__ in) {
    __shared__ float t[32][33];
    int b = blockIdx.z, c0 = blockIdx.y * 32, n0 = blockIdx.x * 32;
    int tx = threadIdx.x, ty = threadIdx.y;
    for (int i = ty; i < 32; i += 8)
        t[i][tx] = in[(size_t)b * CN + (size_t)(c0 + i) * NN + n0 + tx];
    __syncthreads();
    for (int i = ty; i < 32; i += 8)
        g_xh[(size_t)b * CN + (size_t)(n0 + i) * Cc + c0 + tx] = __float2half(t[tx][i]);
}

// ---------------- MMA gram: gram[bh] = q^T @ k over n ---------------------------
// grid (4 n-splits, 64 bh) x 256 threads; warp w covers 16 n per chunk of 128.
__global__ __launch_bounds__(256) void gram_kernel() {
    int bh = blockIdx.y; int b = bh >> 3, h = bh & 7;
    int nbase = blockIdx.x * 1024;
    const __half* qp = g_qkvh + (size_t)b * NN * C3 + h * HD;
    const __half* kp = qp + Cc;
    __shared__ __align__(16) __half qs[128 * 56];
    __shared__ __align__(16) __half ks_[128 * 56];
    __shared__ float gsm[HD * HD];
    int tid = threadIdx.x, wid = tid >> 5, lane = tid & 31;
    int g = lane >> 2, t = lane & 3;
    for (int i = tid; i < HD * HD; i += 256) gsm[i] = 0.f;

    float c[3][6][4];
    #pragma unroll
    for (int mi = 0; mi < 3; mi++)
        #pragma unroll
        for (int nt = 0; nt < 6; nt++)
            #pragma unroll
            for (int q = 0; q < 4; q++) c[mi][nt][q] = 0.f;

    for (int ch = 0; ch < 8; ch++) {
        __syncthreads();
        for (int e = tid; e < 768; e += 256) {
            int r = e / 6, s = e % 6;
            size_t goff = (size_t)(nbase + ch * 128 + r) * C3 + s * 8;
            cpa16h(qs  + r * 56 + s * 8, qp + goff);
            cpa16h(ks_ + r * 56 + s * 8, kp + goff);
        }
        CP_COMMIT(); CP_WAIT0();
        __syncthreads();

        int nrow = wid * 16;
        uint32_t a[3][4], bb[6][2];
        #pragma unroll
        for (int mi = 0; mi < 3; mi++) {
            int row = nrow + (lane & 7) + ((lane >> 4) << 3);
            int col = mi * 16 + ((lane >> 3) & 1) * 8;
            ldsm4t(a[mi], smem_u32(qs) + (row * 56 + col) * 2);
        }
        #pragma unroll
        for (int p = 0; p < 3; p++) {
            int row = nrow + (lane & 7) + ((lane >> 3) & 1) * 8;
            int col = p * 16 + (lane >> 4) * 8;
            uint32_t r[4];
            ldsm4t(r, smem_u32(ks_) + (row * 56 + col) * 2);
            bb[2*p][0] = r[0]; bb[2*p][1] = r[1];
            bb[2*p+1][0] = r[2]; bb[2*p+1][1] = r[3];
        }
        #pragma unroll
        for (int mi = 0; mi < 3; mi++)
            #pragma unroll
            for (int nt = 0; nt < 6; nt++)
                mma_f16(c[mi][nt], a[mi][0], a[mi][1], a[mi][2], a[mi][3],
                        bb[nt][0], bb[nt][1]);
    }

    #pragma unroll
    for (int mi = 0; mi < 3; mi++)
        #pragma unroll
        for (int nt = 0; nt < 6; nt++)
            #pragma unroll
            for (int q = 0; q < 4; q++) {
                int i = mi * 16 + g + ((q & 2) ? 8 : 0);
                int j = nt * 8 + 2 * t + (q & 1);
                atomicAdd(&gsm[i * HD + j], c[mi][nt][q]);
            }
    __syncthreads();
    for (int i = tid; i < HD * HD; i += 256)
        atomicAdd(&g_gram[(size_t)bh * HD * HD + i], gsm[i]);
}

__global__ void softmax_kernel(const float* __restrict__ temp) {
    int gi = blockIdx.x;
    int i = gi % HD; int bh = gi / HD;
    int b = bh >> 3, h = bh & 7;
    int tid = threadIdx.x;      // 64
    float qi = rsqrtf(fmaxf(g_sumsq[b * 2 * Cc + h * HD + i], 1e-24f));
    float v = -3.4e38f;
    if (tid < HD) {
        float kj = rsqrtf(fmaxf(g_sumsq[b * 2 * Cc + Cc + h * HD + tid], 1e-24f));
        v = g_gram[(size_t)bh * HD * HD + i * HD + tid] * qi * kj * temp[h];
    }
    __shared__ float red[64];
    red[tid] = v; __syncthreads();
    for (int st = 32; st > 0; st >>= 1) {
        if (tid < st) red[tid] = fmaxf(red[tid], red[tid + st]);
        __syncthreads();
    }
    float m = red[0]; __syncthreads();
    float e = (tid < HD) ? expf(v - m) : 0.f;
    red[tid] = e; __syncthreads();
    for (int st = 32; st > 0; st >>= 1) {
        if (tid < st) red[tid] += red[tid + st];
        __syncthreads();
    }
    if (tid < HD) g_attn[(size_t)bh * HD * HD + i * HD + tid] = e / red[0];
}

__global__ __launch_bounds__(128) void attnv_kernel() {
    int bh = blockIdx.y; int b = bh >> 3, h = bh & 7;
    int n = blockIdx.x * 128 + threadIdx.x;
    __shared__ float sa[HD * HD];
    for (int e = threadIdx.x; e < HD * HD; e += 128)
        sa[e] = g_attn[(size_t)bh * HD * HD + e];
    __syncthreads();
    const __half* vp = g_qkvh + (size_t)(b * NN + n) * C3 + 2 * Cc + h * HD;
    float vr[HD];
    #pragma unroll
    for (int j6 = 0; j6 < 6; j6++) {
        uint4 u = ((const uint4*)vp)[j6];
        const __half2* hp = (const __half2*)&u;
        #pragma unroll
        for (int q = 0; q < 4; q++) {
            float2 f = __half22float2(hp[q]);
            vr[j6 * 8 + q * 2] = f.x; vr[j6 * 8 + q * 2 + 1] = f.y;
        }
    }
    size_t obase = (size_t)(b * NN + n) * Cc + h * HD;
    float* op = g_at + obase;
    __half* oph = g_ath + obase;
    #pragma unroll
    for (int i0 = 0; i0 < HD; i0 += 8) {
        float res[8];
        #pragma unroll
        for (int i = 0; i < 8; i++) {
            float s = 0.f;
            #pragma unroll
            for (int j = 0; j < HD; j++) s += sa[(i0 + i) * HD + j] * vr[j];
            res[i] = s;
        }
        *(float4*)(op + i0)     = make_float4(res[0], res[1], res[2], res[3]);
        *(float4*)(op + i0 + 4) = make_float4(res[4], res[5], res[6], res[7]);
        __half2 hres[4];
        #pragma unroll
        for (int q = 0; q < 4; q++)
            hres[q] = __floats2half2_rn(res[q*2], res[q*2+1]);
        *(uint4*)(oph + i0) = *(uint4*)hres;
    }
}

// float4-vectorized depthwise conv (NHWC); fout/hout optional
__global__ void dwconv4(const float* __restrict__ in, const float* __restrict__ w,
                        const float* __restrict__ bias, float* __restrict__ fout,
                        __half* __restrict__ hout, int C, int ks, int pad, int dil)
{
    int idx = blockIdx.x * 256 + threadIdx.x;
    int C4 = C >> 2;
    int c4 = idx % C4; int rest = idx / C4;
    int xx = rest & 63, yy = (rest >> 6) & 63, b = rest >> 12;
    int c = c4 << 2;
    const float* ip = in + (size_t)(b * NN) * C + c;
    float4 bv = *(const float4*)(bias + c);
    float ax = bv.x, ay = bv.y, az = bv.z, aw = bv.w;
    const float* wp = w + c * ks * ks;
    const int K2 = ks * ks;
    for (int ky = 0; ky < ks; ky++) {
        int y = yy - pad + ky * dil;
        if ((unsigned)y >= 64u) continue;
        for (int kx = 0; kx < ks; kx++) {
            int x = xx - pad + kx * dil;
            if ((unsigned)x >= 64u) continue;
            float4 v = *(const float4*)(ip + (size_t)(y * 64 + x) * C);
            int tt2 = ky * ks + kx;
            ax += v.x * wp[tt2];
            ay += v.y * wp[tt2 + K2];
            az += v.z * wp[tt2 + 2 * K2];
            aw += v.w * wp[tt2 + 3 * K2];
        }
    }
    size_t off = (size_t)(b * NN + yy * 64 + xx) * C + c;
    if (fout) *(float4*)(fout + off) = make_float4(ax, ay, az, aw);
    if (hout) {
        __half2 h0 = __floats2half2_rn(ax, ay), h1 = __floats2half2_rn(az, aw);
        __half2 hh[2] = {h0, h1};
        *(uint2*)(hout + off) = *(uint2*)hh;
    }
}

// fused sp_dw (3x3 depthwise over C2c) + gelu gate -> gated fp16 (B,N,96)
__global__ void spdw_gelu(const float* __restrict__ sp, const float* __restrict__ w,
                          const float* __restrict__ bias, __half* __restrict__ out)
{
    int idx = blockIdx.x * 256 + threadIdx.x;   // over B*NN*24
    int c4 = idx % 24; int rest = idx / 24;
    int xx = rest & 63, yy = (rest >> 6) & 63, b = rest >> 12;
    int c = c4 << 2;
    const float* ip = sp + (size_t)(b * NN) * C2c;
    float4 bv1 = *(const float4*)(bias + c);
    float4 bv2 = *(const float4*)(bias + c + C4c);
    float a1[4] = {bv1.x, bv1.y, bv1.z, bv1.w};
    float a2[4] = {bv2.x, bv2.y, bv2.z, bv2.w};
    const float* w1 = w + c * 9;
    const float* w2 = w + (c + C4c) * 9;
    #pragma unroll
    for (int ky = 0; ky < 3; ky++) {
        int y = yy - 1 + ky;
        if ((unsigned)y >= 64u) continue;
        #pragma unroll
        for (int kx = 0; kx < 3; kx++) {
            int x = xx - 1 + kx;
            if ((unsigned)x >= 64u) continue;
            const float* pv = ip + (size_t)(y * 64 + x) * C2c + c;
            float4 v1 = *(const float4*)pv;
            float4 v2 = *(const float4*)(pv + C4c);
            int tt2 = ky * 3 + kx;
            a1[0] += v1.x * w1[tt2];      a1[1] += v1.y * w1[tt2 + 9];
            a1[2] += v1.z * w1[tt2 + 18]; a1[3] += v1.w * w1[tt2 + 27];
            a2[0] += v2.x * w2[tt2];      a2[1] += v2.y * w2[tt2 + 9];
            a2[2] += v2.z * w2[tt2 + 18]; a2[3] += v2.w * w2[tt2 + 27];
        }
    }
    float o[4];
    #pragma unroll
    for (int q = 0; q < 4; q++) {
        float gg = 0.5f * a1[q] * (1.f + erff(a1[q] * 0.70710678118654752f));
        o[q] = gg * a2[q];
    }
    __half2 hh[2] = {__floats2half2_rn(o[0], o[1]), __floats2half2_rn(o[2], o[3])};
    *(uint2*)(out + (size_t)(b * NN + yy * 64 + xx) * C4c + c) = *(uint2*)hh;
}

__global__ void tmean_kernel() {
    int b = blockIdx.y, n0 = blockIdx.x * 512, c = threadIdx.x;
    const float* p = g_tt + (size_t)b * NN * C6c + c;
    float s = 0.f;
    for (int n = n0; n < n0 + 512; n++) s += p[(size_t)n * C6c];
    atomicAdd(&g_tmean[b * C6c + c], s);
}

__global__ void ci1_kernel(const float* __restrict__ w, const float* __restrict__ bias) {
    int b = blockIdx.x, co = threadIdx.x;
    __shared__ float tm[C6c];
    tm[co] = g_tmean[b * C6c + co] * (1.f / NN);
    __syncthreads();
    float a = bias[co];
    #pragma unroll
    for (int ci = 0; ci < C6c; ci++) a += w[co * C6c + ci] * tm[ci];
    g_ci1v[b * C6c + co] = a;
}

__global__ void cm_kernel() {
    int b = blockIdx.y, n0 = blockIdx.x * 512, c = threadIdx.x;   // 384 threads
    const float* p = g_chmap + (size_t)b * NN * Cc + c;
    float s = 0.f;
    for (int n = n0; n < n0 + 512; n++) s += p[(size_t)n * Cc];
    atomicAdd(&g_cm[b * Cc + c], s);
}

__global__ void combine_kernel() {
    int idx = blockIdx.x * 256 + threadIdx.x;   // over Bb*NN*96
    int c4 = idx % 96; int bn = idx / 96;
    int b = bn / NN;
    int c = c4 << 2;
    size_t off = (size_t)bn * Cc + c;
    float4 at4 = *(const float4*)(g_at + off);
    float4 ch4 = *(const float4*)(g_chmap + off);
    float4 sp4 = *(const float4*)(g_spmap + off);
    float4 cv4 = *(const float4*)(g_convx + off);
    float4 cm4 = *(const float4*)(&g_cm[b * Cc + c]);
    float y[4];
    const float* a = &at4.x; const float* chp = &ch4.x;
    const float* s = &sp4.x; const float* cv = &cv4.x; const float* cm = &cm4.x;
    #pragma unroll
    for (int q = 0; q < 4; q++) {
        float s1 = 1.f / (1.f + expf(-s[q]));
        float s2 = 1.f / (1.f + expf(-cm[q] * (1.f / NN)));
        y[q] = (a[q] + chp[q]) * s1 + cv[q] * s2;
    }
    __half2 hh[2] = {__floats2half2_rn(y[0], y[1]), __floats2half2_rn(y[2], y[3])};
    *(uint2*)(g_yh + off) = *(uint2*)hh;
}

// ================================================================= launch ===
extern "C" void kernel_launch(void* const* d_in, const int* in_sizes, int n_in,
                              void* d_out, int out_size)
{
    const float* x           = (const float*)d_in[0];
    const float* temperature = (const float*)d_in[1];
    const float* qkv_w       = (const float*)d_in[2];
    const float* proj_w      = (const float*)d_in[3];
    const float* proj_b      = (const float*)d_in[4];
    const float* dw1_w       = (const float*)d_in[5];
    const float* dw1_b       = (const float*)d_in[6];
    const float* dw2_w       = (const float*)d_in[7];
    const float* dw2_b       = (const float*)d_in[8];
    const float* cp_in_w     = (const float*)d_in[9];
    const float* cp_in_b     = (const float*)d_in[10];
    const float* ci1_w       = (const float*)d_in[11];
    const float* ci1_b       = (const float*)d_in[12];
    const float* ci2a_w      = (const float*)d_in[13];
    const float* ci2a_b      = (const float*)d_in[14];
    const float* ci2b_w      = (const float*)d_in[15];
    const float* ci2b_b      = (const float*)d_in[16];
    const float* ci2c_w      = (const float*)d_in[17];
    const float* ci2c_b      = (const float*)d_in[18];
    const float* cp_out_w    = (const float*)d_in[19];
    const float* cp_out_b    = (const float*)d_in[20];
    const float* sp_in_w     = (const float*)d_in[21];
    const float* sp_in_b     = (const float*)d_in[22];
    const float* sp_dw_w     = (const float*)d_in[23];
    const float* sp_dw_b     = (const float*)d_in[24];
    const float* sp_out_w    = (const float*)d_in[25];
    const float* sp_out_b    = (const float*)d_in[26];
    float* out = (float*)d_out;

    __half *xh, *qkvh, *ath, *convxh, *u2h, *u3h, *gatedh, *yh, *wb;
    float *at, *t1, *convx, *chmap, *spmap, *tt, *u1, *sp, *ssq, *ci1v;
    cudaGetSymbolAddress((void**)&xh,     g_xh);
    cudaGetSymbolAddress((void**)&qkvh,   g_qkvh);
    cudaGetSymbolAddress((void**)&ath,    g_ath);
    cudaGetSymbolAddress((void**)&convxh, g_convxh);
    cudaGetSymbolAddress((void**)&u2h,    g_u2h);
    cudaGetSymbolAddress((void**)&u3h,    g_u3h);
    cudaGetSymbolAddress((void**)&gatedh, g_gatedh);
    cudaGetSymbolAddress((void**)&yh,     g_yh);
    cudaGetSymbolAddress((void**)&wb,     g_wbuf);
    cudaGetSymbolAddress((void**)&at,     g_at);
    cudaGetSymbolAddress((void**)&t1,     g_t1);
    cudaGetSymbolAddress((void**)&convx,  g_convx);
    cudaGetSymbolAddress((void**)&chmap,  g_chmap);
    cudaGetSymbolAddress((void**)&spmap,  g_spmap);
    cudaGetSymbolAddress((void**)&tt,     g_tt);
    cudaGetSymbolAddress((void**)&u1,     g_u1);
    cudaGetSymbolAddress((void**)&sp,     g_sp);
    cudaGetSymbolAddress((void**)&ssq,    g_sumsq);
    cudaGetSymbolAddress((void**)&ci1v,   g_ci1v);

    const long long bCN  = CN;
    const long long b3CN = (long long)NN * C3;
    const long long b64  = (long long)NN * C6c;
    const long long b192 = (long long)NN * C2c;
    const long long b96  = (long long)NN * C4c;

    const int SM4 = (128 + 128) * RSH * 2 * 2;   // 40960 B
    const int SM3 = (128 + 96)  * RSH * 2 * 2;   // 35840 B
    const int SM2 = (128 + 64)  * RSH * 2 * 2;   // 30720 B

    WList wl;
    wl.s[0]=qkv_w;  wl.n[0]=3*Cc*Cc;   wl.off[0]=W_QKV;
    wl.s[1]=dw1_w;  wl.n[1]=Cc*Cc;     wl.off[1]=W_DW1;
    wl.s[2]=cp_in_w;wl.n[2]=C6c*Cc;    wl.off[2]=W_CPIN;
    wl.s[3]=ci2c_w; wl.n[3]=C6c*C6c;   wl.off[3]=W_CI2C;
    wl.s[4]=cp_out_w;wl.n[4]=Cc*C6c;   wl.off[4]=W_CPOUT;
    wl.s[5]=sp_in_w;wl.n[5]=C2c*Cc;    wl.off[5]=W_SPIN;
    wl.s[6]=sp_out_w;wl.n[6]=Cc*C4c;   wl.off[6]=W_SPOUT;
    wl.s[7]=proj_w; wl.n[7]=Cc*Cc;     wl.off[7]=W_PROJ;

    zero_kernel<<<576, 256>>>();
    f2h_kernel<<<1728, 256>>>(wl);
    transpose_kernel<<<dim3(128, 12, Bb), dim3(32, 8)>>>(x);

    // qkv (+ fused sumsq)
    mma_gemm<4><<<dim3(9, 32, Bb), 256, SM4>>>(xh, Cc, bCN, wb + W_QKV, Cc, 0,
        nullptr, 0, nullptr, nullptr, ssq, nullptr, qkvh, C3, b3CN, Cc);
    gram_kernel<<<dim3(4, Bb * HEADS), 256>>>();
    softmax_kernel<<<Bb * HEADS * HD, 64>>>(temperature);
    attnv_kernel<<<dim3(NN / 128, Bb * HEADS), 128>>>();

    // dw1 on v
    mma_gemm<4><<<dim3(3, 32, Bb), 256, SM4>>>(qkvh + 2 * Cc, C3, b3CN, wb + W_DW1, Cc, 0,
        dw1_b, 0, nullptr, nullptr, nullptr, t1, nullptr, Cc, bCN, Cc);
    dwconv4<<<(Bb * NN * Cc / 4) / 256, 256>>>(t1, dw2_w, dw2_b, convx, convxh, Cc, 3, 1, 1);

    // channel projection
    mma_gemm<2><<<dim3(1, 32, Bb), 256, SM2>>>(ath, Cc, bCN, wb + W_CPIN, Cc, 0,
        cp_in_b, 0, nullptr, nullptr, nullptr, tt, nullptr, C6c, b64, Cc);
    tmean_kernel<<<dim3(8, Bb), 64>>>();
    ci1_kernel<<<Bb, C6c>>>(ci1_w, ci1_b);
    dwconv4<<<(Bb * NN * C6c / 4) / 256, 256>>>(tt, ci2a_w, ci2a_b, u1, nullptr, C6c, 3, 1, 1);
    dwconv4<<<(Bb * NN * C6c / 4) / 256, 256>>>(u1, ci2b_w, ci2b_b, nullptr, u2h, C6c, 7, 9, 3);
    mma_gemm<2><<<dim3(1, 32, Bb), 256, SM2>>>(u2h, C6c, b64, wb + W_CI2C, C6c, 0,
        ci2c_b, 0, tt, ci1v, nullptr, nullptr, u3h, C6c, b64, C6c);
    mma_gemm<4><<<dim3(3, 32, Bb), 256, SM4>>>(u3h, C6c, b64, wb + W_CPOUT, C6c, 0,
        cp_out_b, 0, nullptr, nullptr, nullptr, chmap, nullptr, Cc, bCN, C6c);
    cm_kernel<<<dim3(8, Bb), Cc>>>();

    // spatial projection
    mma_gemm<3><<<dim3(2, 32, Bb), 256, SM3>>>(convxh, Cc, bCN, wb + W_SPIN, Cc, 0,
        sp_in_b, 0, nullptr, nullptr, nullptr, sp, nullptr, C2c, b192, Cc);
    spdw_gelu<<<(Bb * NN * 24) / 256, 256>>>(sp, sp_dw_w, sp_dw_b, gatedh);
    mma_gemm<4><<<dim3(3, 32, Bb), 256, SM4>>>(gatedh, C4c, b96, wb + W_SPOUT, C4c, 0,
        sp_out_b, 0, nullptr, nullptr, nullptr, spmap, nullptr, Cc, bCN, C4c);

    combine_kernel<<<(Bb * NN * 96) / 256, 256>>>();

    // final projection -> (B,C,N)
    mma_gemm<4><<<dim3(32, 3, Bb), 256, SM4>>>(wb + W_PROJ, Cc, 0, yh, Cc, bCN,
        proj_b, 1, nullptr, nullptr, nullptr, out, nullptr, NN, bCN, Cc);
}

// round 9
// speedup vs baseline: 4.5601x; 1.0065x over previous
#include <cuda_runtime.h>
#include <cuda_fp16.h>
#include <cstdint>
#include <math.h>

#define Bb     8
#define Cc     384
#define NN     4096
#define HEADS  8
#define HD     48
#define CN     (Cc*NN)
#define C3     1152
#define C6c    64
#define C2c    192
#define C4c    96

// ---------------- scratch ----------------------------------------------------
__device__ __align__(16) __half g_xh   [Bb*NN*Cc];
__device__ __align__(16) __half g_qkvh [(size_t)Bb*NN*C3];
__device__ __align__(16) __half g_ath  [Bb*NN*Cc];
__device__ __align__(16) __half g_convxh[Bb*NN*Cc];
__device__ __align__(16) __half g_u2h  [Bb*NN*C6c];
__device__ __align__(16) __half g_u3h  [Bb*NN*C6c];
__device__ __align__(16) __half g_gatedh[Bb*NN*C4c];
__device__ __align__(16) __half g_yh   [Bb*NN*Cc];
__device__ __align__(16) __half g_wbuf [901120];
__device__ float g_at   [Bb*NN*Cc];
__device__ float g_t1   [Bb*NN*Cc];
__device__ float g_convx[Bb*NN*Cc];
__device__ float g_chmap[Bb*NN*Cc];
__device__ float g_spmap[Bb*NN*Cc];
__device__ float g_tt   [Bb*NN*C6c];
__device__ float g_u1   [Bb*NN*C6c];
__device__ float g_sp   [Bb*NN*C2c];
__device__ float g_sumsq[Bb*2*Cc];
__device__ float g_gram [Bb*HEADS*HD*HD];
__device__ float g_attn [Bb*HEADS*HD*HD];
__device__ float g_tmean[Bb*C6c];
__device__ float g_ci1v [Bb*C6c];
__device__ float g_cm   [Bb*Cc];

#define W_QKV   0
#define W_DW1   442368
#define W_CPIN  589824
#define W_CI2C  614400
#define W_CPOUT 618496
#define W_SPIN  643072
#define W_SPOUT 716800
#define W_PROJ  753664

__device__ __forceinline__ uint32_t smem_u32(const void* p) {
    uint32_t a;
    asm("{ .reg .u64 t; cvta.to.shared.u64 t, %1; cvt.u32.u64 %0, t; }" : "=r"(a) : "l"(p));
    return a;
}
__device__ __forceinline__ void cpa16u(uint32_t dst, const __half* src) {
    asm volatile("cp.async.cg.shared.global [%0], [%1], 16;"
                 :: "r"(dst), "l"(__cvta_generic_to_global(src)) : "memory");
}
#define CP_COMMIT() asm volatile("cp.async.commit_group;" ::: "memory")
#define CP_WAIT1()  asm volatile("cp.async.wait_group 1;" ::: "memory")
#define CP_WAIT0()  asm volatile("cp.async.wait_group 0;" ::: "memory")

__device__ __forceinline__ void ldsm4(uint32_t* r, uint32_t addr) {
    asm volatile("ldmatrix.sync.aligned.m8n8.x4.shared.b16 {%0,%1,%2,%3}, [%4];"
        : "=r"(r[0]), "=r"(r[1]), "=r"(r[2]), "=r"(r[3]) : "r"(addr));
}
__device__ __forceinline__ void ldsm4t(uint32_t* r, uint32_t addr) {
    asm volatile("ldmatrix.sync.aligned.m8n8.x4.trans.shared.b16 {%0,%1,%2,%3}, [%4];"
        : "=r"(r[0]), "=r"(r[1]), "=r"(r[2]), "=r"(r[3]) : "r"(addr));
}
__device__ __forceinline__ void ldsm2(uint32_t* r, uint32_t addr) {
    asm volatile("ldmatrix.sync.aligned.m8n8.x2.shared.b16 {%0,%1}, [%2];"
        : "=r"(r[0]), "=r"(r[1]) : "r"(addr));
}
__device__ __forceinline__ void mma_f16(float* d, uint32_t a0, uint32_t a1,
                                        uint32_t a2, uint32_t a3,
                                        uint32_t b0, uint32_t b1) {
    asm volatile(
        "mma.sync.aligned.m16n8k16.row.col.f32.f16.f16.f32 "
        "{%0,%1,%2,%3}, {%4,%5,%6,%7}, {%8,%9}, {%0,%1,%2,%3};"
        : "+f"(d[0]), "+f"(d[1]), "+f"(d[2]), "+f"(d[3])
        : "r"(a0), "r"(a1), "r"(a2), "r"(a3), "r"(b0), "r"(b1));
}

// ---------------- 3-stage pipelined fp16 ldmatrix GEMM -------------------------
// D[i][j] = sum_k A[i][k]*B[j][k] (both fp16, K-major). CTA 128 x NI*32, BK=32.
#define RSH 40
template<int NI>
__global__ __launch_bounds__(256)
void mma_gemm(const __half* __restrict__ A, int lda, long long abatch,
              const __half* __restrict__ B, int ldb, long long bbatch,
              const float* __restrict__ bias, int biasRowMode,
              const float* __restrict__ emul, const float* __restrict__ escale,
              float* __restrict__ ssq,
              float* __restrict__ Outf, __half* __restrict__ Outh,
              int ldo, long long obatch, int K)
{
    constexpr int n_tile = NI * 32;
    constexpr int BTASK = n_tile * 4;              // 16B tasks for B tile
    constexpr int BIT   = (BTASK + 255) / 256;     // loader iterations
    constexpr uint32_t STAGEB = (128 + n_tile) * RSH * 2;   // bytes per stage
    extern __shared__ __half sh[];
    const uint32_t smBase = smem_u32(sh);

    const int tid  = threadIdx.x;
    const int wid  = tid >> 5, lane = tid & 31;
    const int g    = lane >> 2, tig = lane & 3;
    const int z    = blockIdx.z;
    const int arow0 = blockIdx.y * 128;
    const int brow0 = blockIdx.x * n_tile;
    const int wm = (wid & 1) * 64;
    const int wn = (wid >> 1) * (NI * 8);

    const __half* Ab = A + (size_t)z * abatch + (size_t)arow0 * lda;
    const __half* Bp = B + (size_t)z * bbatch + (size_t)brow0 * ldb;

    // ---- hoisted loader addressing: A has 512 16B-tasks (2/thread)
    const __half* aSrc[2];  uint32_t aDst[2];
    #pragma unroll
    for (int i = 0; i < 2; i++) {
        int e = tid + i * 256;
        aSrc[i] = Ab + (size_t)(e >> 2) * lda + (e & 3) * 8;
        aDst[i] = ((e >> 2) * RSH + (e & 3) * 8) * 2;
    }
    // B: BTASK tasks, last iteration may be partial
    const __half* bSrc[BIT]; uint32_t bDst[BIT]; bool bAct[BIT];
    #pragma unroll
    for (int i = 0; i < BIT; i++) {
        int e = tid + i * 256;
        bAct[i] = (e < BTASK);
        int ec = bAct[i] ? e : 0;
        bSrc[i] = Bp + (size_t)(ec >> 2) * ldb + (ec & 3) * 8;
        bDst[i] = (128 * RSH + (ec >> 2) * RSH + (ec & 3) * 8) * 2;
    }

    // ---- hoisted ldmatrix offsets (bytes, relative to stage base)
    uint32_t aOff[4];
    #pragma unroll
    for (int mi = 0; mi < 4; mi++)
        aOff[mi] = (((wm + mi * 16 + (lane & 15)) * RSH) + (lane >> 4) * 8) * 2;
    uint32_t bPairOff[(NI + 1) / 2];
    #pragma unroll
    for (int np = 0; np < NI / 2; np++)
        bPairOff[np] = ((128 + wn + np * 16 + ((lane >> 4) << 3) + (lane & 7)) * RSH +
                        ((lane >> 3) & 1) * 8) * 2;
    uint32_t bSoloOff = ((128 + wn + (NI - 1) * 8 + (lane & 7)) * RSH +
                         ((lane >> 3) & 1) * 8) * 2;

    float c[4][NI][4];
    #pragma unroll
    for (int mi = 0; mi < 4; mi++)
        #pragma unroll
        for (int ni = 0; ni < NI; ni++)
            #pragma unroll
            for (int q = 0; q < 4; q++) c[mi][ni][q] = 0.f;

    auto loadTiles = [&](int kc, uint32_t stBase) {
        const int koff = kc * 32;
        #pragma unroll
        for (int i = 0; i < 2; i++)
            cpa16u(stBase + aDst[i], aSrc[i] + koff);
        #pragma unroll
        for (int i = 0; i < BIT; i++)
            if (bAct[i]) cpa16u(stBase + bDst[i], bSrc[i] + koff);
        CP_COMMIT();
    };

    const int nch = K >> 5;
    loadTiles(0, smBase);
    if (nch > 1) loadTiles(1, smBase + STAGEB); else CP_COMMIT();

    uint32_t smC = smBase;                  // compute stage base
    uint32_t smL = smBase + 2 * STAGEB;     // load stage base (kc+2)
    for (int kc = 0; kc < nch; kc++) {
        CP_WAIT1();
        __syncthreads();
        if (kc + 2 < nch) loadTiles(kc + 2, smL); else CP_COMMIT();

        #pragma unroll
        for (int ks = 0; ks < 2; ks++) {
            const uint32_t kb = ks * 32;    // 16 halves = 32 bytes
            uint32_t a[4][4];
            #pragma unroll
            for (int mi = 0; mi < 4; mi++)
                ldsm4(a[mi], smC + aOff[mi] + kb);
            uint32_t b[NI][2];
            #pragma unroll
            for (int np = 0; np < NI / 2; np++) {
                uint32_t r[4]; ldsm4(r, smC + bPairOff[np] + kb);
                b[2*np][0] = r[0]; b[2*np][1] = r[1];
                b[2*np+1][0] = r[2]; b[2*np+1][1] = r[3];
            }
            if (NI & 1) ldsm2(b[NI-1], smC + bSoloOff + kb);
            #pragma unroll
            for (int ni = 0; ni < NI; ni++)
                #pragma unroll
                for (int mi = 0; mi < 4; mi++)
                    mma_f16(c[mi][ni], a[mi][0], a[mi][1], a[mi][2], a[mi][3],
                            b[ni][0], b[ni][1]);
        }
        // rotate stages
        smC = (smC == smBase + 2 * STAGEB) ? smBase : smC + STAGEB;
        smL = (smL == smBase + 2 * STAGEB) ? smBase : smL + STAGEB;
    }

    // fused column sum-of-squares (qkv: q,k L2 norms)
    if (ssq) {
        #pragma unroll
        for (int ni = 0; ni < NI; ni++) {
            int col = brow0 + wn + ni * 8 + tig * 2;
            if (col < 2 * Cc) {
                float s0 = 0.f, s1 = 0.f;
                #pragma unroll
                for (int mi = 0; mi < 4; mi++) {
                    s0 += c[mi][ni][0] * c[mi][ni][0] + c[mi][ni][2] * c[mi][ni][2];
                    s1 += c[mi][ni][1] * c[mi][ni][1] + c[mi][ni][3] * c[mi][ni][3];
                }
                s0 += __shfl_xor_sync(0xffffffffu, s0, 4);
                s1 += __shfl_xor_sync(0xffffffffu, s1, 4);
                s0 += __shfl_xor_sync(0xffffffffu, s0, 8);
                s1 += __shfl_xor_sync(0xffffffffu, s1, 8);
                s0 += __shfl_xor_sync(0xffffffffu, s0, 16);
                s1 += __shfl_xor_sync(0xffffffffu, s1, 16);
                if (g == 0) {
                    atomicAdd(&ssq[z * 2 * Cc + col], s0);
                    atomicAdd(&ssq[z * 2 * Cc + col + 1], s1);
                }
            }
        }
    }

    // epilogue
    #pragma unroll
    for (int mi = 0; mi < 4; mi++) {
        const int row = arow0 + wm + mi * 16 + g;
        float bv0 = 0.f, bv1 = 0.f;
        if (bias && biasRowMode) { bv0 = bias[row]; bv1 = bias[row + 8]; }
        #pragma unroll
        for (int ni = 0; ni < NI; ni++) {
            const int col = brow0 + wn + ni * 8 + tig * 2;
            float bc0 = 0.f, bc1 = 0.f;
            if (bias && !biasRowMode) { bc0 = bias[col]; bc1 = bias[col + 1]; }
            size_t o0 = (size_t)z * obatch + (size_t)row * ldo + col;
            size_t o1 = o0 + 8 * (size_t)ldo;
            float v00 = c[mi][ni][0] + bv0 + bc0, v01 = c[mi][ni][1] + bv0 + bc1;
            float v10 = c[mi][ni][2] + bv1 + bc0, v11 = c[mi][ni][3] + bv1 + bc1;
            if (emul) {
                float2 m0 = *(const float2*)(emul + o0);
                float2 m1 = *(const float2*)(emul + o1);
                float s0 = escale[z * C6c + col], s1 = escale[z * C6c + col + 1];
                v00 *= m0.x * s0; v01 *= m0.y * s1;
                v10 *= m1.x * s0; v11 *= m1.y * s1;
            }
            if (Outh) {
                *(__half2*)(Outh + o0) = __floats2half2_rn(v00, v01);
                *(__half2*)(Outh + o1) = __floats2half2_rn(v10, v11);
            } else {
                *(float2*)(Outf + o0) = make_float2(v00, v01);
                *(float2*)(Outf + o1) = make_float2(v10, v11);
            }
        }
    }
}

// ---------------- weight fp32 -> fp16 -------------------------------------------
struct WList { const float* s[8]; int n[8]; int off[8]; };
__global__ void f2h_kernel(WList wl) {
    int idx = blockIdx.x * 256 + threadIdx.x;
    #pragma unroll
    for (int k = 0; k < 8; k++)
        if (idx < wl.n[k]) g_wbuf[wl.off[k] + idx] = __float2half(wl.s[k][idx]);
}

__global__ void zero_kernel() {
    int i = blockIdx.x * 256 + threadIdx.x;
    if (i < Bb*2*Cc)          g_sumsq[i] = 0.f;
    if (i < Bb*HEADS*HD*HD)   g_gram[i]  = 0.f;
    if (i < Bb*C6c)           g_tmean[i] = 0.f;
    if (i < Bb*Cc)            g_cm[i]    = 0.f;
}

__global__ void transpose_kernel(const float* __restrict__ in) {
    __shared__ float t[32][33];
    int b = blockIdx.z, c0 = blockIdx.y * 32, n0 = blockIdx.x * 32;
    int tx = threadIdx.x, ty = threadIdx.y;
    for (int i = ty; i < 32; i += 8)
        t[i][tx] = in[(size_t)b * CN + (size_t)(c0 + i) * NN + n0 + tx];
    __syncthreads();
    for (int i = ty; i < 32; i += 8)
        g_xh[(size_t)b * CN + (size_t)(n0 + i) * Cc + c0 + tx] = __float2half(t[tx][i]);
}

// ---------------- MMA gram ------------------------------------------------------
__global__ __launch_bounds__(256) void gram_kernel() {
    int bh = blockIdx.y; int b = bh >> 3, h = bh & 7;
    int nbase = blockIdx.x * 1024;
    const __half* qp = g_qkvh + (size_t)b * NN * C3 + h * HD;
    const __half* kp = qp + Cc;
    __shared__ __align__(16) __half qs[128 * 56];
    __shared__ __align__(16) __half ks_[128 * 56];
    __shared__ float gsm[HD * HD];
    int tid = threadIdx.x, wid = tid >> 5, lane = tid & 31;
    int g = lane >> 2, t = lane & 3;
    for (int i = tid; i < HD * HD; i += 256) gsm[i] = 0.f;

    float c[3][6][4];
    #pragma unroll
    for (int mi = 0; mi < 3; mi++)
        #pragma unroll
        for (int nt = 0; nt < 6; nt++)
            #pragma unroll
            for (int q = 0; q < 4; q++) c[mi][nt][q] = 0.f;

    for (int ch = 0; ch < 8; ch++) {
        __syncthreads();
        for (int e = tid; e < 768; e += 256) {
            int r = e / 6, s = e % 6;
            size_t goff = (size_t)(nbase + ch * 128 + r) * C3 + s * 8;
            cpa16u(smem_u32(qs  + r * 56 + s * 8), qp + goff);
            cpa16u(smem_u32(ks_ + r * 56 + s * 8), kp + goff);
        }
        CP_COMMIT(); CP_WAIT0();
        __syncthreads();

        int nrow = wid * 16;
        uint32_t a[3][4], bb[6][2];
        #pragma unroll
        for (int mi = 0; mi < 3; mi++) {
            int row = nrow + (lane & 7) + ((lane >> 4) << 3);
            int col = mi * 16 + ((lane >> 3) & 1) * 8;
            ldsm4t(a[mi], smem_u32(qs) + (row * 56 + col) * 2);
        }
        #pragma unroll
        for (int p = 0; p < 3; p++) {
            int row = nrow + (lane & 7) + ((lane >> 3) & 1) * 8;
            int col = p * 16 + (lane >> 4) * 8;
            uint32_t r[4];
            ldsm4t(r, smem_u32(ks_) + (row * 56 + col) * 2);
            bb[2*p][0] = r[0]; bb[2*p][1] = r[1];
            bb[2*p+1][0] = r[2]; bb[2*p+1][1] = r[3];
        }
        #pragma unroll
        for (int mi = 0; mi < 3; mi++)
            #pragma unroll
            for (int nt = 0; nt < 6; nt++)
                mma_f16(c[mi][nt], a[mi][0], a[mi][1], a[mi][2], a[mi][3],
                        bb[nt][0], bb[nt][1]);
    }

    #pragma unroll
    for (int mi = 0; mi < 3; mi++)
        #pragma unroll
        for (int nt = 0; nt < 6; nt++)
            #pragma unroll
            for (int q = 0; q < 4; q++) {
                int i = mi * 16 + g + ((q & 2) ? 8 : 0);
                int j = nt * 8 + 2 * t + (q & 1);
                atomicAdd(&gsm[i * HD + j], c[mi][nt][q]);
            }
    __syncthreads();
    for (int i = tid; i < HD * HD; i += 256)
        atomicAdd(&g_gram[(size_t)bh * HD * HD + i], gsm[i]);
}

__global__ void softmax_kernel(const float* __restrict__ temp) {
    int gi = blockIdx.x;
    int i = gi % HD; int bh = gi / HD;
    int b = bh >> 3, h = bh & 7;
    int tid = threadIdx.x;
    float qi = rsqrtf(fmaxf(g_sumsq[b * 2 * Cc + h * HD + i], 1e-24f));
    float v = -3.4e38f;
    if (tid < HD) {
        float kj = rsqrtf(fmaxf(g_sumsq[b * 2 * Cc + Cc + h * HD + tid], 1e-24f));
        v = g_gram[(size_t)bh * HD * HD + i * HD + tid] * qi * kj * temp[h];
    }
    __shared__ float red[64];
    red[tid] = v; __syncthreads();
    for (int st = 32; st > 0; st >>= 1) {
        if (tid < st) red[tid] = fmaxf(red[tid], red[tid + st]);
        __syncthreads();
    }
    float m = red[0]; __syncthreads();
    float e = (tid < HD) ? expf(v - m) : 0.f;
    red[tid] = e; __syncthreads();
    for (int st = 32; st > 0; st >>= 1) {
        if (tid < st) red[tid] += red[tid + st];
        __syncthreads();
    }
    if (tid < HD) g_attn[(size_t)bh * HD * HD + i * HD + tid] = e / red[0];
}

__global__ __launch_bounds__(128) void attnv_kernel() {
    int bh = blockIdx.y; int b = bh >> 3, h = bh & 7;
    int n = blockIdx.x * 128 + threadIdx.x;
    __shared__ float sa[HD * HD];
    for (int e = threadIdx.x; e < HD * HD; e += 128)
        sa[e] = g_attn[(size_t)bh * HD * HD + e];
    __syncthreads();
    const __half* vp = g_qkvh + (size_t)(b * NN + n) * C3 + 2 * Cc + h * HD;
    float vr[HD];
    #pragma unroll
    for (int j6 = 0; j6 < 6; j6++) {
        uint4 u = ((const uint4*)vp)[j6];
        const __half2* hp = (const __half2*)&u;
        #pragma unroll
        for (int q = 0; q < 4; q++) {
            float2 f = __half22float2(hp[q]);
            vr[j6 * 8 + q * 2] = f.x; vr[j6 * 8 + q * 2 + 1] = f.y;
        }
    }
    size_t obase = (size_t)(b * NN + n) * Cc + h * HD;
    float* op = g_at + obase;
    __half* oph = g_ath + obase;
    #pragma unroll
    for (int i0 = 0; i0 < HD; i0 += 8) {
        float res[8];
        #pragma unroll
        for (int i = 0; i < 8; i++) {
            float s = 0.f;
            #pragma unroll
            for (int j = 0; j < HD; j++) s += sa[(i0 + i) * HD + j] * vr[j];
            res[i] = s;
        }
        *(float4*)(op + i0)     = make_float4(res[0], res[1], res[2], res[3]);
        *(float4*)(op + i0 + 4) = make_float4(res[4], res[5], res[6], res[7]);
        __half2 hres[4];
        #pragma unroll
        for (int q = 0; q < 4; q++)
            hres[q] = __floats2half2_rn(res[q*2], res[q*2+1]);
        *(uint4*)(oph + i0) = *(uint4*)hres;
    }
}

__global__ void dwconv4(const float* __restrict__ in, const float* __restrict__ w,
                        const float* __restrict__ bias, float* __restrict__ fout,
                        __half* __restrict__ hout, int C, int ks, int pad, int dil)
{
    int idx = blockIdx.x * 256 + threadIdx.x;
    int C4 = C >> 2;
    int c4 = idx % C4; int rest = idx / C4;
    int xx = rest & 63, yy = (rest >> 6) & 63, b = rest >> 12;
    int c = c4 << 2;
    const float* ip = in + (size_t)(b * NN) * C + c;
    float4 bv = *(const float4*)(bias + c);
    float ax = bv.x, ay = bv.y, az = bv.z, aw = bv.w;
    const float* wp = w + c * ks * ks;
    const int K2 = ks * ks;
    for (int ky = 0; ky < ks; ky++) {
        int y = yy - pad + ky * dil;
        if ((unsigned)y >= 64u) continue;
        for (int kx = 0; kx < ks; kx++) {
            int x = xx - pad + kx * dil;
            if ((unsigned)x >= 64u) continue;
            float4 v = *(const float4*)(ip + (size_t)(y * 64 + x) * C);
            int tt2 = ky * ks + kx;
            ax += v.x * wp[tt2];
            ay += v.y * wp[tt2 + K2];
            az += v.z * wp[tt2 + 2 * K2];
            aw += v.w * wp[tt2 + 3 * K2];
        }
    }
    size_t off = (size_t)(b * NN + yy * 64 + xx) * C + c;
    if (fout) *(float4*)(fout + off) = make_float4(ax, ay, az, aw);
    if (hout) {
        __half2 h0 = __floats2half2_rn(ax, ay), h1 = __floats2half2_rn(az, aw);
        __half2 hh[2] = {h0, h1};
        *(uint2*)(hout + off) = *(uint2*)hh;
    }
}

__global__ void spdw_gelu(const float* __restrict__ sp, const float* __restrict__ w,
                          const float* __restrict__ bias, __half* __restrict__ out)
{
    int idx = blockIdx.x * 256 + threadIdx.x;
    int c4 = idx % 24; int rest = idx / 24;
    int xx = rest & 63, yy = (rest >> 6) & 63, b = rest >> 12;
    int c = c4 << 2;
    const float* ip = sp + (size_t)(b * NN) * C2c;
    float4 bv1 = *(const float4*)(bias + c);
    float4 bv2 = *(const float4*)(bias + c + C4c);
    float a1[4] = {bv1.x, bv1.y, bv1.z, bv1.w};
    float a2[4] = {bv2.x, bv2.y, bv2.z, bv2.w};
    const float* w1 = w + c * 9;
    const float* w2 = w + (c + C4c) * 9;
    #pragma unroll
    for (int ky = 0; ky < 3; ky++) {
        int y = yy - 1 + ky;
        if ((unsigned)y >= 64u) continue;
        #pragma unroll
        for (int kx = 0; kx < 3; kx++) {
            int x = xx - 1 + kx;
            if ((unsigned)x >= 64u) continue;
            const float* pv = ip + (size_t)(y * 64 + x) * C2c + c;
            float4 v1 = *(const float4*)pv;
            float4 v2 = *(const float4*)(pv + C4c);
            int tt2 = ky * 3 + kx;
            a1[0] += v1.x * w1[tt2];      a1[1] += v1.y * w1[tt2 + 9];
            a1[2] += v1.z * w1[tt2 + 18]; a1[3] += v1.w * w1[tt2 + 27];
            a2[0] += v2.x * w2[tt2];      a2[1] += v2.y * w2[tt2 + 9];
            a2[2] += v2.z * w2[tt2 + 18]; a2[3] += v2.w * w2[tt2 + 27];
        }
    }
    float o[4];
    #pragma unroll
    for (int q = 0; q < 4; q++) {
        float gg = 0.5f * a1[q] * (1.f + erff(a1[q] * 0.70710678118654752f));
        o[q] = gg * a2[q];
    }
    __half2 hh[2] = {__floats2half2_rn(o[0], o[1]), __floats2half2_rn(o[2], o[3])};
    *(uint2*)(out + (size_t)(b * NN + yy * 64 + xx) * C4c + c) = *(uint2*)hh;
}

__global__ void tmean_kernel() {
    int b = blockIdx.y, n0 = blockIdx.x * 512, c = threadIdx.x;
    const float* p = g_tt + (size_t)b * NN * C6c + c;
    float s = 0.f;
    for (int n = n0; n < n0 + 512; n++) s += p[(size_t)n * C6c];
    atomicAdd(&g_tmean[b * C6c + c], s);
}

__global__ void ci1_kernel(const float* __restrict__ w, const float* __restrict__ bias) {
    int b = blockIdx.x, co = threadIdx.x;
    __shared__ float tm[C6c];
    tm[co] = g_tmean[b * C6c + co] * (1.f / NN);
    __syncthreads();
    float a = bias[co];
    #pragma unroll
    for (int ci = 0; ci < C6c; ci++) a += w[co * C6c + ci] * tm[ci];
    g_ci1v[b * C6c + co] = a;
}

__global__ void cm_kernel() {
    int b = blockIdx.y, n0 = blockIdx.x * 512, c = threadIdx.x;
    const float* p = g_chmap + (size_t)b * NN * Cc + c;
    float s = 0.f;
    for (int n = n0; n < n0 + 512; n++) s += p[(size_t)n * Cc];
    atomicAdd(&g_cm[b * Cc + c], s);
}

__global__ void combine_kernel() {
    int idx = blockIdx.x * 256 + threadIdx.x;
    int c4 = idx % 96; int bn = idx / 96;
    int b = bn / NN;
    int c = c4 << 2;
    size_t off = (size_t)bn * Cc + c;
    float4 at4 = *(const float4*)(g_at + off);
    float4 ch4 = *(const float4*)(g_chmap + off);
    float4 sp4 = *(const float4*)(g_spmap + off);
    float4 cv4 = *(const float4*)(g_convx + off);
    float4 cm4 = *(const float4*)(&g_cm[b * Cc + c]);
    float y[4];
    const float* a = &at4.x; const float* chp = &ch4.x;
    const float* s = &sp4.x; const float* cv = &cv4.x; const float* cm = &cm4.x;
    #pragma unroll
    for (int q = 0; q < 4; q++) {
        float s1 = 1.f / (1.f + expf(-s[q]));
        float s2 = 1.f / (1.f + expf(-cm[q] * (1.f / NN)));
        y[q] = (a[q] + chp[q]) * s1 + cv[q] * s2;
    }
    __half2 hh[2] = {__floats2half2_rn(y[0], y[1]), __floats2half2_rn(y[2], y[3])};
    *(uint2*)(g_yh + off) = *(uint2*)hh;
}

// ================================================================= launch ===
extern "C" void kernel_launch(void* const* d_in, const int* in_sizes, int n_in,
                              void* d_out, int out_size)
{
    const float* x           = (const float*)d_in[0];
    const float* temperature = (const float*)d_in[1];
    const float* qkv_w       = (const float*)d_in[2];
    const float* proj_w      = (const float*)d_in[3];
    const float* proj_b      = (const float*)d_in[4];
    const float* dw1_w       = (const float*)d_in[5];
    const float* dw1_b       = (const float*)d_in[6];
    const float* dw2_w       = (const float*)d_in[7];
    const float* dw2_b       = (const float*)d_in[8];
    const float* cp_in_w     = (const float*)d_in[9];
    const float* cp_in_b     = (const float*)d_in[10];
    const float* ci1_w       = (const float*)d_in[11];
    const float* ci1_b       = (const float*)d_in[12];
    const float* ci2a_w      = (const float*)d_in[13];
    const float* ci2a_b      = (const float*)d_in[14];
    const float* ci2b_w      = (const float*)d_in[15];
    const float* ci2b_b      = (const float*)d_in[16];
    const float* ci2c_w      = (const float*)d_in[17];
    const float* ci2c_b      = (const float*)d_in[18];
    const float* cp_out_w    = (const float*)d_in[19];
    const float* cp_out_b    = (const float*)d_in[20];
    const float* sp_in_w     = (const float*)d_in[21];
    const float* sp_in_b     = (const float*)d_in[22];
    const float* sp_dw_w     = (const float*)d_in[23];
    const float* sp_dw_b     = (const float*)d_in[24];
    const float* sp_out_w    = (const float*)d_in[25];
    const float* sp_out_b    = (const float*)d_in[26];
    float* out = (float*)d_out;

    __half *xh, *qkvh, *ath, *convxh, *u2h, *u3h, *gatedh, *yh, *wb;
    float *at, *t1, *convx, *chmap, *spmap, *tt, *u1, *sp, *ssq, *ci1v;
    cudaGetSymbolAddress((void**)&xh,     g_xh);
    cudaGetSymbolAddress((void**)&qkvh,   g_qkvh);
    cudaGetSymbolAddress((void**)&ath,    g_ath);
    cudaGetSymbolAddress((void**)&convxh, g_convxh);
    cudaGetSymbolAddress((void**)&u2h,    g_u2h);
    cudaGetSymbolAddress((void**)&u3h,    g_u3h);
    cudaGetSymbolAddress((void**)&gatedh, g_gatedh);
    cudaGetSymbolAddress((void**)&yh,     g_yh);
    cudaGetSymbolAddress((void**)&wb,     g_wbuf);
    cudaGetSymbolAddress((void**)&at,     g_at);
    cudaGetSymbolAddress((void**)&t1,     g_t1);
    cudaGetSymbolAddress((void**)&convx,  g_convx);
    cudaGetSymbolAddress((void**)&chmap,  g_chmap);
    cudaGetSymbolAddress((void**)&spmap,  g_spmap);
    cudaGetSymbolAddress((void**)&tt,     g_tt);
    cudaGetSymbolAddress((void**)&u1,     g_u1);
    cudaGetSymbolAddress((void**)&sp,     g_sp);
    cudaGetSymbolAddress((void**)&ssq,    g_sumsq);
    cudaGetSymbolAddress((void**)&ci1v,   g_ci1v);

    const long long bCN  = CN;
    const long long b3CN = (long long)NN * C3;
    const long long b64  = (long long)NN * C6c;
    const long long b192 = (long long)NN * C2c;
    const long long b96  = (long long)NN * C4c;

    const int SM4 = (128 + 128) * RSH * 2 * 3;   // 61440 B (3 stages)
    const int SM3 = (128 + 96)  * RSH * 2 * 3;   // 53760 B
    const int SM2 = (128 + 64)  * RSH * 2 * 3;   // 46080 B
    cudaFuncSetAttribute(mma_gemm<4>, cudaFuncAttributeMaxDynamicSharedMemorySize, SM4);
    cudaFuncSetAttribute(mma_gemm<3>, cudaFuncAttributeMaxDynamicSharedMemorySize, SM3);
    cudaFuncSetAttribute(mma_gemm<2>, cudaFuncAttributeMaxDynamicSharedMemorySize, SM2);

    WList wl;
    wl.s[0]=qkv_w;  wl.n[0]=3*Cc*Cc;   wl.off[0]=W_QKV;
    wl.s[1]=dw1_w;  wl.n[1]=Cc*Cc;     wl.off[1]=W_DW1;
    wl.s[2]=cp_in_w;wl.n[2]=C6c*Cc;    wl.off[2]=W_CPIN;
    wl.s[3]=ci2c_w; wl.n[3]=C6c*C6c;   wl.off[3]=W_CI2C;
    wl.s[4]=cp_out_w;wl.n[4]=Cc*C6c;   wl.off[4]=W_CPOUT;
    wl.s[5]=sp_in_w;wl.n[5]=C2c*Cc;    wl.off[5]=W_SPIN;
    wl.s[6]=sp_out_w;wl.n[6]=Cc*C4c;   wl.off[6]=W_SPOUT;
    wl.s[7]=proj_w; wl.n[7]=Cc*Cc;     wl.off[7]=W_PROJ;

    zero_kernel<<<576, 256>>>();
    f2h_kernel<<<1728, 256>>>(wl);
    transpose_kernel<<<dim3(128, 12, Bb), dim3(32, 8)>>>(x);

    // qkv (+ fused sumsq)
    mma_gemm<4><<<dim3(9, 32, Bb), 256, SM4>>>(xh, Cc, bCN, wb + W_QKV, Cc, 0,
        nullptr, 0, nullptr, nullptr, ssq, nullptr, qkvh, C3, b3CN, Cc);
    gram_kernel<<<dim3(4, Bb * HEADS), 256>>>();
    softmax_kernel<<<Bb * HEADS * HD, 64>>>(temperature);
    attnv_kernel<<<dim3(NN / 128, Bb * HEADS), 128>>>();

    // dw1 on v
    mma_gemm<4><<<dim3(3, 32, Bb), 256, SM4>>>(qkvh + 2 * Cc, C3, b3CN, wb + W_DW1, Cc, 0,
        dw1_b, 0, nullptr, nullptr, nullptr, t1, nullptr, Cc, bCN, Cc);
    dwconv4<<<(Bb * NN * Cc / 4) / 256, 256>>>(t1, dw2_w, dw2_b, convx, convxh, Cc, 3, 1, 1);

    // channel projection
    mma_gemm<2><<<dim3(1, 32, Bb), 256, SM2>>>(ath, Cc, bCN, wb + W_CPIN, Cc, 0,
        cp_in_b, 0, nullptr, nullptr, nullptr, tt, nullptr, C6c, b64, Cc);
    tmean_kernel<<<dim3(8, Bb), 64>>>();
    ci1_kernel<<<Bb, C6c>>>(ci1_w, ci1_b);
    dwconv4<<<(Bb * NN * C6c / 4) / 256, 256>>>(tt, ci2a_w, ci2a_b, u1, nullptr, C6c, 3, 1, 1);
    dwconv4<<<(Bb * NN * C6c / 4) / 256, 256>>>(u1, ci2b_w, ci2b_b, nullptr, u2h, C6c, 7, 9, 3);
    mma_gemm<2><<<dim3(1, 32, Bb), 256, SM2>>>(u2h, C6c, b64, wb + W_CI2C, C6c, 0,
        ci2c_b, 0, tt, ci1v, nullptr, nullptr, u3h, C6c, b64, C6c);
    mma_gemm<4><<<dim3(3, 32, Bb), 256, SM4>>>(u3h, C6c, b64, wb + W_CPOUT, C6c, 0,
        cp_out_b, 0, nullptr, nullptr, nullptr, chmap, nullptr, Cc, bCN, C6c);
    cm_kernel<<<dim3(8, Bb), Cc>>>();

    // spatial projection
    mma_gemm<3><<<dim3(2, 32, Bb), 256, SM3>>>(convxh, Cc, bCN, wb + W_SPIN, Cc, 0,
        sp_in_b, 0, nullptr, nullptr, nullptr, sp, nullptr, C2c, b192, Cc);
    spdw_gelu<<<(Bb * NN * 24) / 256, 256>>>(sp, sp_dw_w, sp_dw_b, gatedh);
    mma_gemm<4><<<dim3(3, 32, Bb), 256, SM4>>>(gatedh, C4c, b96, wb + W_SPOUT, C4c, 0,
        sp_out_b, 0, nullptr, nullptr, nullptr, spmap, nullptr, Cc, bCN, C4c);

    combine_kernel<<<(Bb * NN * 96) / 256, 256>>>();

    // final projection -> (B,C,N)
    mma_gemm<4><<<dim3(32, 3, Bb), 256, SM4>>>(wb + W_PROJ, Cc, 0, yh, Cc, bCN,
        proj_b, 1, nullptr, nullptr, nullptr, out, nullptr, NN, bCN, Cc);
}

// round 10
// speedup vs baseline: 4.6601x; 1.0219x over previous
#include <cuda_runtime.h>
#include <cuda_fp16.h>
#include <cstdint>
#include <math.h>

#define Bb     8
#define Cc     384
#define NN     4096
#define HEADS  8
#define HD     48
#define CN     (Cc*NN)
#define C3     1152
#define C6c    64
#define C2c    192
#define C4c    96

// ---------------- scratch (all intermediates fp16; small stats fp32) ----------
__device__ __align__(16) __half g_xh    [Bb*NN*Cc];
__device__ __align__(16) __half g_qkvh  [(size_t)Bb*NN*C3];
__device__ __align__(16) __half g_ath   [Bb*NN*Cc];
__device__ __align__(16) __half g_t1h   [Bb*NN*Cc];
__device__ __align__(16) __half g_convxh[Bb*NN*Cc];
__device__ __align__(16) __half g_chmaph[Bb*NN*Cc];
__device__ __align__(16) __half g_spmaph[Bb*NN*Cc];
__device__ __align__(16) __half g_tth   [Bb*NN*C6c];
__device__ __align__(16) __half g_u1h   [Bb*NN*C6c];
__device__ __align__(16) __half g_u2h   [Bb*NN*C6c];
__device__ __align__(16) __half g_u3h   [Bb*NN*C6c];
__device__ __align__(16) __half g_sph   [Bb*NN*C2c];
__device__ __align__(16) __half g_gatedh[Bb*NN*C4c];
__device__ __align__(16) __half g_yh    [Bb*NN*Cc];
__device__ __align__(16) __half g_wbuf  [901120];
__device__ float g_sumsq[Bb*2*Cc];
__device__ float g_gram [Bb*HEADS*HD*HD];
__device__ float g_attn [Bb*HEADS*HD*HD];
__device__ float g_tmean[Bb*C6c];
__device__ float g_ci1v [Bb*C6c];
__device__ float g_cm   [Bb*Cc];

#define W_QKV   0
#define W_DW1   442368
#define W_CPIN  589824
#define W_CI2C  614400
#define W_CPOUT 618496
#define W_SPIN  643072
#define W_SPOUT 716800
#define W_PROJ  753664

__device__ __forceinline__ uint32_t smem_u32(const void* p) {
    uint32_t a;
    asm("{ .reg .u64 t; cvta.to.shared.u64 t, %1; cvt.u32.u64 %0, t; }" : "=r"(a) : "l"(p));
    return a;
}
__device__ __forceinline__ void cpa16u(uint32_t dst, const __half* src) {
    asm volatile("cp.async.cg.shared.global [%0], [%1], 16;"
                 :: "r"(dst), "l"(__cvta_generic_to_global(src)) : "memory");
}
#define CP_COMMIT() asm volatile("cp.async.commit_group;" ::: "memory")
#define CP_WAIT1()  asm volatile("cp.async.wait_group 1;" ::: "memory")
#define CP_WAIT0()  asm volatile("cp.async.wait_group 0;" ::: "memory")

__device__ __forceinline__ void ldsm4(uint32_t* r, uint32_t addr) {
    asm volatile("ldmatrix.sync.aligned.m8n8.x4.shared.b16 {%0,%1,%2,%3}, [%4];"
        : "=r"(r[0]), "=r"(r[1]), "=r"(r[2]), "=r"(r[3]) : "r"(addr));
}
__device__ __forceinline__ void ldsm4t(uint32_t* r, uint32_t addr) {
    asm volatile("ldmatrix.sync.aligned.m8n8.x4.trans.shared.b16 {%0,%1,%2,%3}, [%4];"
        : "=r"(r[0]), "=r"(r[1]), "=r"(r[2]), "=r"(r[3]) : "r"(addr));
}
__device__ __forceinline__ void ldsm2(uint32_t* r, uint32_t addr) {
    asm volatile("ldmatrix.sync.aligned.m8n8.x2.shared.b16 {%0,%1}, [%2];"
        : "=r"(r[0]), "=r"(r[1]) : "r"(addr));
}
__device__ __forceinline__ void mma_f16(float* d, uint32_t a0, uint32_t a1,
                                        uint32_t a2, uint32_t a3,
                                        uint32_t b0, uint32_t b1) {
    asm volatile(
        "mma.sync.aligned.m16n8k16.row.col.f32.f16.f16.f32 "
        "{%0,%1,%2,%3}, {%4,%5,%6,%7}, {%8,%9}, {%0,%1,%2,%3};"
        : "+f"(d[0]), "+f"(d[1]), "+f"(d[2]), "+f"(d[3])
        : "r"(a0), "r"(a1), "r"(a2), "r"(a3), "r"(b0), "r"(b1));
}

// ---------------- 3-stage pipelined fp16 ldmatrix GEMM -------------------------
#define RSH 40
template<int NI>
__global__ __launch_bounds__(256)
void mma_gemm(const __half* __restrict__ A, int lda, long long abatch,
              const __half* __restrict__ B, int ldb, long long bbatch,
              const float* __restrict__ bias, int biasRowMode,
              const __half* __restrict__ emul, const float* __restrict__ escale,
              float* __restrict__ ssq,
              float* __restrict__ Outf, __half* __restrict__ Outh,
              int ldo, long long obatch, int K)
{
    constexpr int n_tile = NI * 32;
    constexpr int BTASK = n_tile * 4;
    constexpr int BIT   = (BTASK + 255) / 256;
    constexpr uint32_t STAGEB = (128 + n_tile) * RSH * 2;
    extern __shared__ __half sh[];
    const uint32_t smBase = smem_u32(sh);

    const int tid  = threadIdx.x;
    const int wid  = tid >> 5, lane = tid & 31;
    const int g    = lane >> 2, tig = lane & 3;
    const int z    = blockIdx.z;
    const int arow0 = blockIdx.y * 128;
    const int brow0 = blockIdx.x * n_tile;
    const int wm = (wid & 1) * 64;
    const int wn = (wid >> 1) * (NI * 8);

    const __half* Ab = A + (size_t)z * abatch + (size_t)arow0 * lda;
    const __half* Bp = B + (size_t)z * bbatch + (size_t)brow0 * ldb;

    const __half* aSrc[2];  uint32_t aDst[2];
    #pragma unroll
    for (int i = 0; i < 2; i++) {
        int e = tid + i * 256;
        aSrc[i] = Ab + (size_t)(e >> 2) * lda + (e & 3) * 8;
        aDst[i] = ((e >> 2) * RSH + (e & 3) * 8) * 2;
    }
    const __half* bSrc[BIT]; uint32_t bDst[BIT]; bool bAct[BIT];
    #pragma unroll
    for (int i = 0; i < BIT; i++) {
        int e = tid + i * 256;
        bAct[i] = (e < BTASK);
        int ec = bAct[i] ? e : 0;
        bSrc[i] = Bp + (size_t)(ec >> 2) * ldb + (ec & 3) * 8;
        bDst[i] = (128 * RSH + (ec >> 2) * RSH + (ec & 3) * 8) * 2;
    }

    uint32_t aOff[4];
    #pragma unroll
    for (int mi = 0; mi < 4; mi++)
        aOff[mi] = (((wm + mi * 16 + (lane & 15)) * RSH) + (lane >> 4) * 8) * 2;
    uint32_t bPairOff[(NI + 1) / 2];
    #pragma unroll
    for (int np = 0; np < NI / 2; np++)
        bPairOff[np] = ((128 + wn + np * 16 + ((lane >> 4) << 3) + (lane & 7)) * RSH +
                        ((lane >> 3) & 1) * 8) * 2;
    uint32_t bSoloOff = ((128 + wn + (NI - 1) * 8 + (lane & 7)) * RSH +
                         ((lane >> 3) & 1) * 8) * 2;

    float c[4][NI][4];
    #pragma unroll
    for (int mi = 0; mi < 4; mi++)
        #pragma unroll
        for (int ni = 0; ni < NI; ni++)
            #pragma unroll
            for (int q = 0; q < 4; q++) c[mi][ni][q] = 0.f;

    auto loadTiles = [&](int kc, uint32_t stBase) {
        const int koff = kc * 32;
        #pragma unroll
        for (int i = 0; i < 2; i++)
            cpa16u(stBase + aDst[i], aSrc[i] + koff);
        #pragma unroll
        for (int i = 0; i < BIT; i++)
            if (bAct[i]) cpa16u(stBase + bDst[i], bSrc[i] + koff);
        CP_COMMIT();
    };

    const int nch = K >> 5;
    loadTiles(0, smBase);
    if (nch > 1) loadTiles(1, smBase + STAGEB); else CP_COMMIT();

    uint32_t smC = smBase;
    uint32_t smL = smBase + 2 * STAGEB;
    for (int kc = 0; kc < nch; kc++) {
        CP_WAIT1();
        __syncthreads();
        if (kc + 2 < nch) loadTiles(kc + 2, smL); else CP_COMMIT();

        #pragma unroll
        for (int ks = 0; ks < 2; ks++) {
            const uint32_t kb = ks * 32;
            uint32_t a[4][4];
            #pragma unroll
            for (int mi = 0; mi < 4; mi++)
                ldsm4(a[mi], smC + aOff[mi] + kb);
            uint32_t b[NI][2];
            #pragma unroll
            for (int np = 0; np < NI / 2; np++) {
                uint32_t r[4]; ldsm4(r, smC + bPairOff[np] + kb);
                b[2*np][0] = r[0]; b[2*np][1] = r[1];
                b[2*np+1][0] = r[2]; b[2*np+1][1] = r[3];
            }
            if (NI & 1) ldsm2(b[NI-1], smC + bSoloOff + kb);
            #pragma unroll
            for (int ni = 0; ni < NI; ni++)
                #pragma unroll
                for (int mi = 0; mi < 4; mi++)
                    mma_f16(c[mi][ni], a[mi][0], a[mi][1], a[mi][2], a[mi][3],
                            b[ni][0], b[ni][1]);
        }
        smC = (smC == smBase + 2 * STAGEB) ? smBase : smC + STAGEB;
        smL = (smL == smBase + 2 * STAGEB) ? smBase : smL + STAGEB;
    }

    if (ssq) {
        #pragma unroll
        for (int ni = 0; ni < NI; ni++) {
            int col = brow0 + wn + ni * 8 + tig * 2;
            if (col < 2 * Cc) {
                float s0 = 0.f, s1 = 0.f;
                #pragma unroll
                for (int mi = 0; mi < 4; mi++) {
                    s0 += c[mi][ni][0] * c[mi][ni][0] + c[mi][ni][2] * c[mi][ni][2];
                    s1 += c[mi][ni][1] * c[mi][ni][1] + c[mi][ni][3] * c[mi][ni][3];
                }
                s0 += __shfl_xor_sync(0xffffffffu, s0, 4);
                s1 += __shfl_xor_sync(0xffffffffu, s1, 4);
                s0 += __shfl_xor_sync(0xffffffffu, s0, 8);
                s1 += __shfl_xor_sync(0xffffffffu, s1, 8);
                s0 += __shfl_xor_sync(0xffffffffu, s0, 16);
                s1 += __shfl_xor_sync(0xffffffffu, s1, 16);
                if (g == 0) {
                    atomicAdd(&ssq[z * 2 * Cc + col], s0);
                    atomicAdd(&ssq[z * 2 * Cc + col + 1], s1);
                }
            }
        }
    }

    #pragma unroll
    for (int mi = 0; mi < 4; mi++) {
        const int row = arow0 + wm + mi * 16 + g;
        float bv0 = 0.f, bv1 = 0.f;
        if (bias && biasRowMode) { bv0 = bias[row]; bv1 = bias[row + 8]; }
        #pragma unroll
        for (int ni = 0; ni < NI; ni++) {
            const int col = brow0 + wn + ni * 8 + tig * 2;
            float bc0 = 0.f, bc1 = 0.f;
            if (bias && !biasRowMode) { bc0 = bias[col]; bc1 = bias[col + 1]; }
            size_t o0 = (size_t)z * obatch + (size_t)row * ldo + col;
            size_t o1 = o0 + 8 * (size_t)ldo;
            float v00 = c[mi][ni][0] + bv0 + bc0, v01 = c[mi][ni][1] + bv0 + bc1;
            float v10 = c[mi][ni][2] + bv1 + bc0, v11 = c[mi][ni][3] + bv1 + bc1;
            if (emul) {   // fused: out = t * ci1 * (gemm+bias), t fp16
                float2 m0 = __half22float2(*(const __half2*)(emul + o0));
                float2 m1 = __half22float2(*(const __half2*)(emul + o1));
                float s0 = escale[z * C6c + col], s1 = escale[z * C6c + col + 1];
                v00 *= m0.x * s0; v01 *= m0.y * s1;
                v10 *= m1.x * s0; v11 *= m1.y * s1;
            }
            if (Outh) {
                *(__half2*)(Outh + o0) = __floats2half2_rn(v00, v01);
                *(__half2*)(Outh + o1) = __floats2half2_rn(v10, v11);
            } else {
                *(float2*)(Outf + o0) = make_float2(v00, v01);
                *(float2*)(Outf + o1) = make_float2(v10, v11);
            }
        }
    }
}

// ---------------- weight fp32 -> fp16 -------------------------------------------
struct WList { const float* s[8]; int n[8]; int off[8]; };
__global__ void f2h_kernel(WList wl) {
    int idx = blockIdx.x * 256 + threadIdx.x;
    #pragma unroll
    for (int k = 0; k < 8; k++)
        if (idx < wl.n[k]) g_wbuf[wl.off[k] + idx] = __float2half(wl.s[k][idx]);
}

__global__ void zero_kernel() {
    int i = blockIdx.x * 256 + threadIdx.x;
    if (i < Bb*2*Cc)          g_sumsq[i] = 0.f;
    if (i < Bb*HEADS*HD*HD)   g_gram[i]  = 0.f;
    if (i < Bb*C6c)           g_tmean[i] = 0.f;
    if (i < Bb*Cc)            g_cm[i]    = 0.f;
}

__global__ void transpose_kernel(const float* __restrict__ in) {
    __shared__ float t[32][33];
    int b = blockIdx.z, c0 = blockIdx.y * 32, n0 = blockIdx.x * 32;
    int tx = threadIdx.x, ty = threadIdx.y;
    for (int i = ty; i < 32; i += 8)
        t[i][tx] = in[(size_t)b * CN + (size_t)(c0 + i) * NN + n0 + tx];
    __syncthreads();
    for (int i = ty; i < 32; i += 8)
        g_xh[(size_t)b * CN + (size_t)(n0 + i) * Cc + c0 + tx] = __float2half(t[tx][i]);
}

// ---------------- MMA gram ------------------------------------------------------
__global__ __launch_bounds__(256) void gram_kernel() {
    int bh = blockIdx.y; int b = bh >> 3, h = bh & 7;
    int nbase = blockIdx.x * 1024;
    const __half* qp = g_qkvh + (size_t)b * NN * C3 + h * HD;
    const __half* kp = qp + Cc;
    __shared__ __align__(16) __half qs[128 * 56];
    __shared__ __align__(16) __half ks_[128 * 56];
    __shared__ float gsm[HD * HD];
    int tid = threadIdx.x, wid = tid >> 5, lane = tid & 31;
    int g = lane >> 2, t = lane & 3;
    for (int i = tid; i < HD * HD; i += 256) gsm[i] = 0.f;

    float c[3][6][4];
    #pragma unroll
    for (int mi = 0; mi < 3; mi++)
        #pragma unroll
        for (int nt = 0; nt < 6; nt++)
            #pragma unroll
            for (int q = 0; q < 4; q++) c[mi][nt][q] = 0.f;

    for (int ch = 0; ch < 8; ch++) {
        __syncthreads();
        for (int e = tid; e < 768; e += 256) {
            int r = e / 6, s = e % 6;
            size_t goff = (size_t)(nbase + ch * 128 + r) * C3 + s * 8;
            cpa16u(smem_u32(qs  + r * 56 + s * 8), qp + goff);
            cpa16u(smem_u32(ks_ + r * 56 + s * 8), kp + goff);
        }
        CP_COMMIT(); CP_WAIT0();
        __syncthreads();

        int nrow = wid * 16;
        uint32_t a[3][4], bb[6][2];
        #pragma unroll
        for (int mi = 0; mi < 3; mi++) {
            int row = nrow + (lane & 7) + ((lane >> 4) << 3);
            int col = mi * 16 + ((lane >> 3) & 1) * 8;
            ldsm4t(a[mi], smem_u32(qs) + (row * 56 + col) * 2);
        }
        #pragma unroll
        for (int p = 0; p < 3; p++) {
            int row = nrow + (lane & 7) + ((lane >> 3) & 1) * 8;
            int col = p * 16 + (lane >> 4) * 8;
            uint32_t r[4];
            ldsm4t(r, smem_u32(ks_) + (row * 56 + col) * 2);
            bb[2*p][0] = r[0]; bb[2*p][1] = r[1];
            bb[2*p+1][0] = r[2]; bb[2*p+1][1] = r[3];
        }
        #pragma unroll
        for (int mi = 0; mi < 3; mi++)
            #pragma unroll
            for (int nt = 0; nt < 6; nt++)
                mma_f16(c[mi][nt], a[mi][0], a[mi][1], a[mi][2], a[mi][3],
                        bb[nt][0], bb[nt][1]);
    }

    #pragma unroll
    for (int mi = 0; mi < 3; mi++)
        #pragma unroll
        for (int nt = 0; nt < 6; nt++)
            #pragma unroll
            for (int q = 0; q < 4; q++) {
                int i = mi * 16 + g + ((q & 2) ? 8 : 0);
                int j = nt * 8 + 2 * t + (q & 1);
                atomicAdd(&gsm[i * HD + j], c[mi][nt][q]);
            }
    __syncthreads();
    for (int i = tid; i < HD * HD; i += 256)
        atomicAdd(&g_gram[(size_t)bh * HD * HD + i], gsm[i]);
}

__global__ void softmax_kernel(const float* __restrict__ temp) {
    int gi = blockIdx.x;
    int i = gi % HD; int bh = gi / HD;
    int b = bh >> 3, h = bh & 7;
    int tid = threadIdx.x;
    float qi = rsqrtf(fmaxf(g_sumsq[b * 2 * Cc + h * HD + i], 1e-24f));
    float v = -3.4e38f;
    if (tid < HD) {
        float kj = rsqrtf(fmaxf(g_sumsq[b * 2 * Cc + Cc + h * HD + tid], 1e-24f));
        v = g_gram[(size_t)bh * HD * HD + i * HD + tid] * qi * kj * temp[h];
    }
    __shared__ float red[64];
    red[tid] = v; __syncthreads();
    for (int st = 32; st > 0; st >>= 1) {
        if (tid < st) red[tid] = fmaxf(red[tid], red[tid + st]);
        __syncthreads();
    }
    float m = red[0]; __syncthreads();
    float e = (tid < HD) ? expf(v - m) : 0.f;
    red[tid] = e; __syncthreads();
    for (int st = 32; st > 0; st >>= 1) {
        if (tid < st) red[tid] += red[tid + st];
        __syncthreads();
    }
    if (tid < HD) g_attn[(size_t)bh * HD * HD + i * HD + tid] = e / red[0];
}

__global__ __launch_bounds__(128) void attnv_kernel() {
    int bh = blockIdx.y; int b = bh >> 3, h = bh & 7;
    int n = blockIdx.x * 128 + threadIdx.x;
    __shared__ float sa[HD * HD];
    for (int e = threadIdx.x; e < HD * HD; e += 128)
        sa[e] = g_attn[(size_t)bh * HD * HD + e];
    __syncthreads();
    const __half* vp = g_qkvh + (size_t)(b * NN + n) * C3 + 2 * Cc + h * HD;
    float vr[HD];
    #pragma unroll
    for (int j6 = 0; j6 < 6; j6++) {
        uint4 u = ((const uint4*)vp)[j6];
        const __half2* hp = (const __half2*)&u;
        #pragma unroll
        for (int q = 0; q < 4; q++) {
            float2 f = __half22float2(hp[q]);
            vr[j6 * 8 + q * 2] = f.x; vr[j6 * 8 + q * 2 + 1] = f.y;
        }
    }
    __half* oph = g_ath + (size_t)(b * NN + n) * Cc + h * HD;
    #pragma unroll
    for (int i0 = 0; i0 < HD; i0 += 8) {
        float res[8];
        #pragma unroll
        for (int i = 0; i < 8; i++) {
            float s = 0.f;
            #pragma unroll
            for (int j = 0; j < HD; j++) s += sa[(i0 + i) * HD + j] * vr[j];
            res[i] = s;
        }
        __half2 hres[4];
        #pragma unroll
        for (int q = 0; q < 4; q++)
            hres[q] = __floats2half2_rn(res[q*2], res[q*2+1]);
        *(uint4*)(oph + i0) = *(uint4*)hres;
    }
}

// fp16-in fp16-out depthwise conv (NHWC, C % 4 == 0), fp32 accumulate
__global__ void dwconv4h(const __half* __restrict__ in, const float* __restrict__ w,
                         const float* __restrict__ bias, __half* __restrict__ out,
                         int C, int ks, int pad, int dil)
{
    int idx = blockIdx.x * 256 + threadIdx.x;
    int C4 = C >> 2;
    int c4 = idx % C4; int rest = idx / C4;
    int xx = rest & 63, yy = (rest >> 6) & 63, b = rest >> 12;
    int c = c4 << 2;
    const __half* ip = in + (size_t)(b * NN) * C + c;
    float4 bv = *(const float4*)(bias + c);
    float a0 = bv.x, a1 = bv.y, a2 = bv.z, a3 = bv.w;
    const float* wp = w + c * ks * ks;
    const int K2 = ks * ks;
    for (int ky = 0; ky < ks; ky++) {
        int y = yy - pad + ky * dil;
        if ((unsigned)y >= 64u) continue;
        for (int kx = 0; kx < ks; kx++) {
            int x = xx - pad + kx * dil;
            if ((unsigned)x >= 64u) continue;
            uint2 u = *(const uint2*)(ip + (size_t)(y * 64 + x) * C);
            const __half2* hp = (const __half2*)&u;
            float2 f0 = __half22float2(hp[0]), f1 = __half22float2(hp[1]);
            int t = ky * ks + kx;
            a0 += f0.x * wp[t];
            a1 += f0.y * wp[t + K2];
            a2 += f1.x * wp[t + 2 * K2];
            a3 += f1.y * wp[t + 3 * K2];
        }
    }
    __half2 hh[2] = {__floats2half2_rn(a0, a1), __floats2half2_rn(a2, a3)};
    *(uint2*)(out + (size_t)(b * NN + yy * 64 + xx) * C + c) = *(uint2*)hh;
}

// fused sp_dw (3x3 depthwise over C2c, fp16 in) + gelu gate -> gated fp16
__global__ void spdw_gelu(const __half* __restrict__ sp, const float* __restrict__ w,
                          const float* __restrict__ bias, __half* __restrict__ out)
{
    int idx = blockIdx.x * 256 + threadIdx.x;
    int c4 = idx % 24; int rest = idx / 24;
    int xx = rest & 63, yy = (rest >> 6) & 63, b = rest >> 12;
    int c = c4 << 2;
    const __half* ip = sp + (size_t)(b * NN) * C2c;
    float4 bv1 = *(const float4*)(bias + c);
    float4 bv2 = *(const float4*)(bias + c + C4c);
    float a1[4] = {bv1.x, bv1.y, bv1.z, bv1.w};
    float a2[4] = {bv2.x, bv2.y, bv2.z, bv2.w};
    const float* w1 = w + c * 9;
    const float* w2 = w + (c + C4c) * 9;
    #pragma unroll
    for (int ky = 0; ky < 3; ky++) {
        int y = yy - 1 + ky;
        if ((unsigned)y >= 64u) continue;
        #pragma unroll
        for (int kx = 0; kx < 3; kx++) {
            int x = xx - 1 + kx;
            if ((unsigned)x >= 64u) continue;
            const __half* pv = ip + (size_t)(y * 64 + x) * C2c + c;
            uint2 u1v = *(const uint2*)pv;
            uint2 u2v = *(const uint2*)(pv + C4c);
            const __half2* h1 = (const __half2*)&u1v;
            const __half2* h2 = (const __half2*)&u2v;
            float2 f10 = __half22float2(h1[0]), f11 = __half22float2(h1[1]);
            float2 f20 = __half22float2(h2[0]), f21 = __half22float2(h2[1]);
            int t = ky * 3 + kx;
            a1[0] += f10.x * w1[t];      a1[1] += f10.y * w1[t + 9];
            a1[2] += f11.x * w1[t + 18]; a1[3] += f11.y * w1[t + 27];
            a2[0] += f20.x * w2[t];      a2[1] += f20.y * w2[t + 9];
            a2[2] += f21.x * w2[t + 18]; a2[3] += f21.y * w2[t + 27];
        }
    }
    float o[4];
    #pragma unroll
    for (int q = 0; q < 4; q++) {
        float gg = 0.5f * a1[q] * (1.f + erff(a1[q] * 0.70710678118654752f));
        o[q] = gg * a2[q];
    }
    __half2 hh[2] = {__floats2half2_rn(o[0], o[1]), __floats2half2_rn(o[2], o[3])};
    *(uint2*)(out + (size_t)(b * NN + yy * 64 + xx) * C4c + c) = *(uint2*)hh;
}

__global__ void tmean_kernel() {
    int b = blockIdx.y, n0 = blockIdx.x * 512, c = threadIdx.x;
    const __half* p = g_tth + (size_t)b * NN * C6c + c;
    float s = 0.f;
    for (int n = n0; n < n0 + 512; n++) s += __half2float(p[(size_t)n * C6c]);
    atomicAdd(&g_tmean[b * C6c + c], s);
}

__global__ void ci1_kernel(const float* __restrict__ w, const float* __restrict__ bias) {
    int b = blockIdx.x, co = threadIdx.x;
    __shared__ float tm[C6c];
    tm[co] = g_tmean[b * C6c + co] * (1.f / NN);
    __syncthreads();
    float a = bias[co];
    #pragma unroll
    for (int ci = 0; ci < C6c; ci++) a += w[co * C6c + ci] * tm[ci];
    g_ci1v[b * C6c + co] = a;
}

__global__ void cm_kernel() {
    int b = blockIdx.y, n0 = blockIdx.x * 512, c = threadIdx.x;
    const __half* p = g_chmaph + (size_t)b * NN * Cc + c;
    float s = 0.f;
    for (int n = n0; n < n0 + 512; n++) s += __half2float(p[(size_t)n * Cc]);
    atomicAdd(&g_cm[b * Cc + c], s);
}

__global__ void combine_kernel() {
    int idx = blockIdx.x * 256 + threadIdx.x;   // over Bb*NN*96
    int c4 = idx % 96; int bn = idx / 96;
    int b = bn / NN;
    int c = c4 << 2;
    size_t off = (size_t)bn * Cc + c;
    uint2 ua = *(const uint2*)(g_ath + off);
    uint2 uc = *(const uint2*)(g_chmaph + off);
    uint2 us = *(const uint2*)(g_spmaph + off);
    uint2 uv = *(const uint2*)(g_convxh + off);
    float4 cm4 = *(const float4*)(&g_cm[b * Cc + c]);
    const __half2* ha = (const __half2*)&ua;
    const __half2* hc = (const __half2*)&uc;
    const __half2* hs = (const __half2*)&us;
    const __half2* hv = (const __half2*)&uv;
    float a[4], ch[4], sp_[4], cv[4];
    #pragma unroll
    for (int q = 0; q < 2; q++) {
        float2 f;
        f = __half22float2(ha[q]); a[q*2] = f.x;  a[q*2+1] = f.y;
        f = __half22float2(hc[q]); ch[q*2] = f.x; ch[q*2+1] = f.y;
        f = __half22float2(hs[q]); sp_[q*2] = f.x; sp_[q*2+1] = f.y;
        f = __half22float2(hv[q]); cv[q*2] = f.x; cv[q*2+1] = f.y;
    }
    const float* cm = &cm4.x;
    float y[4];
    #pragma unroll
    for (int q = 0; q < 4; q++) {
        float s1 = 1.f / (1.f + expf(-sp_[q]));
        float s2 = 1.f / (1.f + expf(-cm[q] * (1.f / NN)));
        y[q] = (a[q] + ch[q]) * s1 + cv[q] * s2;
    }
    __half2 hh[2] = {__floats2half2_rn(y[0], y[1]), __floats2half2_rn(y[2], y[3])};
    *(uint2*)(g_yh + off) = *(uint2*)hh;
}

// ================================================================= launch ===
extern "C" void kernel_launch(void* const* d_in, const int* in_sizes, int n_in,
                              void* d_out, int out_size)
{
    const float* x           = (const float*)d_in[0];
    const float* temperature = (const float*)d_in[1];
    const float* qkv_w       = (const float*)d_in[2];
    const float* proj_w      = (const float*)d_in[3];
    const float* proj_b      = (const float*)d_in[4];
    const float* dw1_w       = (const float*)d_in[5];
    const float* dw1_b       = (const float*)d_in[6];
    const float* dw2_w       = (const float*)d_in[7];
    const float* dw2_b       = (const float*)d_in[8];
    const float* cp_in_w     = (const float*)d_in[9];
    const float* cp_in_b     = (const float*)d_in[10];
    const float* ci1_w       = (const float*)d_in[11];
    const float* ci1_b       = (const float*)d_in[12];
    const float* ci2a_w      = (const float*)d_in[13];
    const float* ci2a_b      = (const float*)d_in[14];
    const float* ci2b_w      = (const float*)d_in[15];
    const float* ci2b_b      = (const float*)d_in[16];
    const float* ci2c_w      = (const float*)d_in[17];
    const float* ci2c_b      = (const float*)d_in[18];
    const float* cp_out_w    = (const float*)d_in[19];
    const float* cp_out_b    = (const float*)d_in[20];
    const float* sp_in_w     = (const float*)d_in[21];
    const float* sp_in_b     = (const float*)d_in[22];
    const float* sp_dw_w     = (const float*)d_in[23];
    const float* sp_dw_b     = (const float*)d_in[24];
    const float* sp_out_w    = (const float*)d_in[25];
    const float* sp_out_b    = (const float*)d_in[26];
    float* out = (float*)d_out;

    __half *xh, *qkvh, *ath, *t1h, *convxh, *chmaph, *spmaph, *tth, *u1h, *u2h,
           *u3h, *sph, *gatedh, *yh, *wb;
    float *ssq, *ci1v;
    cudaGetSymbolAddress((void**)&xh,     g_xh);
    cudaGetSymbolAddress((void**)&qkvh,   g_qkvh);
    cudaGetSymbolAddress((void**)&ath,    g_ath);
    cudaGetSymbolAddress((void**)&t1h,    g_t1h);
    cudaGetSymbolAddress((void**)&convxh, g_convxh);
    cudaGetSymbolAddress((void**)&chmaph, g_chmaph);
    cudaGetSymbolAddress((void**)&spmaph, g_spmaph);
    cudaGetSymbolAddress((void**)&tth,    g_tth);
    cudaGetSymbolAddress((void**)&u1h,    g_u1h);
    cudaGetSymbolAddress((void**)&u2h,    g_u2h);
    cudaGetSymbolAddress((void**)&u3h,    g_u3h);
    cudaGetSymbolAddress((void**)&sph,    g_sph);
    cudaGetSymbolAddress((void**)&gatedh, g_gatedh);
    cudaGetSymbolAddress((void**)&yh,     g_yh);
    cudaGetSymbolAddress((void**)&wb,     g_wbuf);
    cudaGetSymbolAddress((void**)&ssq,    g_sumsq);
    cudaGetSymbolAddress((void**)&ci1v,   g_ci1v);

    const long long bCN  = CN;
    const long long b3CN = (long long)NN * C3;
    const long long b64  = (long long)NN * C6c;
    const long long b192 = (long long)NN * C2c;
    const long long b96  = (long long)NN * C4c;

    const int SM4 = (128 + 128) * RSH * 2 * 3;   // 61440 B (3 stages)
    const int SM3 = (128 + 96)  * RSH * 2 * 3;   // 53760 B
    const int SM2 = (128 + 64)  * RSH * 2 * 3;   // 46080 B
    cudaFuncSetAttribute(mma_gemm<4>, cudaFuncAttributeMaxDynamicSharedMemorySize, SM4);
    cudaFuncSetAttribute(mma_gemm<3>, cudaFuncAttributeMaxDynamicSharedMemorySize, SM3);
    cudaFuncSetAttribute(mma_gemm<2>, cudaFuncAttributeMaxDynamicSharedMemorySize, SM2);

    WList wl;
    wl.s[0]=qkv_w;  wl.n[0]=3*Cc*Cc;   wl.off[0]=W_QKV;
    wl.s[1]=dw1_w;  wl.n[1]=Cc*Cc;     wl.off[1]=W_DW1;
    wl.s[2]=cp_in_w;wl.n[2]=C6c*Cc;    wl.off[2]=W_CPIN;
    wl.s[3]=ci2c_w; wl.n[3]=C6c*C6c;   wl.off[3]=W_CI2C;
    wl.s[4]=cp_out_w;wl.n[4]=Cc*C6c;   wl.off[4]=W_CPOUT;
    wl.s[5]=sp_in_w;wl.n[5]=C2c*Cc;    wl.off[5]=W_SPIN;
    wl.s[6]=sp_out_w;wl.n[6]=Cc*C4c;   wl.off[6]=W_SPOUT;
    wl.s[7]=proj_w; wl.n[7]=Cc*Cc;     wl.off[7]=W_PROJ;

    zero_kernel<<<576, 256>>>();
    f2h_kernel<<<1728, 256>>>(wl);
    transpose_kernel<<<dim3(128, 12, Bb), dim3(32, 8)>>>(x);

    // qkv (+ fused sumsq)
    mma_gemm<4><<<dim3(9, 32, Bb), 256, SM4>>>(xh, Cc, bCN, wb + W_QKV, Cc, 0,
        nullptr, 0, nullptr, nullptr, ssq, nullptr, qkvh, C3, b3CN, Cc);
    gram_kernel<<<dim3(4, Bb * HEADS), 256>>>();
    softmax_kernel<<<Bb * HEADS * HD, 64>>>(temperature);
    attnv_kernel<<<dim3(NN / 128, Bb * HEADS), 128>>>();

    // dw1 on v -> t1h (fp16), then depthwise 3x3 -> convxh
    mma_gemm<4><<<dim3(3, 32, Bb), 256, SM4>>>(qkvh + 2 * Cc, C3, b3CN, wb + W_DW1, Cc, 0,
        dw1_b, 0, nullptr, nullptr, nullptr, nullptr, t1h, Cc, bCN, Cc);
    dwconv4h<<<(Bb * NN * Cc / 4) / 256, 256>>>(t1h, dw2_w, dw2_b, convxh, Cc, 3, 1, 1);

    // channel projection
    mma_gemm<2><<<dim3(1, 32, Bb), 256, SM2>>>(ath, Cc, bCN, wb + W_CPIN, Cc, 0,
        cp_in_b, 0, nullptr, nullptr, nullptr, nullptr, tth, C6c, b64, Cc);
    tmean_kernel<<<dim3(8, Bb), 64>>>();
    ci1_kernel<<<Bb, C6c>>>(ci1_w, ci1_b);
    dwconv4h<<<(Bb * NN * C6c / 4) / 256, 256>>>(tth, ci2a_w, ci2a_b, u1h, C6c, 3, 1, 1);
    dwconv4h<<<(Bb * NN * C6c / 4) / 256, 256>>>(u1h, ci2b_w, ci2b_b, u2h, C6c, 7, 9, 3);
    mma_gemm<2><<<dim3(1, 32, Bb), 256, SM2>>>(u2h, C6c, b64, wb + W_CI2C, C6c, 0,
        ci2c_b, 0, tth, ci1v, nullptr, nullptr, u3h, C6c, b64, C6c);
    mma_gemm<4><<<dim3(3, 32, Bb), 256, SM4>>>(u3h, C6c, b64, wb + W_CPOUT, C6c, 0,
        cp_out_b, 0, nullptr, nullptr, nullptr, nullptr, chmaph, Cc, bCN, C6c);
    cm_kernel<<<dim3(8, Bb), Cc>>>();

    // spatial projection
    mma_gemm<3><<<dim3(2, 32, Bb), 256, SM3>>>(convxh, Cc, bCN, wb + W_SPIN, Cc, 0,
        sp_in_b, 0, nullptr, nullptr, nullptr, nullptr, sph, C2c, b192, Cc);
    spdw_gelu<<<(Bb * NN * 24) / 256, 256>>>(sph, sp_dw_w, sp_dw_b, gatedh);
    mma_gemm<4><<<dim3(3, 32, Bb), 256, SM4>>>(gatedh, C4c, b96, wb + W_SPOUT, C4c, 0,
        sp_out_b, 0, nullptr, nullptr, nullptr, nullptr, spmaph, Cc, bCN, C4c);

    combine_kernel<<<(Bb * NN * 96) / 256, 256>>>();

    // final projection -> (B,C,N) fp32 output
    mma_gemm<4><<<dim3(32, 3, Bb), 256, SM4>>>(wb + W_PROJ, Cc, 0, yh, Cc, bCN,
        proj_b, 1, nullptr, nullptr, nullptr, out, nullptr, NN, bCN, Cc);
}

// round 11
// speedup vs baseline: 4.7332x; 1.0157x over previous
#include <cuda_runtime.h>
#include <cuda_fp16.h>
#include <cstdint>
#include <math.h>

#define Bb     8
#define Cc     384
#define NN     4096
#define HEADS  8
#define HD     48
#define CN     (Cc*NN)
#define C3     1152
#define C6c    64
#define C2c    192
#define C4c    96

// ---------------- scratch (all intermediates fp16; small stats fp32) ----------
__device__ __align__(16) __half g_xh    [Bb*NN*Cc];
__device__ __align__(16) __half g_qkvh  [(size_t)Bb*NN*C3];
__device__ __align__(16) __half g_ath   [Bb*NN*Cc];
__device__ __align__(16) __half g_t1h   [Bb*NN*Cc];
__device__ __align__(16) __half g_convxh[Bb*NN*Cc];
__device__ __align__(16) __half g_chmaph[Bb*NN*Cc];
__device__ __align__(16) __half g_tth   [Bb*NN*C6c];
__device__ __align__(16) __half g_u1h   [Bb*NN*C6c];
__device__ __align__(16) __half g_u2h   [Bb*NN*C6c];
__device__ __align__(16) __half g_u3h   [Bb*NN*C6c];
__device__ __align__(16) __half g_sph   [Bb*NN*C2c];
__device__ __align__(16) __half g_gatedh[Bb*NN*128];   // K padded 96 -> 128
__device__ __align__(16) __half g_yh    [Bb*NN*Cc];
__device__ __align__(16) __half g_wbuf  [917504];
__device__ float g_sumsq[Bb*2*Cc];
__device__ float g_gram [Bb*HEADS*HD*HD];
__device__ float g_attn [Bb*HEADS*HD*HD];
__device__ float g_tmean[Bb*C6c];
__device__ float g_ci1v [Bb*C6c];
__device__ float g_cm   [Bb*Cc];

#define W_QKV   0
#define W_DW1   442368
#define W_CPIN  589824
#define W_CI2C  614400
#define W_CPOUT 618496
#define W_SPIN  643072
#define W_SPOUT 716800      // padded: Cc rows x 128
#define W_PROJ  765952

__device__ __forceinline__ uint32_t smem_u32(const void* p) {
    uint32_t a;
    asm("{ .reg .u64 t; cvta.to.shared.u64 t, %1; cvt.u32.u64 %0, t; }" : "=r"(a) : "l"(p));
    return a;
}
__device__ __forceinline__ void cpa16u(uint32_t dst, const __half* src) {
    asm volatile("cp.async.cg.shared.global [%0], [%1], 16;"
                 :: "r"(dst), "l"(__cvta_generic_to_global(src)) : "memory");
}
#define CP_COMMIT() asm volatile("cp.async.commit_group;" ::: "memory")
#define CP_WAIT1()  asm volatile("cp.async.wait_group 1;" ::: "memory")
#define CP_WAIT0()  asm volatile("cp.async.wait_group 0;" ::: "memory")

__device__ __forceinline__ void ldsm4(uint32_t* r, uint32_t addr) {
    asm volatile("ldmatrix.sync.aligned.m8n8.x4.shared.b16 {%0,%1,%2,%3}, [%4];"
        : "=r"(r[0]), "=r"(r[1]), "=r"(r[2]), "=r"(r[3]) : "r"(addr));
}
__device__ __forceinline__ void ldsm4t(uint32_t* r, uint32_t addr) {
    asm volatile("ldmatrix.sync.aligned.m8n8.x4.trans.shared.b16 {%0,%1,%2,%3}, [%4];"
        : "=r"(r[0]), "=r"(r[1]), "=r"(r[2]), "=r"(r[3]) : "r"(addr));
}
__device__ __forceinline__ void ldsm2(uint32_t* r, uint32_t addr) {
    asm volatile("ldmatrix.sync.aligned.m8n8.x2.shared.b16 {%0,%1}, [%2];"
        : "=r"(r[0]), "=r"(r[1]) : "r"(addr));
}
__device__ __forceinline__ void mma_f16(float* d, uint32_t a0, uint32_t a1,
                                        uint32_t a2, uint32_t a3,
                                        uint32_t b0, uint32_t b1) {
    asm volatile(
        "mma.sync.aligned.m16n8k16.row.col.f32.f16.f16.f32 "
        "{%0,%1,%2,%3}, {%4,%5,%6,%7}, {%8,%9}, {%0,%1,%2,%3};"
        : "+f"(d[0]), "+f"(d[1]), "+f"(d[2]), "+f"(d[3])
        : "r"(a0), "r"(a1), "r"(a2), "r"(a3), "r"(b0), "r"(b1));
}
__device__ __forceinline__ float sigf(float v) { return 1.f / (1.f + expf(-v)); }

// ---------------- 3-stage pipelined fp16 ldmatrix GEMM, BK=64 -------------------
// D[i][j] = sum_k A[i][k]*B[j][k] (both fp16, K-major). CTA 128 x NI*32.
#define RSH 72       // halves per smem row (144B): 9 = 1 mod 8 -> conflict-free
template<int NI>
__global__ __launch_bounds__(256, 2)
void mma_gemm(const __half* __restrict__ A, int lda, long long abatch,
              const __half* __restrict__ B, int ldb, long long bbatch,
              const float* __restrict__ bias, int biasRowMode,
              const __half* __restrict__ emul, const float* __restrict__ escale,
              float* __restrict__ ssq,
              const __half* __restrict__ cAt, const __half* __restrict__ cCh,
              const __half* __restrict__ cCv, const float* __restrict__ cCm,
              float* __restrict__ Outf, __half* __restrict__ Outh,
              int ldo, long long obatch, int K)
{
    constexpr int n_tile = NI * 32;
    constexpr uint32_t STAGEB = (128 + n_tile) * RSH * 2;
    extern __shared__ __half sh[];
    const uint32_t smBase = smem_u32(sh);

    const int tid  = threadIdx.x;
    const int wid  = tid >> 5, lane = tid & 31;
    const int g    = lane >> 2, tig = lane & 3;
    const int z    = blockIdx.z;
    const int arow0 = blockIdx.y * 128;
    const int brow0 = blockIdx.x * n_tile;
    const int wm = (wid & 1) * 64;
    const int wn = (wid >> 1) * (NI * 8);

    const __half* Ab = A + (size_t)z * abatch + (size_t)arow0 * lda;
    const __half* Bp = B + (size_t)z * bbatch + (size_t)brow0 * ldb;

    // A: 128 rows x 8 segs = 1024 tasks (4/thread); B: n_tile*8 = NI*256 (NI/thread)
    const __half* aSrc[4];  uint32_t aDst[4];
    #pragma unroll
    for (int i = 0; i < 4; i++) {
        int e = tid + i * 256;
        aSrc[i] = Ab + (size_t)(e >> 3) * lda + (e & 7) * 8;
        aDst[i] = ((e >> 3) * RSH + (e & 7) * 8) * 2;
    }
    const __half* bSrc[NI]; uint32_t bDst[NI];
    #pragma unroll
    for (int i = 0; i < NI; i++) {
        int e = tid + i * 256;
        bSrc[i] = Bp + (size_t)(e >> 3) * ldb + (e & 7) * 8;
        bDst[i] = (128 * RSH + (e >> 3) * RSH + (e & 7) * 8) * 2;
    }

    uint32_t aOff[4];
    #pragma unroll
    for (int mi = 0; mi < 4; mi++)
        aOff[mi] = (((wm + mi * 16 + (lane & 15)) * RSH) + (lane >> 4) * 8) * 2;
    uint32_t bPairOff[(NI + 1) / 2];
    #pragma unroll
    for (int np = 0; np < NI / 2; np++)
        bPairOff[np] = ((128 + wn + np * 16 + ((lane >> 4) << 3) + (lane & 7)) * RSH +
                        ((lane >> 3) & 1) * 8) * 2;
    uint32_t bSoloOff = ((128 + wn + (NI - 1) * 8 + (lane & 7)) * RSH +
                         ((lane >> 3) & 1) * 8) * 2;

    float c[4][NI][4];
    #pragma unroll
    for (int mi = 0; mi < 4; mi++)
        #pragma unroll
        for (int ni = 0; ni < NI; ni++)
            #pragma unroll
            for (int q = 0; q < 4; q++) c[mi][ni][q] = 0.f;

    auto loadTiles = [&](int kc, uint32_t stBase) {
        const int koff = kc * 64;
        #pragma unroll
        for (int i = 0; i < 4; i++)
            cpa16u(stBase + aDst[i], aSrc[i] + koff);
        #pragma unroll
        for (int i = 0; i < NI; i++)
            cpa16u(stBase + bDst[i], bSrc[i] + koff);
        CP_COMMIT();
    };

    const int nch = K >> 6;
    loadTiles(0, smBase);
    if (nch > 1) loadTiles(1, smBase + STAGEB); else CP_COMMIT();

    uint32_t smC = smBase;
    uint32_t smL = smBase + 2 * STAGEB;
    for (int kc = 0; kc < nch; kc++) {
        CP_WAIT1();
        __syncthreads();
        if (kc + 2 < nch) loadTiles(kc + 2, smL); else CP_COMMIT();

        #pragma unroll
        for (int ks = 0; ks < 4; ks++) {
            const uint32_t kb = ks * 32;     // 16 halves
            uint32_t a[4][4];
            #pragma unroll
            for (int mi = 0; mi < 4; mi++)
                ldsm4(a[mi], smC + aOff[mi] + kb);
            uint32_t b[NI][2];
            #pragma unroll
            for (int np = 0; np < NI / 2; np++) {
                uint32_t r[4]; ldsm4(r, smC + bPairOff[np] + kb);
                b[2*np][0] = r[0]; b[2*np][1] = r[1];
                b[2*np+1][0] = r[2]; b[2*np+1][1] = r[3];
            }
            if (NI & 1) ldsm2(b[NI-1], smC + bSoloOff + kb);
            #pragma unroll
            for (int ni = 0; ni < NI; ni++)
                #pragma unroll
                for (int mi = 0; mi < 4; mi++)
                    mma_f16(c[mi][ni], a[mi][0], a[mi][1], a[mi][2], a[mi][3],
                            b[ni][0], b[ni][1]);
        }
        smC = (smC == smBase + 2 * STAGEB) ? smBase : smC + STAGEB;
        smL = (smL == smBase + 2 * STAGEB) ? smBase : smL + STAGEB;
    }

    if (ssq) {
        #pragma unroll
        for (int ni = 0; ni < NI; ni++) {
            int col = brow0 + wn + ni * 8 + tig * 2;
            if (col < 2 * Cc) {
                float s0 = 0.f, s1 = 0.f;
                #pragma unroll
                for (int mi = 0; mi < 4; mi++) {
                    s0 += c[mi][ni][0] * c[mi][ni][0] + c[mi][ni][2] * c[mi][ni][2];
                    s1 += c[mi][ni][1] * c[mi][ni][1] + c[mi][ni][3] * c[mi][ni][3];
                }
                s0 += __shfl_xor_sync(0xffffffffu, s0, 4);
                s1 += __shfl_xor_sync(0xffffffffu, s1, 4);
                s0 += __shfl_xor_sync(0xffffffffu, s0, 8);
                s1 += __shfl_xor_sync(0xffffffffu, s1, 8);
                s0 += __shfl_xor_sync(0xffffffffu, s0, 16);
                s1 += __shfl_xor_sync(0xffffffffu, s1, 16);
                if (g == 0) {
                    atomicAdd(&ssq[z * 2 * Cc + col], s0);
                    atomicAdd(&ssq[z * 2 * Cc + col + 1], s1);
                }
            }
        }
    }

    #pragma unroll
    for (int mi = 0; mi < 4; mi++) {
        const int row = arow0 + wm + mi * 16 + g;
        float bv0 = 0.f, bv1 = 0.f;
        if (bias && biasRowMode) { bv0 = bias[row]; bv1 = bias[row + 8]; }
        #pragma unroll
        for (int ni = 0; ni < NI; ni++) {
            const int col = brow0 + wn + ni * 8 + tig * 2;
            float bc0 = 0.f, bc1 = 0.f;
            if (bias && !biasRowMode) { bc0 = bias[col]; bc1 = bias[col + 1]; }
            size_t o0 = (size_t)z * obatch + (size_t)row * ldo + col;
            size_t o1 = o0 + 8 * (size_t)ldo;
            float v00 = c[mi][ni][0] + bv0 + bc0, v01 = c[mi][ni][1] + bv0 + bc1;
            float v10 = c[mi][ni][2] + bv1 + bc0, v11 = c[mi][ni][3] + bv1 + bc1;
            if (emul) {   // fused: out = t * ci1 * (gemm+bias)
                float2 m0 = __half22float2(*(const __half2*)(emul + o0));
                float2 m1 = __half22float2(*(const __half2*)(emul + o1));
                float s0 = escale[z * C6c + col], s1 = escale[z * C6c + col + 1];
                v00 *= m0.x * s0; v01 *= m0.y * s1;
                v10 *= m1.x * s0; v11 *= m1.y * s1;
            }
            if (cAt) {    // fused combine: y = (at+ch)*sig(gemm) + cv*sig(cm)
                float sc0 = sigf(cCm[z * Cc + col] * (1.f / NN));
                float sc1 = sigf(cCm[z * Cc + col + 1] * (1.f / NN));
                float2 a0 = __half22float2(*(const __half2*)(cAt + o0));
                float2 a1 = __half22float2(*(const __half2*)(cAt + o1));
                float2 h0 = __half22float2(*(const __half2*)(cCh + o0));
                float2 h1 = __half22float2(*(const __half2*)(cCh + o1));
                float2 w0 = __half22float2(*(const __half2*)(cCv + o0));
                float2 w1 = __half22float2(*(const __half2*)(cCv + o1));
                v00 = (a0.x + h0.x) * sigf(v00) + w0.x * sc0;
                v01 = (a0.y + h0.y) * sigf(v01) + w0.y * sc1;
                v10 = (a1.x + h1.x) * sigf(v10) + w1.x * sc0;
                v11 = (a1.y + h1.y) * sigf(v11) + w1.y * sc1;
            }
            if (Outh) {
                *(__half2*)(Outh + o0) = __floats2half2_rn(v00, v01);
                *(__half2*)(Outh + o1) = __floats2half2_rn(v10, v11);
            } else {
                *(float2*)(Outf + o0) = make_float2(v00, v01);
                *(float2*)(Outf + o1) = make_float2(v10, v11);
            }
        }
    }
}

// ---------------- weight fp32 -> fp16 (entry may be K-padded) -------------------
struct WList { const float* s[8]; int n[8]; int off[8]; int padK[8]; int srcK[8]; };
__global__ void f2h_kernel(WList wl) {
    int idx = blockIdx.x * 256 + threadIdx.x;
    #pragma unroll
    for (int k = 0; k < 8; k++) {
        if (idx < wl.n[k]) {
            float v;
            if (wl.padK[k]) {
                int r = idx / wl.padK[k], kk = idx % wl.padK[k];
                v = (kk < wl.srcK[k]) ? wl.s[k][r * wl.srcK[k] + kk] : 0.f;
            } else v = wl.s[k][idx];
            g_wbuf[wl.off[k] + idx] = __float2half(v);
        }
    }
}

__global__ void zero_kernel() {
    int i = blockIdx.x * 256 + threadIdx.x;
    if (i < Bb*2*Cc)          g_sumsq[i] = 0.f;
    if (i < Bb*HEADS*HD*HD)   g_gram[i]  = 0.f;
    if (i < Bb*C6c)           g_tmean[i] = 0.f;
    if (i < Bb*Cc)            g_cm[i]    = 0.f;
    if (i < Bb*NN*4) {        // zero gated pad [96,128) once per launch (uint4 = 8 halves)
        int row = i >> 2, seg = i & 3;
        *(uint4*)(g_gatedh + (size_t)row * 128 + 96 + seg * 8) = make_uint4(0,0,0,0);
    }
}

__global__ void transpose_kernel(const float* __restrict__ in) {
    __shared__ float t[32][33];
    int b = blockIdx.z, c0 = blockIdx.y * 32, n0 = blockIdx.x * 32;
    int tx = threadIdx.x, ty = threadIdx.y;
    for (int i = ty; i < 32; i += 8)
        t[i][tx] = in[(size_t)b * CN + (size_t)(c0 + i) * NN + n0 + tx];
    __syncthreads();
    for (int i = ty; i < 32; i += 8)
        g_xh[(size_t)b * CN + (size_t)(n0 + i) * Cc + c0 + tx] = __float2half(t[tx][i]);
}

// ---------------- MMA gram ------------------------------------------------------
__global__ __launch_bounds__(256) void gram_kernel() {
    int bh = blockIdx.y; int b = bh >> 3, h = bh & 7;
    int nbase = blockIdx.x * 1024;
    const __half* qp = g_qkvh + (size_t)b * NN * C3 + h * HD;
    const __half* kp = qp + Cc;
    __shared__ __align__(16) __half qs[128 * 56];
    __shared__ __align__(16) __half ks_[128 * 56];
    __shared__ float gsm[HD * HD];
    int tid = threadIdx.x, wid = tid >> 5, lane = tid & 31;
    int g = lane >> 2, t = lane & 3;
    for (int i = tid; i < HD * HD; i += 256) gsm[i] = 0.f;

    float c[3][6][4];
    #pragma unroll
    for (int mi = 0; mi < 3; mi++)
        #pragma unroll
        for (int nt = 0; nt < 6; nt++)
            #pragma unroll
            for (int q = 0; q < 4; q++) c[mi][nt][q] = 0.f;

    for (int ch = 0; ch < 8; ch++) {
        __syncthreads();
        for (int e = tid; e < 768; e += 256) {
            int r = e / 6, s = e % 6;
            size_t goff = (size_t)(nbase + ch * 128 + r) * C3 + s * 8;
            cpa16u(smem_u32(qs  + r * 56 + s * 8), qp + goff);
            cpa16u(smem_u32(ks_ + r * 56 + s * 8), kp + goff);
        }
        CP_COMMIT(); CP_WAIT0();
        __syncthreads();

        int nrow = wid * 16;
        uint32_t a[3][4], bb[6][2];
        #pragma unroll
        for (int mi = 0; mi < 3; mi++) {
            int row = nrow + (lane & 7) + ((lane >> 4) << 3);
            int col = mi * 16 + ((lane >> 3) & 1) * 8;
            ldsm4t(a[mi], smem_u32(qs) + (row * 56 + col) * 2);
        }
        #pragma unroll
        for (int p = 0; p < 3; p++) {
            int row = nrow + (lane & 7) + ((lane >> 3) & 1) * 8;
            int col = p * 16 + (lane >> 4) * 8;
            uint32_t r[4];
            ldsm4t(r, smem_u32(ks_) + (row * 56 + col) * 2);
            bb[2*p][0] = r[0]; bb[2*p][1] = r[1];
            bb[2*p+1][0] = r[2]; bb[2*p+1][1] = r[3];
        }
        #pragma unroll
        for (int mi = 0; mi < 3; mi++)
            #pragma unroll
            for (int nt = 0; nt < 6; nt++)
                mma_f16(c[mi][nt], a[mi][0], a[mi][1], a[mi][2], a[mi][3],
                        bb[nt][0], bb[nt][1]);
    }

    #pragma unroll
    for (int mi = 0; mi < 3; mi++)
        #pragma unroll
        for (int nt = 0; nt < 6; nt++)
            #pragma unroll
            for (int q = 0; q < 4; q++) {
                int i = mi * 16 + g + ((q & 2) ? 8 : 0);
                int j = nt * 8 + 2 * t + (q & 1);
                atomicAdd(&gsm[i * HD + j], c[mi][nt][q]);
            }
    __syncthreads();
    for (int i = tid; i < HD * HD; i += 256)
        atomicAdd(&g_gram[(size_t)bh * HD * HD + i], gsm[i]);
}

__global__ void softmax_kernel(const float* __restrict__ temp) {
    int gi = blockIdx.x;
    int i = gi % HD; int bh = gi / HD;
    int b = bh >> 3, h = bh & 7;
    int tid = threadIdx.x;
    float qi = rsqrtf(fmaxf(g_sumsq[b * 2 * Cc + h * HD + i], 1e-24f));
    float v = -3.4e38f;
    if (tid < HD) {
        float kj = rsqrtf(fmaxf(g_sumsq[b * 2 * Cc + Cc + h * HD + tid], 1e-24f));
        v = g_gram[(size_t)bh * HD * HD + i * HD + tid] * qi * kj * temp[h];
    }
    __shared__ float red[64];
    red[tid] = v; __syncthreads();
    for (int st = 32; st > 0; st >>= 1) {
        if (tid < st) red[tid] = fmaxf(red[tid], red[tid + st]);
        __syncthreads();
    }
    float m = red[0]; __syncthreads();
    float e = (tid < HD) ? expf(v - m) : 0.f;
    red[tid] = e; __syncthreads();
    for (int st = 32; st > 0; st >>= 1) {
        if (tid < st) red[tid] += red[tid + st];
        __syncthreads();
    }
    if (tid < HD) g_attn[(size_t)bh * HD * HD + i * HD + tid] = e / red[0];
}

__global__ __launch_bounds__(128) void attnv_kernel() {
    int bh = blockIdx.y; int b = bh >> 3, h = bh & 7;
    int n = blockIdx.x * 128 + threadIdx.x;
    __shared__ float sa[HD * HD];
    for (int e = threadIdx.x; e < HD * HD; e += 128)
        sa[e] = g_attn[(size_t)bh * HD * HD + e];
    __syncthreads();
    const __half* vp = g_qkvh + (size_t)(b * NN + n) * C3 + 2 * Cc + h * HD;
    float vr[HD];
    #pragma unroll
    for (int j6 = 0; j6 < 6; j6++) {
        uint4 u = ((const uint4*)vp)[j6];
        const __half2* hp = (const __half2*)&u;
        #pragma unroll
        for (int q = 0; q < 4; q++) {
            float2 f = __half22float2(hp[q]);
            vr[j6 * 8 + q * 2] = f.x; vr[j6 * 8 + q * 2 + 1] = f.y;
        }
    }
    __half* oph = g_ath + (size_t)(b * NN + n) * Cc + h * HD;
    #pragma unroll
    for (int i0 = 0; i0 < HD; i0 += 8) {
        float res[8];
        #pragma unroll
        for (int i = 0; i < 8; i++) {
            float s = 0.f;
            #pragma unroll
            for (int j = 0; j < HD; j++) s += sa[(i0 + i) * HD + j] * vr[j];
            res[i] = s;
        }
        __half2 hres[4];
        #pragma unroll
        for (int q = 0; q < 4; q++)
            hres[q] = __floats2half2_rn(res[q*2], res[q*2+1]);
        *(uint4*)(oph + i0) = *(uint4*)hres;
    }
}

// fp16-in fp16-out depthwise conv (NHWC, C % 4 == 0), fp32 accumulate
__global__ void dwconv4h(const __half* __restrict__ in, const float* __restrict__ w,
                         const float* __restrict__ bias, __half* __restrict__ out,
                         int C, int ks, int pad, int dil)
{
    int idx = blockIdx.x * 256 + threadIdx.x;
    int C4 = C >> 2;
    int c4 = idx % C4; int rest = idx / C4;
    int xx = rest & 63, yy = (rest >> 6) & 63, b = rest >> 12;
    int c = c4 << 2;
    const __half* ip = in + (size_t)(b * NN) * C + c;
    float4 bv = *(const float4*)(bias + c);
    float a0 = bv.x, a1 = bv.y, a2 = bv.z, a3 = bv.w;
    const float* wp = w + c * ks * ks;
    const int K2 = ks * ks;
    for (int ky = 0; ky < ks; ky++) {
        int y = yy - pad + ky * dil;
        if ((unsigned)y >= 64u) continue;
        for (int kx = 0; kx < ks; kx++) {
            int x = xx - pad + kx * dil;
            if ((unsigned)x >= 64u) continue;
            uint2 u = *(const uint2*)(ip + (size_t)(y * 64 + x) * C);
            const __half2* hp = (const __half2*)&u;
            float2 f0 = __half22float2(hp[0]), f1 = __half22float2(hp[1]);
            int t = ky * ks + kx;
            a0 += f0.x * wp[t];
            a1 += f0.y * wp[t + K2];
            a2 += f1.x * wp[t + 2 * K2];
            a3 += f1.y * wp[t + 3 * K2];
        }
    }
    __half2 hh[2] = {__floats2half2_rn(a0, a1), __floats2half2_rn(a2, a3)};
    *(uint2*)(out + (size_t)(b * NN + yy * 64 + xx) * C + c) = *(uint2*)hh;
}

// fused sp_dw (3x3 depthwise over C2c, fp16 in) + gelu gate -> gated (stride 128)
__global__ void spdw_gelu(const __half* __restrict__ sp, const float* __restrict__ w,
                          const float* __restrict__ bias, __half* __restrict__ out)
{
    int idx = blockIdx.x * 256 + threadIdx.x;
    int c4 = idx % 24; int rest = idx / 24;
    int xx = rest & 63, yy = (rest >> 6) & 63, b = rest >> 12;
    int c = c4 << 2;
    const __half* ip = sp + (size_t)(b * NN) * C2c;
    float4 bv1 = *(const float4*)(bias + c);
    float4 bv2 = *(const float4*)(bias + c + C4c);
    float a1[4] = {bv1.x, bv1.y, bv1.z, bv1.w};
    float a2[4] = {bv2.x, bv2.y, bv2.z, bv2.w};
    const float* w1 = w + c * 9;
    const float* w2 = w + (c + C4c) * 9;
    #pragma unroll
    for (int ky = 0; ky < 3; ky++) {
        int y = yy - 1 + ky;
        if ((unsigned)y >= 64u) continue;
        #pragma unroll
        for (int kx = 0; kx < 3; kx++) {
            int x = xx - 1 + kx;
            if ((unsigned)x >= 64u) continue;
            const __half* pv = ip + (size_t)(y * 64 + x) * C2c + c;
            uint2 u1v = *(const uint2*)pv;
            uint2 u2v = *(const uint2*)(pv + C4c);
            const __half2* h1 = (const __half2*)&u1v;
            const __half2* h2 = (const __half2*)&u2v;
            float2 f10 = __half22float2(h1[0]), f11 = __half22float2(h1[1]);
            float2 f20 = __half22float2(h2[0]), f21 = __half22float2(h2[1]);
            int t = ky * 3 + kx;
            a1[0] += f10.x * w1[t];      a1[1] += f10.y * w1[t + 9];
            a1[2] += f11.x * w1[t + 18]; a1[3] += f11.y * w1[t + 27];
            a2[0] += f20.x * w2[t];      a2[1] += f20.y * w2[t + 9];
            a2[2] += f21.x * w2[t + 18]; a2[3] += f21.y * w2[t + 27];
        }
    }
    float o[4];
    #pragma unroll
    for (int q = 0; q < 4; q++) {
        float gg = 0.5f * a1[q] * (1.f + erff(a1[q] * 0.70710678118654752f));
        o[q] = gg * a2[q];
    }
    __half2 hh[2] = {__floats2half2_rn(o[0], o[1]), __floats2half2_rn(o[2], o[3])};
    *(uint2*)(out + (size_t)(b * NN + yy * 64 + xx) * 128 + c) = *(uint2*)hh;
}

__global__ void tmean_kernel() {
    int b = blockIdx.y, n0 = blockIdx.x * 128, c = threadIdx.x;
    const __half* p = g_tth + (size_t)b * NN * C6c + c;
    float s = 0.f;
    for (int n = n0; n < n0 + 128; n++) s += __half2float(p[(size_t)n * C6c]);
    atomicAdd(&g_tmean[b * C6c + c], s);
}

__global__ void ci1_kernel(const float* __restrict__ w, const float* __restrict__ bias) {
    int b = blockIdx.x, co = threadIdx.x;
    __shared__ float tm[C6c];
    tm[co] = g_tmean[b * C6c + co] * (1.f / NN);
    __syncthreads();
    float a = bias[co];
    #pragma unroll
    for (int ci = 0; ci < C6c; ci++) a += w[co * C6c + ci] * tm[ci];
    g_ci1v[b * C6c + co] = a;
}

__global__ void cm_kernel() {
    int b = blockIdx.y, n0 = blockIdx.x * 128, c = threadIdx.x;
    const __half* p = g_chmaph + (size_t)b * NN * Cc + c;
    float s = 0.f;
    for (int n = n0; n < n0 + 128; n++) s += __half2float(p[(size_t)n * Cc]);
    atomicAdd(&g_cm[b * Cc + c], s);
}

// ================================================================= launch ===
extern "C" void kernel_launch(void* const* d_in, const int* in_sizes, int n_in,
                              void* d_out, int out_size)
{
    const float* x           = (const float*)d_in[0];
    const float* temperature = (const float*)d_in[1];
    const float* qkv_w       = (const float*)d_in[2];
    const float* proj_w      = (const float*)d_in[3];
    const float* proj_b      = (const float*)d_in[4];
    const float* dw1_w       = (const float*)d_in[5];
    const float* dw1_b       = (const float*)d_in[6];
    const float* dw2_w       = (const float*)d_in[7];
    const float* dw2_b       = (const float*)d_in[8];
    const float* cp_in_w     = (const float*)d_in[9];
    const float* cp_in_b     = (const float*)d_in[10];
    const float* ci1_w       = (const float*)d_in[11];
    const float* ci1_b       = (const float*)d_in[12];
    const float* ci2a_w      = (const float*)d_in[13];
    const float* ci2a_b      = (const float*)d_in[14];
    const float* ci2b_w      = (const float*)d_in[15];
    const float* ci2b_b      = (const float*)d_in[16];
    const float* ci2c_w      = (const float*)d_in[17];
    const float* ci2c_b      = (const float*)d_in[18];
    const float* cp_out_w    = (const float*)d_in[19];
    const float* cp_out_b    = (const float*)d_in[20];
    const float* sp_in_w     = (const float*)d_in[21];
    const float* sp_in_b     = (const float*)d_in[22];
    const float* sp_dw_w     = (const float*)d_in[23];
    const float* sp_dw_b     = (const float*)d_in[24];
    const float* sp_out_w    = (const float*)d_in[25];
    const float* sp_out_b    = (const float*)d_in[26];
    float* out = (float*)d_out;

    __half *xh, *qkvh, *ath, *t1h, *convxh, *chmaph, *tth, *u1h, *u2h,
           *u3h, *sph, *gatedh, *yh, *wb;
    float *ssq, *ci1v, *cm;
    cudaGetSymbolAddress((void**)&xh,     g_xh);
    cudaGetSymbolAddress((void**)&qkvh,   g_qkvh);
    cudaGetSymbolAddress((void**)&ath,    g_ath);
    cudaGetSymbolAddress((void**)&t1h,    g_t1h);
    cudaGetSymbolAddress((void**)&convxh, g_convxh);
    cudaGetSymbolAddress((void**)&chmaph, g_chmaph);
    cudaGetSymbolAddress((void**)&tth,    g_tth);
    cudaGetSymbolAddress((void**)&u1h,    g_u1h);
    cudaGetSymbolAddress((void**)&u2h,    g_u2h);
    cudaGetSymbolAddress((void**)&u3h,    g_u3h);
    cudaGetSymbolAddress((void**)&sph,    g_sph);
    cudaGetSymbolAddress((void**)&gatedh, g_gatedh);
    cudaGetSymbolAddress((void**)&yh,     g_yh);
    cudaGetSymbolAddress((void**)&wb,     g_wbuf);
    cudaGetSymbolAddress((void**)&ssq,    g_sumsq);
    cudaGetSymbolAddress((void**)&ci1v,   g_ci1v);
    cudaGetSymbolAddress((void**)&cm,     g_cm);

    const long long bCN  = CN;
    const long long b3CN = (long long)NN * C3;
    const long long b64  = (long long)NN * C6c;
    const long long b192 = (long long)NN * C2c;
    const long long b128 = (long long)NN * 128;

    const int SM4 = (128 + 128) * RSH * 2 * 3;   // 110592 B
    const int SM3 = (128 + 96)  * RSH * 2 * 3;   // 96768 B
    const int SM2 = (128 + 64)  * RSH * 2 * 3;   // 82944 B
    cudaFuncSetAttribute(mma_gemm<4>, cudaFuncAttributeMaxDynamicSharedMemorySize, SM4);
    cudaFuncSetAttribute(mma_gemm<3>, cudaFuncAttributeMaxDynamicSharedMemorySize, SM3);
    cudaFuncSetAttribute(mma_gemm<2>, cudaFuncAttributeMaxDynamicSharedMemorySize, SM2);

    WList wl;
    for (int k = 0; k < 8; k++) { wl.padK[k] = 0; wl.srcK[k] = 0; }
    wl.s[0]=qkv_w;   wl.n[0]=3*Cc*Cc;  wl.off[0]=W_QKV;
    wl.s[1]=dw1_w;   wl.n[1]=Cc*Cc;    wl.off[1]=W_DW1;
    wl.s[2]=cp_in_w; wl.n[2]=C6c*Cc;   wl.off[2]=W_CPIN;
    wl.s[3]=ci2c_w;  wl.n[3]=C6c*C6c;  wl.off[3]=W_CI2C;
    wl.s[4]=cp_out_w;wl.n[4]=Cc*C6c;   wl.off[4]=W_CPOUT;
    wl.s[5]=sp_in_w; wl.n[5]=C2c*Cc;   wl.off[5]=W_SPIN;
    wl.s[6]=sp_out_w;wl.n[6]=Cc*128;   wl.off[6]=W_SPOUT; wl.padK[6]=128; wl.srcK[6]=96;
    wl.s[7]=proj_w;  wl.n[7]=Cc*Cc;    wl.off[7]=W_PROJ;

    zero_kernel<<<576, 256>>>();
    f2h_kernel<<<1728, 256>>>(wl);
    transpose_kernel<<<dim3(128, 12, Bb), dim3(32, 8)>>>(x);

    // qkv (+ fused sumsq)
    mma_gemm<4><<<dim3(9, 32, Bb), 256, SM4>>>(xh, Cc, bCN, wb + W_QKV, Cc, 0,
        nullptr, 0, nullptr, nullptr, ssq, nullptr, nullptr, nullptr, nullptr,
        nullptr, qkvh, C3, b3CN, Cc);
    gram_kernel<<<dim3(4, Bb * HEADS), 256>>>();
    softmax_kernel<<<Bb * HEADS * HD, 64>>>(temperature);
    attnv_kernel<<<dim3(NN / 128, Bb * HEADS), 128>>>();

    // dw1 on v -> t1h, depthwise 3x3 -> convxh
    mma_gemm<4><<<dim3(3, 32, Bb), 256, SM4>>>(qkvh + 2 * Cc, C3, b3CN, wb + W_DW1, Cc, 0,
        dw1_b, 0, nullptr, nullptr, nullptr, nullptr, nullptr, nullptr, nullptr,
        nullptr, t1h, Cc, bCN, Cc);
    dwconv4h<<<(Bb * NN * Cc / 4) / 256, 256>>>(t1h, dw2_w, dw2_b, convxh, Cc, 3, 1, 1);

    // channel projection
    mma_gemm<2><<<dim3(1, 32, Bb), 256, SM2>>>(ath, Cc, bCN, wb + W_CPIN, Cc, 0,
        cp_in_b, 0, nullptr, nullptr, nullptr, nullptr, nullptr, nullptr, nullptr,
        nullptr, tth, C6c, b64, Cc);
    tmean_kernel<<<dim3(32, Bb), 64>>>();
    ci1_kernel<<<Bb, C6c>>>(ci1_w, ci1_b);
    dwconv4h<<<(Bb * NN * C6c / 4) / 256, 256>>>(tth, ci2a_w, ci2a_b, u1h, C6c, 3, 1, 1);
    dwconv4h<<<(Bb * NN * C6c / 4) / 256, 256>>>(u1h, ci2b_w, ci2b_b, u2h, C6c, 7, 9, 3);
    mma_gemm<2><<<dim3(1, 32, Bb), 256, SM2>>>(u2h, C6c, b64, wb + W_CI2C, C6c, 0,
        ci2c_b, 0, tth, ci1v, nullptr, nullptr, nullptr, nullptr, nullptr,
        nullptr, u3h, C6c, b64, C6c);
    mma_gemm<4><<<dim3(3, 32, Bb), 256, SM4>>>(u3h, C6c, b64, wb + W_CPOUT, C6c, 0,
        cp_out_b, 0, nullptr, nullptr, nullptr, nullptr, nullptr, nullptr, nullptr,
        nullptr, chmaph, Cc, bCN, C6c);
    cm_kernel<<<dim3(32, Bb), Cc>>>();

    // spatial projection
    mma_gemm<3><<<dim3(2, 32, Bb), 256, SM3>>>(convxh, Cc, bCN, wb + W_SPIN, Cc, 0,
        sp_in_b, 0, nullptr, nullptr, nullptr, nullptr, nullptr, nullptr, nullptr,
        nullptr, sph, C2c, b192, Cc);
    spdw_gelu<<<(Bb * NN * 24) / 256, 256>>>(sph, sp_dw_w, sp_dw_b, gatedh);
    // sp_out (K padded to 128) + fused combine -> yh
    mma_gemm<4><<<dim3(3, 32, Bb), 256, SM4>>>(gatedh, 128, b128, wb + W_SPOUT, 128, 0,
        sp_out_b, 0, nullptr, nullptr, nullptr, ath, chmaph, convxh, cm,
        nullptr, yh, Cc, bCN, 128);

    // final projection -> (B,C,N) fp32 output
    mma_gemm<4><<<dim3(32, 3, Bb), 256, SM4>>>(wb + W_PROJ, Cc, 0, yh, Cc, bCN,
        proj_b, 1, nullptr, nullptr, nullptr, nullptr, nullptr, nullptr, nullptr,
        out, nullptr, NN, bCN, Cc);
}

// round 12
// speedup vs baseline: 5.0092x; 1.0583x over previous
#include <cuda_runtime.h>
#include <cuda_fp16.h>
#include <cstdint>
#include <math.h>

#define Bb     8
#define Cc     384
#define NN     4096
#define HEADS  8
#define HD     48
#define CN     (Cc*NN)
#define C3     1152
#define C6c    64
#define C2c    192
#define C4c    96

// ---------------- scratch (all intermediates fp16; small stats fp32) ----------
__device__ __align__(16) __half g_xh    [Bb*NN*Cc];
__device__ __align__(16) __half g_qkvh  [(size_t)Bb*NN*C3];
__device__ __align__(16) __half g_ath   [Bb*NN*Cc];
__device__ __align__(16) __half g_t1h   [Bb*NN*Cc];
__device__ __align__(16) __half g_convxh[Bb*NN*Cc];
__device__ __align__(16) __half g_chmaph[Bb*NN*Cc];
__device__ __align__(16) __half g_tth   [Bb*NN*C6c];
__device__ __align__(16) __half g_u1h   [Bb*NN*C6c];
__device__ __align__(16) __half g_u2h   [Bb*NN*C6c];
__device__ __align__(16) __half g_u3h   [Bb*NN*C6c];
__device__ __align__(16) __half g_sph   [Bb*NN*C2c];
__device__ __align__(16) __half g_gatedh[Bb*NN*128];   // K padded 96 -> 128
__device__ __align__(16) __half g_yh    [Bb*NN*Cc];
__device__ __align__(16) __half g_wbuf  [917504];
__device__ float g_sumsq[Bb*2*Cc];
__device__ float g_gram [Bb*HEADS*HD*HD];
__device__ float g_attn [Bb*HEADS*HD*HD];
__device__ float g_tmean[Bb*C6c];
__device__ float g_ci1v [Bb*C6c];
__device__ float g_cm   [Bb*Cc];

#define W_QKV   0
#define W_DW1   442368
#define W_CPIN  589824
#define W_CI2C  614400
#define W_CPOUT 618496
#define W_SPIN  643072
#define W_SPOUT 716800      // padded: Cc rows x 128
#define W_PROJ  765952

__device__ __forceinline__ uint32_t smem_u32(const void* p) {
    uint32_t a;
    asm("{ .reg .u64 t; cvta.to.shared.u64 t, %1; cvt.u32.u64 %0, t; }" : "=r"(a) : "l"(p));
    return a;
}
__device__ __forceinline__ void cpa16u(uint32_t dst, const __half* src) {
    asm volatile("cp.async.cg.shared.global [%0], [%1], 16;"
                 :: "r"(dst), "l"(__cvta_generic_to_global(src)) : "memory");
}
#define CP_COMMIT() asm volatile("cp.async.commit_group;" ::: "memory")
#define CP_WAIT1()  asm volatile("cp.async.wait_group 1;" ::: "memory")
#define CP_WAIT0()  asm volatile("cp.async.wait_group 0;" ::: "memory")

__device__ __forceinline__ void ldsm4(uint32_t* r, uint32_t addr) {
    asm volatile("ldmatrix.sync.aligned.m8n8.x4.shared.b16 {%0,%1,%2,%3}, [%4];"
        : "=r"(r[0]), "=r"(r[1]), "=r"(r[2]), "=r"(r[3]) : "r"(addr));
}
__device__ __forceinline__ void ldsm4t(uint32_t* r, uint32_t addr) {
    asm volatile("ldmatrix.sync.aligned.m8n8.x4.trans.shared.b16 {%0,%1,%2,%3}, [%4];"
        : "=r"(r[0]), "=r"(r[1]), "=r"(r[2]), "=r"(r[3]) : "r"(addr));
}
__device__ __forceinline__ void ldsm2(uint32_t* r, uint32_t addr) {
    asm volatile("ldmatrix.sync.aligned.m8n8.x2.shared.b16 {%0,%1}, [%2];"
        : "=r"(r[0]), "=r"(r[1]) : "r"(addr));
}
__device__ __forceinline__ void mma_f16(float* d, uint32_t a0, uint32_t a1,
                                        uint32_t a2, uint32_t a3,
                                        uint32_t b0, uint32_t b1) {
    asm volatile(
        "mma.sync.aligned.m16n8k16.row.col.f32.f16.f16.f32 "
        "{%0,%1,%2,%3}, {%4,%5,%6,%7}, {%8,%9}, {%0,%1,%2,%3};"
        : "+f"(d[0]), "+f"(d[1]), "+f"(d[2]), "+f"(d[3])
        : "r"(a0), "r"(a1), "r"(a2), "r"(a3), "r"(b0), "r"(b1));
}
__device__ __forceinline__ float sigf(float v) { return 1.f / (1.f + expf(-v)); }

// ---------------- 3-stage pipelined fp16 ldmatrix GEMM, BK=64 -------------------
#define RSH 72       // halves per smem row (144B): conflict-free ldmatrix
template<int NI>
__global__ __launch_bounds__(256, 2)
void mma_gemm(const __half* __restrict__ A, int lda, long long abatch,
              const __half* __restrict__ B, int ldb, long long bbatch,
              const float* __restrict__ bias, int biasRowMode,
              const __half* __restrict__ emul, const float* __restrict__ escale,
              float* __restrict__ ssq,
              const __half* __restrict__ cAt, const __half* __restrict__ cCh,
              const __half* __restrict__ cCv, const float* __restrict__ cCm,
              float* __restrict__ Outf, __half* __restrict__ Outh,
              int ldo, long long obatch, int K)
{
    constexpr int n_tile = NI * 32;
    constexpr uint32_t STAGEB = (128 + n_tile) * RSH * 2;
    extern __shared__ __half sh[];
    const uint32_t smBase = smem_u32(sh);

    const int tid  = threadIdx.x;
    const int wid  = tid >> 5, lane = tid & 31;
    const int g    = lane >> 2, tig = lane & 3;
    const int z    = blockIdx.z;
    const int arow0 = blockIdx.y * 128;
    const int brow0 = blockIdx.x * n_tile;
    const int wm = (wid & 1) * 64;
    const int wn = (wid >> 1) * (NI * 8);

    const __half* Ab = A + (size_t)z * abatch + (size_t)arow0 * lda;
    const __half* Bp = B + (size_t)z * bbatch + (size_t)brow0 * ldb;

    const __half* aSrc[4];  uint32_t aDst[4];
    #pragma unroll
    for (int i = 0; i < 4; i++) {
        int e = tid + i * 256;
        aSrc[i] = Ab + (size_t)(e >> 3) * lda + (e & 7) * 8;
        aDst[i] = ((e >> 3) * RSH + (e & 7) * 8) * 2;
    }
    const __half* bSrc[NI]; uint32_t bDst[NI];
    #pragma unroll
    for (int i = 0; i < NI; i++) {
        int e = tid + i * 256;
        bSrc[i] = Bp + (size_t)(e >> 3) * ldb + (e & 7) * 8;
        bDst[i] = (128 * RSH + (e >> 3) * RSH + (e & 7) * 8) * 2;
    }

    uint32_t aOff[4];
    #pragma unroll
    for (int mi = 0; mi < 4; mi++)
        aOff[mi] = (((wm + mi * 16 + (lane & 15)) * RSH) + (lane >> 4) * 8) * 2;
    uint32_t bPairOff[(NI + 1) / 2];
    #pragma unroll
    for (int np = 0; np < NI / 2; np++)
        bPairOff[np] = ((128 + wn + np * 16 + ((lane >> 4) << 3) + (lane & 7)) * RSH +
                        ((lane >> 3) & 1) * 8) * 2;
    uint32_t bSoloOff = ((128 + wn + (NI - 1) * 8 + (lane & 7)) * RSH +
                         ((lane >> 3) & 1) * 8) * 2;

    float c[4][NI][4];
    #pragma unroll
    for (int mi = 0; mi < 4; mi++)
        #pragma unroll
        for (int ni = 0; ni < NI; ni++)
            #pragma unroll
            for (int q = 0; q < 4; q++) c[mi][ni][q] = 0.f;

    auto loadTiles = [&](int kc, uint32_t stBase) {
        const int koff = kc * 64;
        #pragma unroll
        for (int i = 0; i < 4; i++)
            cpa16u(stBase + aDst[i], aSrc[i] + koff);
        #pragma unroll
        for (int i = 0; i < NI; i++)
            cpa16u(stBase + bDst[i], bSrc[i] + koff);
        CP_COMMIT();
    };

    const int nch = K >> 6;
    loadTiles(0, smBase);
    if (nch > 1) loadTiles(1, smBase + STAGEB); else CP_COMMIT();

    uint32_t smC = smBase;
    uint32_t smL = smBase + 2 * STAGEB;
    for (int kc = 0; kc < nch; kc++) {
        CP_WAIT1();
        __syncthreads();
        if (kc + 2 < nch) loadTiles(kc + 2, smL); else CP_COMMIT();

        #pragma unroll
        for (int ks = 0; ks < 4; ks++) {
            const uint32_t kb = ks * 32;
            uint32_t a[4][4];
            #pragma unroll
            for (int mi = 0; mi < 4; mi++)
                ldsm4(a[mi], smC + aOff[mi] + kb);
            uint32_t b[NI][2];
            #pragma unroll
            for (int np = 0; np < NI / 2; np++) {
                uint32_t r[4]; ldsm4(r, smC + bPairOff[np] + kb);
                b[2*np][0] = r[0]; b[2*np][1] = r[1];
                b[2*np+1][0] = r[2]; b[2*np+1][1] = r[3];
            }
            if (NI & 1) ldsm2(b[NI-1], smC + bSoloOff + kb);
            #pragma unroll
            for (int ni = 0; ni < NI; ni++)
                #pragma unroll
                for (int mi = 0; mi < 4; mi++)
                    mma_f16(c[mi][ni], a[mi][0], a[mi][1], a[mi][2], a[mi][3],
                            b[ni][0], b[ni][1]);
        }
        smC = (smC == smBase + 2 * STAGEB) ? smBase : smC + STAGEB;
        smL = (smL == smBase + 2 * STAGEB) ? smBase : smL + STAGEB;
    }

    if (ssq) {
        #pragma unroll
        for (int ni = 0; ni < NI; ni++) {
            int col = brow0 + wn + ni * 8 + tig * 2;
            if (col < 2 * Cc) {
                float s0 = 0.f, s1 = 0.f;
                #pragma unroll
                for (int mi = 0; mi < 4; mi++) {
                    s0 += c[mi][ni][0] * c[mi][ni][0] + c[mi][ni][2] * c[mi][ni][2];
                    s1 += c[mi][ni][1] * c[mi][ni][1] + c[mi][ni][3] * c[mi][ni][3];
                }
                s0 += __shfl_xor_sync(0xffffffffu, s0, 4);
                s1 += __shfl_xor_sync(0xffffffffu, s1, 4);
                s0 += __shfl_xor_sync(0xffffffffu, s0, 8);
                s1 += __shfl_xor_sync(0xffffffffu, s1, 8);
                s0 += __shfl_xor_sync(0xffffffffu, s0, 16);
                s1 += __shfl_xor_sync(0xffffffffu, s1, 16);
                if (g == 0) {
                    atomicAdd(&ssq[z * 2 * Cc + col], s0);
                    atomicAdd(&ssq[z * 2 * Cc + col + 1], s1);
                }
            }
        }
    }

    #pragma unroll
    for (int mi = 0; mi < 4; mi++) {
        const int row = arow0 + wm + mi * 16 + g;
        float bv0 = 0.f, bv1 = 0.f;
        if (bias && biasRowMode) { bv0 = bias[row]; bv1 = bias[row + 8]; }
        #pragma unroll
        for (int ni = 0; ni < NI; ni++) {
            const int col = brow0 + wn + ni * 8 + tig * 2;
            float bc0 = 0.f, bc1 = 0.f;
            if (bias && !biasRowMode) { bc0 = bias[col]; bc1 = bias[col + 1]; }
            size_t o0 = (size_t)z * obatch + (size_t)row * ldo + col;
            size_t o1 = o0 + 8 * (size_t)ldo;
            float v00 = c[mi][ni][0] + bv0 + bc0, v01 = c[mi][ni][1] + bv0 + bc1;
            float v10 = c[mi][ni][2] + bv1 + bc0, v11 = c[mi][ni][3] + bv1 + bc1;
            if (emul) {
                float2 m0 = __half22float2(*(const __half2*)(emul + o0));
                float2 m1 = __half22float2(*(const __half2*)(emul + o1));
                float s0 = escale[z * C6c + col], s1 = escale[z * C6c + col + 1];
                v00 *= m0.x * s0; v01 *= m0.y * s1;
                v10 *= m1.x * s0; v11 *= m1.y * s1;
            }
            if (cAt) {
                float sc0 = sigf(cCm[z * Cc + col] * (1.f / NN));
                float sc1 = sigf(cCm[z * Cc + col + 1] * (1.f / NN));
                float2 a0 = __half22float2(*(const __half2*)(cAt + o0));
                float2 a1 = __half22float2(*(const __half2*)(cAt + o1));
                float2 h0 = __half22float2(*(const __half2*)(cCh + o0));
                float2 h1 = __half22float2(*(const __half2*)(cCh + o1));
                float2 w0 = __half22float2(*(const __half2*)(cCv + o0));
                float2 w1 = __half22float2(*(const __half2*)(cCv + o1));
                v00 = (a0.x + h0.x) * sigf(v00) + w0.x * sc0;
                v01 = (a0.y + h0.y) * sigf(v01) + w0.y * sc1;
                v10 = (a1.x + h1.x) * sigf(v10) + w1.x * sc0;
                v11 = (a1.y + h1.y) * sigf(v11) + w1.y * sc1;
            }
            if (Outh) {
                *(__half2*)(Outh + o0) = __floats2half2_rn(v00, v01);
                *(__half2*)(Outh + o1) = __floats2half2_rn(v10, v11);
            } else {
                *(float2*)(Outf + o0) = make_float2(v00, v01);
                *(float2*)(Outf + o1) = make_float2(v10, v11);
            }
        }
    }
}

// ---------------- weight fp32 -> fp16 (entry may be K-padded) -------------------
struct WList { const float* s[8]; int n[8]; int off[8]; int padK[8]; int srcK[8]; };
__global__ void f2h_kernel(WList wl) {
    int idx = blockIdx.x * 256 + threadIdx.x;
    #pragma unroll
    for (int k = 0; k < 8; k++) {
        if (idx < wl.n[k]) {
            float v;
            if (wl.padK[k]) {
                int r = idx / wl.padK[k], kk = idx % wl.padK[k];
                v = (kk < wl.srcK[k]) ? wl.s[k][r * wl.srcK[k] + kk] : 0.f;
            } else v = wl.s[k][idx];
            g_wbuf[wl.off[k] + idx] = __float2half(v);
        }
    }
}

__global__ void zero_kernel() {
    int i = blockIdx.x * 256 + threadIdx.x;
    if (i < Bb*2*Cc)          g_sumsq[i] = 0.f;
    if (i < Bb*HEADS*HD*HD)   g_gram[i]  = 0.f;
    if (i < Bb*C6c)           g_tmean[i] = 0.f;
    if (i < Bb*Cc)            g_cm[i]    = 0.f;
    if (i < Bb*NN*4) {
        int row = i >> 2, seg = i & 3;
        *(uint4*)(g_gatedh + (size_t)row * 128 + 96 + seg * 8) = make_uint4(0,0,0,0);
    }
}

__global__ void transpose_kernel(const float* __restrict__ in) {
    __shared__ float t[32][33];
    int b = blockIdx.z, c0 = blockIdx.y * 32, n0 = blockIdx.x * 32;
    int tx = threadIdx.x, ty = threadIdx.y;
    for (int i = ty; i < 32; i += 8)
        t[i][tx] = in[(size_t)b * CN + (size_t)(c0 + i) * NN + n0 + tx];
    __syncthreads();
    for (int i = ty; i < 32; i += 8)
        g_xh[(size_t)b * CN + (size_t)(n0 + i) * Cc + c0 + tx] = __float2half(t[tx][i]);
}

// ---------------- MMA gram ------------------------------------------------------
__global__ __launch_bounds__(256) void gram_kernel() {
    int bh = blockIdx.y; int b = bh >> 3, h = bh & 7;
    int nbase = blockIdx.x * 1024;
    const __half* qp = g_qkvh + (size_t)b * NN * C3 + h * HD;
    const __half* kp = qp + Cc;
    __shared__ __align__(16) __half qs[128 * 56];
    __shared__ __align__(16) __half ks_[128 * 56];
    __shared__ float gsm[HD * HD];
    int tid = threadIdx.x, wid = tid >> 5, lane = tid & 31;
    int g = lane >> 2, t = lane & 3;
    for (int i = tid; i < HD * HD; i += 256) gsm[i] = 0.f;

    float c[3][6][4];
    #pragma unroll
    for (int mi = 0; mi < 3; mi++)
        #pragma unroll
        for (int nt = 0; nt < 6; nt++)
            #pragma unroll
            for (int q = 0; q < 4; q++) c[mi][nt][q] = 0.f;

    for (int ch = 0; ch < 8; ch++) {
        __syncthreads();
        for (int e = tid; e < 768; e += 256) {
            int r = e / 6, s = e % 6;
            size_t goff = (size_t)(nbase + ch * 128 + r) * C3 + s * 8;
            cpa16u(smem_u32(qs  + r * 56 + s * 8), qp + goff);
            cpa16u(smem_u32(ks_ + r * 56 + s * 8), kp + goff);
        }
        CP_COMMIT(); CP_WAIT0();
        __syncthreads();

        int nrow = wid * 16;
        uint32_t a[3][4], bb[6][2];
        #pragma unroll
        for (int mi = 0; mi < 3; mi++) {
            int row = nrow + (lane & 7) + ((lane >> 4) << 3);
            int col = mi * 16 + ((lane >> 3) & 1) * 8;
            ldsm4t(a[mi], smem_u32(qs) + (row * 56 + col) * 2);
        }
        #pragma unroll
        for (int p = 0; p < 3; p++) {
            int row = nrow + (lane & 7) + ((lane >> 3) & 1) * 8;
            int col = p * 16 + (lane >> 4) * 8;
            uint32_t r[4];
            ldsm4t(r, smem_u32(ks_) + (row * 56 + col) * 2);
            bb[2*p][0] = r[0]; bb[2*p][1] = r[1];
            bb[2*p+1][0] = r[2]; bb[2*p+1][1] = r[3];
        }
        #pragma unroll
        for (int mi = 0; mi < 3; mi++)
            #pragma unroll
            for (int nt = 0; nt < 6; nt++)
                mma_f16(c[mi][nt], a[mi][0], a[mi][1], a[mi][2], a[mi][3],
                        bb[nt][0], bb[nt][1]);
    }

    #pragma unroll
    for (int mi = 0; mi < 3; mi++)
        #pragma unroll
        for (int nt = 0; nt < 6; nt++)
            #pragma unroll
            for (int q = 0; q < 4; q++) {
                int i = mi * 16 + g + ((q & 2) ? 8 : 0);
                int j = nt * 8 + 2 * t + (q & 1);
                atomicAdd(&gsm[i * HD + j], c[mi][nt][q]);
            }
    __syncthreads();
    for (int i = tid; i < HD * HD; i += 256)
        atomicAdd(&g_gram[(size_t)bh * HD * HD + i], gsm[i]);
}

__global__ void softmax_kernel(const float* __restrict__ temp) {
    int gi = blockIdx.x;
    int i = gi % HD; int bh = gi / HD;
    int b = bh >> 3, h = bh & 7;
    int tid = threadIdx.x;
    float qi = rsqrtf(fmaxf(g_sumsq[b * 2 * Cc + h * HD + i], 1e-24f));
    float v = -3.4e38f;
    if (tid < HD) {
        float kj = rsqrtf(fmaxf(g_sumsq[b * 2 * Cc + Cc + h * HD + tid], 1e-24f));
        v = g_gram[(size_t)bh * HD * HD + i * HD + tid] * qi * kj * temp[h];
    }
    __shared__ float red[64];
    red[tid] = v; __syncthreads();
    for (int st = 32; st > 0; st >>= 1) {
        if (tid < st) red[tid] = fmaxf(red[tid], red[tid + st]);
        __syncthreads();
    }
    float m = red[0]; __syncthreads();
    float e = (tid < HD) ? expf(v - m) : 0.f;
    red[tid] = e; __syncthreads();
    for (int st = 32; st > 0; st >>= 1) {
        if (tid < st) red[tid] += red[tid + st];
        __syncthreads();
    }
    if (tid < HD) g_attn[(size_t)bh * HD * HD + i * HD + tid] = e / red[0];
}

__global__ __launch_bounds__(128) void attnv_kernel() {
    int bh = blockIdx.y; int b = bh >> 3, h = bh & 7;
    int n = blockIdx.x * 128 + threadIdx.x;
    __shared__ float sa[HD * HD];
    for (int e = threadIdx.x; e < HD * HD; e += 128)
        sa[e] = g_attn[(size_t)bh * HD * HD + e];
    __syncthreads();
    const __half* vp = g_qkvh + (size_t)(b * NN + n) * C3 + 2 * Cc + h * HD;
    float vr[HD];
    #pragma unroll
    for (int j6 = 0; j6 < 6; j6++) {
        uint4 u = ((const uint4*)vp)[j6];
        const __half2* hp = (const __half2*)&u;
        #pragma unroll
        for (int q = 0; q < 4; q++) {
            float2 f = __half22float2(hp[q]);
            vr[j6 * 8 + q * 2] = f.x; vr[j6 * 8 + q * 2 + 1] = f.y;
        }
    }
    __half* oph = g_ath + (size_t)(b * NN + n) * Cc + h * HD;
    #pragma unroll
    for (int i0 = 0; i0 < HD; i0 += 8) {
        float res[8];
        #pragma unroll
        for (int i = 0; i < 8; i++) {
            float s = 0.f;
            #pragma unroll
            for (int j = 0; j < HD; j++) s += sa[(i0 + i) * HD + j] * vr[j];
            res[i] = s;
        }
        __half2 hres[4];
        #pragma unroll
        for (int q = 0; q < 4; q++)
            hres[q] = __floats2half2_rn(res[q*2], res[q*2+1]);
        *(uint4*)(oph + i0) = *(uint4*)hres;
    }
}

// fp16-in fp16-out depthwise conv (NHWC, C % 4 == 0), fp32 accumulate
__global__ void dwconv4h(const __half* __restrict__ in, const float* __restrict__ w,
                         const float* __restrict__ bias, __half* __restrict__ out,
                         int C, int ks, int pad, int dil)
{
    int idx = blockIdx.x * 256 + threadIdx.x;
    int C4 = C >> 2;
    int c4 = idx % C4; int rest = idx / C4;
    int xx = rest & 63, yy = (rest >> 6) & 63, b = rest >> 12;
    int c = c4 << 2;
    const __half* ip = in + (size_t)(b * NN) * C + c;
    float4 bv = *(const float4*)(bias + c);
    float a0 = bv.x, a1 = bv.y, a2 = bv.z, a3 = bv.w;
    const float* wp = w + c * ks * ks;
    const int K2 = ks * ks;
    for (int ky = 0; ky < ks; ky++) {
        int y = yy - pad + ky * dil;
        if ((unsigned)y >= 64u) continue;
        for (int kx = 0; kx < ks; kx++) {
            int x = xx - pad + kx * dil;
            if ((unsigned)x >= 64u) continue;
            uint2 u = *(const uint2*)(ip + (size_t)(y * 64 + x) * C);
            const __half2* hp = (const __half2*)&u;
            float2 f0 = __half22float2(hp[0]), f1 = __half22float2(hp[1]);
            int t = ky * ks + kx;
            a0 += f0.x * wp[t];
            a1 += f0.y * wp[t + K2];
            a2 += f1.x * wp[t + 2 * K2];
            a3 += f1.y * wp[t + 3 * K2];
        }
    }
    __half2 hh[2] = {__floats2half2_rn(a0, a1), __floats2half2_rn(a2, a3)};
    *(uint2*)(out + (size_t)(b * NN + yy * 64 + xx) * C + c) = *(uint2*)hh;
}

// fused sp_dw (3x3 depthwise over C2c, fp16 in) + gelu gate -> gated (stride 128)
__global__ void spdw_gelu(const __half* __restrict__ sp, const float* __restrict__ w,
                          const float* __restrict__ bias, __half* __restrict__ out)
{
    int idx = blockIdx.x * 256 + threadIdx.x;
    int c4 = idx % 24; int rest = idx / 24;
    int xx = rest & 63, yy = (rest >> 6) & 63, b = rest >> 12;
    int c = c4 << 2;
    const __half* ip = sp + (size_t)(b * NN) * C2c;
    float4 bv1 = *(const float4*)(bias + c);
    float4 bv2 = *(const float4*)(bias + c + C4c);
    float a1[4] = {bv1.x, bv1.y, bv1.z, bv1.w};
    float a2[4] = {bv2.x, bv2.y, bv2.z, bv2.w};
    const float* w1 = w + c * 9;
    const float* w2 = w + (c + C4c) * 9;
    #pragma unroll
    for (int ky = 0; ky < 3; ky++) {
        int y = yy - 1 + ky;
        if ((unsigned)y >= 64u) continue;
        #pragma unroll
        for (int kx = 0; kx < 3; kx++) {
            int x = xx - 1 + kx;
            if ((unsigned)x >= 64u) continue;
            const __half* pv = ip + (size_t)(y * 64 + x) * C2c + c;
            uint2 u1v = *(const uint2*)pv;
            uint2 u2v = *(const uint2*)(pv + C4c);
            const __half2* h1 = (const __half2*)&u1v;
            const __half2* h2 = (const __half2*)&u2v;
            float2 f10 = __half22float2(h1[0]), f11 = __half22float2(h1[1]);
            float2 f20 = __half22float2(h2[0]), f21 = __half22float2(h2[1]);
            int t = ky * 3 + kx;
            a1[0] += f10.x * w1[t];      a1[1] += f10.y * w1[t + 9];
            a1[2] += f11.x * w1[t + 18]; a1[3] += f11.y * w1[t + 27];
            a2[0] += f20.x * w2[t];      a2[1] += f20.y * w2[t + 9];
            a2[2] += f21.x * w2[t + 18]; a2[3] += f21.y * w2[t + 27];
        }
    }
    float o[4];
    #pragma unroll
    for (int q = 0; q < 4; q++) {
        float gg = 0.5f * a1[q] * (1.f + erff(a1[q] * 0.70710678118654752f));
        o[q] = gg * a2[q];
    }
    __half2 hh[2] = {__floats2half2_rn(o[0], o[1]), __floats2half2_rn(o[2], o[3])};
    *(uint2*)(out + (size_t)(b * NN + yy * 64 + xx) * 128 + c) = *(uint2*)hh;
}

__global__ void tmean_kernel() {
    int b = blockIdx.y, n0 = blockIdx.x * 128, c = threadIdx.x;
    const __half* p = g_tth + (size_t)b * NN * C6c + c;
    float s = 0.f;
    for (int n = n0; n < n0 + 128; n++) s += __half2float(p[(size_t)n * C6c]);
    atomicAdd(&g_tmean[b * C6c + c], s);
}

__global__ void ci1_kernel(const float* __restrict__ w, const float* __restrict__ bias) {
    int b = blockIdx.x, co = threadIdx.x;
    __shared__ float tm[C6c];
    tm[co] = g_tmean[b * C6c + co] * (1.f / NN);
    __syncthreads();
    float a = bias[co];
    #pragma unroll
    for (int ci = 0; ci < C6c; ci++) a += w[co * C6c + ci] * tm[ci];
    g_ci1v[b * C6c + co] = a;
}

__global__ void cm_kernel() {
    int b = blockIdx.y, n0 = blockIdx.x * 128, c = threadIdx.x;
    const __half* p = g_chmaph + (size_t)b * NN * Cc + c;
    float s = 0.f;
    for (int n = n0; n < n0 + 128; n++) s += __half2float(p[(size_t)n * Cc]);
    atomicAdd(&g_cm[b * Cc + c], s);
}

// ================================================================= launch ===
extern "C" void kernel_launch(void* const* d_in, const int* in_sizes, int n_in,
                              void* d_out, int out_size)
{
    const float* x           = (const float*)d_in[0];
    const float* temperature = (const float*)d_in[1];
    const float* qkv_w       = (const float*)d_in[2];
    const float* proj_w      = (const float*)d_in[3];
    const float* proj_b      = (const float*)d_in[4];
    const float* dw1_w       = (const float*)d_in[5];
    const float* dw1_b       = (const float*)d_in[6];
    const float* dw2_w       = (const float*)d_in[7];
    const float* dw2_b       = (const float*)d_in[8];
    const float* cp_in_w     = (const float*)d_in[9];
    const float* cp_in_b     = (const float*)d_in[10];
    const float* ci1_w       = (const float*)d_in[11];
    const float* ci1_b       = (const float*)d_in[12];
    const float* ci2a_w      = (const float*)d_in[13];
    const float* ci2a_b      = (const float*)d_in[14];
    const float* ci2b_w      = (const float*)d_in[15];
    const float* ci2b_b      = (const float*)d_in[16];
    const float* ci2c_w      = (const float*)d_in[17];
    const float* ci2c_b      = (const float*)d_in[18];
    const float* cp_out_w    = (const float*)d_in[19];
    const float* cp_out_b    = (const float*)d_in[20];
    const float* sp_in_w     = (const float*)d_in[21];
    const float* sp_in_b     = (const float*)d_in[22];
    const float* sp_dw_w     = (const float*)d_in[23];
    const float* sp_dw_b     = (const float*)d_in[24];
    const float* sp_out_w    = (const float*)d_in[25];
    const float* sp_out_b    = (const float*)d_in[26];
    float* out = (float*)d_out;

    __half *xh, *qkvh, *ath, *t1h, *convxh, *chmaph, *tth, *u1h, *u2h,
           *u3h, *sph, *gatedh, *yh, *wb;
    float *ssq, *ci1v, *cm;
    cudaGetSymbolAddress((void**)&xh,     g_xh);
    cudaGetSymbolAddress((void**)&qkvh,   g_qkvh);
    cudaGetSymbolAddress((void**)&ath,    g_ath);
    cudaGetSymbolAddress((void**)&t1h,    g_t1h);
    cudaGetSymbolAddress((void**)&convxh, g_convxh);
    cudaGetSymbolAddress((void**)&chmaph, g_chmaph);
    cudaGetSymbolAddress((void**)&tth,    g_tth);
    cudaGetSymbolAddress((void**)&u1h,    g_u1h);
    cudaGetSymbolAddress((void**)&u2h,    g_u2h);
    cudaGetSymbolAddress((void**)&u3h,    g_u3h);
    cudaGetSymbolAddress((void**)&sph,    g_sph);
    cudaGetSymbolAddress((void**)&gatedh, g_gatedh);
    cudaGetSymbolAddress((void**)&yh,     g_yh);
    cudaGetSymbolAddress((void**)&wb,     g_wbuf);
    cudaGetSymbolAddress((void**)&ssq,    g_sumsq);
    cudaGetSymbolAddress((void**)&ci1v,   g_ci1v);
    cudaGetSymbolAddress((void**)&cm,     g_cm);

    const long long bCN  = CN;
    const long long b3CN = (long long)NN * C3;
    const long long b64  = (long long)NN * C6c;
    const long long b192 = (long long)NN * C2c;
    const long long b128 = (long long)NN * 128;

    const int SM4 = (128 + 128) * RSH * 2 * 3;   // 110592 B
    const int SM3 = (128 + 96)  * RSH * 2 * 3;   // 96768 B
    const int SM2 = (128 + 64)  * RSH * 2 * 3;   // 82944 B

    // one-time handles (created on the uncaptured correctness call)
    static bool inited = false;
    static cudaStream_t sB;
    static cudaEvent_t evStart, evPro, evQ, evB;
    if (!inited) {
        cudaStreamCreateWithFlags(&sB, cudaStreamNonBlocking);
        cudaEventCreateWithFlags(&evStart, cudaEventDisableTiming);
        cudaEventCreateWithFlags(&evPro,   cudaEventDisableTiming);
        cudaEventCreateWithFlags(&evQ,     cudaEventDisableTiming);
        cudaEventCreateWithFlags(&evB,     cudaEventDisableTiming);
        cudaFuncSetAttribute(mma_gemm<4>, cudaFuncAttributeMaxDynamicSharedMemorySize, SM4);
        cudaFuncSetAttribute(mma_gemm<3>, cudaFuncAttributeMaxDynamicSharedMemorySize, SM3);
        cudaFuncSetAttribute(mma_gemm<2>, cudaFuncAttributeMaxDynamicSharedMemorySize, SM2);
        inited = true;
    }

    WList wl;
    for (int k = 0; k < 8; k++) { wl.padK[k] = 0; wl.srcK[k] = 0; }
    wl.s[0]=qkv_w;   wl.n[0]=3*Cc*Cc;  wl.off[0]=W_QKV;
    wl.s[1]=dw1_w;   wl.n[1]=Cc*Cc;    wl.off[1]=W_DW1;
    wl.s[2]=cp_in_w; wl.n[2]=C6c*Cc;   wl.off[2]=W_CPIN;
    wl.s[3]=ci2c_w;  wl.n[3]=C6c*C6c;  wl.off[3]=W_CI2C;
    wl.s[4]=cp_out_w;wl.n[4]=Cc*C6c;   wl.off[4]=W_CPOUT;
    wl.s[5]=sp_in_w; wl.n[5]=C2c*Cc;   wl.off[5]=W_SPIN;
    wl.s[6]=sp_out_w;wl.n[6]=Cc*128;   wl.off[6]=W_SPOUT; wl.padK[6]=128; wl.srcK[6]=96;
    wl.s[7]=proj_w;  wl.n[7]=Cc*Cc;    wl.off[7]=W_PROJ;

    // -------- prologue: f2h on sB concurrent with zero+transpose on main ----
    cudaEventRecord(evStart, 0);
    cudaStreamWaitEvent(sB, evStart, 0);
    f2h_kernel<<<1728, 256, 0, sB>>>(wl);
    cudaEventRecord(evPro, sB);
    zero_kernel<<<576, 256>>>();
    transpose_kernel<<<dim3(128, 12, Bb), dim3(32, 8)>>>(x);
    cudaStreamWaitEvent(0, evPro, 0);

    // qkv (+ fused sumsq)
    mma_gemm<4><<<dim3(9, 32, Bb), 256, SM4>>>(xh, Cc, bCN, wb + W_QKV, Cc, 0,
        nullptr, 0, nullptr, nullptr, ssq, nullptr, nullptr, nullptr, nullptr,
        nullptr, qkvh, C3, b3CN, Cc);
    cudaEventRecord(evQ, 0);
    cudaStreamWaitEvent(sB, evQ, 0);

    // -------- branch B (conv/spatial) on sB ---------------------------------
    mma_gemm<4><<<dim3(3, 32, Bb), 256, SM4, sB>>>(qkvh + 2 * Cc, C3, b3CN,
        wb + W_DW1, Cc, 0, dw1_b, 0, nullptr, nullptr, nullptr,
        nullptr, nullptr, nullptr, nullptr, nullptr, t1h, Cc, bCN, Cc);
    dwconv4h<<<(Bb * NN * Cc / 4) / 256, 256, 0, sB>>>(t1h, dw2_w, dw2_b, convxh, Cc, 3, 1, 1);
    mma_gemm<3><<<dim3(2, 32, Bb), 256, SM3, sB>>>(convxh, Cc, bCN, wb + W_SPIN, Cc, 0,
        sp_in_b, 0, nullptr, nullptr, nullptr, nullptr, nullptr, nullptr, nullptr,
        nullptr, sph, C2c, b192, Cc);
    spdw_gelu<<<(Bb * NN * 24) / 256, 256, 0, sB>>>(sph, sp_dw_w, sp_dw_b, gatedh);
    cudaEventRecord(evB, sB);

    // -------- branch A (attention/channel) on main stream -------------------
    gram_kernel<<<dim3(4, Bb * HEADS), 256>>>();
    softmax_kernel<<<Bb * HEADS * HD, 64>>>(temperature);
    attnv_kernel<<<dim3(NN / 128, Bb * HEADS), 128>>>();
    mma_gemm<2><<<dim3(1, 32, Bb), 256, SM2>>>(ath, Cc, bCN, wb + W_CPIN, Cc, 0,
        cp_in_b, 0, nullptr, nullptr, nullptr, nullptr, nullptr, nullptr, nullptr,
        nullptr, tth, C6c, b64, Cc);
    tmean_kernel<<<dim3(32, Bb), 64>>>();
    ci1_kernel<<<Bb, C6c>>>(ci1_w, ci1_b);
    dwconv4h<<<(Bb * NN * C6c / 4) / 256, 256>>>(tth, ci2a_w, ci2a_b, u1h, C6c, 3, 1, 1);
    dwconv4h<<<(Bb * NN * C6c / 4) / 256, 256>>>(u1h, ci2b_w, ci2b_b, u2h, C6c, 7, 9, 3);
    mma_gemm<2><<<dim3(1, 32, Bb), 256, SM2>>>(u2h, C6c, b64, wb + W_CI2C, C6c, 0,
        ci2c_b, 0, tth, ci1v, nullptr, nullptr, nullptr, nullptr, nullptr,
        nullptr, u3h, C6c, b64, C6c);
    mma_gemm<4><<<dim3(3, 32, Bb), 256, SM4>>>(u3h, C6c, b64, wb + W_CPOUT, C6c, 0,
        cp_out_b, 0, nullptr, nullptr, nullptr, nullptr, nullptr, nullptr, nullptr,
        nullptr, chmaph, Cc, bCN, C6c);
    cm_kernel<<<dim3(32, Bb), Cc>>>();

    // -------- join, sp_out + fused combine, proj ----------------------------
    cudaStreamWaitEvent(0, evB, 0);
    mma_gemm<4><<<dim3(3, 32, Bb), 256, SM4>>>(gatedh, 128, b128, wb + W_SPOUT, 128, 0,
        sp_out_b, 0, nullptr, nullptr, nullptr, ath, chmaph, convxh, cm,
        nullptr, yh, Cc, bCN, 128);
    mma_gemm<4><<<dim3(32, 3, Bb), 256, SM4>>>(wb + W_PROJ, Cc, 0, yh, Cc, bCN,
        proj_b, 1, nullptr, nullptr, nullptr, nullptr, nullptr, nullptr, nullptr,
        out, nullptr, NN, bCN, Cc);
}